// round 6
// baseline (speedup 1.0000x reference)
#include <cuda_runtime.h>
#include <math.h>

#define BB 2
#define CC 64
#define HH 256
#define WW 256
#define HWW (HH*WW)

typedef unsigned long long ull;

// packed f32x2 helpers (FFMA2 only reachable via PTX)
#define PACK2(out, lo, hi) \
    asm("mov.b64 %0, {%1, %2};" : "=l"(out) : "f"(lo), "f"(hi))
#define UNPACK2(lo, hi, in) \
    asm("mov.b64 {%0, %1}, %2;" : "=f"(lo), "=f"(hi) : "l"(in))
#define FFMA2(acc, a, b) \
    asm("fma.rn.f32x2 %0, %1, %2, %3;" : "=l"(acc) : "l"(a), "l"(b), "l"(acc))

// ---- scratch (device globals; no runtime allocation allowed) ----
__device__ float g_om[BB*27*HWW];       // offset/mask conv output
__device__ float g_h1[BB*CC*HWW];       // after DCN + bn1 + relu
__device__ float g_h2[BB*CC*HWW];       // after conv_h + bn2 + relu
__device__ float g_h3[BB*CC*HWW];       // after conv_w + bn3 + relu
__device__ float2 g_w2_om[CC*9*32];     // [c][tap][ocpad32], duplicated {w,w}
__device__ float2 g_w2_dcn[CC*9*CC];    // [c][tap][oc], duplicated
__device__ float2 g_w2_h[CC*9*CC];
__device__ float2 g_w2_w[CC*9*CC];

// ---------------------------------------------------------------------------
// Weight transpose + duplicate: src [OC][C][3][3] -> dst [(c*9+tap)][oc] = {w,w}
// ---------------------------------------------------------------------------
__global__ void prep_weights_kernel(const float* __restrict__ w_om,
                                    const float* __restrict__ w_dcn,
                                    const float* __restrict__ w_h,
                                    const float* __restrict__ w_w) {
    const int i0 = blockIdx.x * blockDim.x + threadIdx.x;
    const int stride = gridDim.x * blockDim.x;
    for (int i = i0; i < CC*9*32; i += stride) {
        int oc = i & 31; int ct = i >> 5; int c = ct / 9, tap = ct % 9;
        float v = (oc < 27) ? w_om[(oc*CC + c)*9 + tap] : 0.f;
        g_w2_om[i] = make_float2(v, v);
    }
    for (int i = i0; i < CC*9*CC; i += stride) {
        int oc = i & 63; int ct = i >> 6; int c = ct / 9, tap = ct % 9;
        int s = (oc*CC + c)*9 + tap;
        float a = w_dcn[s], bq = w_h[s], cq = w_w[s];
        g_w2_dcn[i] = make_float2(a, a);
        g_w2_h[i]   = make_float2(bq, bq);
        g_w2_w[i]   = make_float2(cq, cq);
    }
}

// ---------------------------------------------------------------------------
// Offset/mask conv: x[64ch] -> g_om[27ch], 3x3 pad1 (dil=1), + bias. FFMA2.
// Block 256 = 32 pxg x 8 ocg; per-thread 4px x 4oc.
// ---------------------------------------------------------------------------
__global__ void __launch_bounds__(256)
conv_om_kernel(const float* __restrict__ x,
               const float* __restrict__ b_om) {
    const int x0 = blockIdx.x * 128;
    const int y  = blockIdx.y;
    const int b  = blockIdx.z;
    const int tid = threadIdx.x;
    const int pxg = tid & 31, ocg = tid >> 5;
    const int px0 = pxg * 4, oc0 = ocg * 4;
    const int NCOL = 130;

    __shared__ float s_rows[3][136];
    __shared__ float2 s_w2[9*32];

    ull acc2[4][2];
#pragma unroll
    for (int i = 0; i < 4; i++) { acc2[i][0] = 0ull; acc2[i][1] = 0ull; }

    for (int c = 0; c < CC; c++) {
        __syncthreads();
        const float* xc = x + ((size_t)(b*CC + c))*HWW;
        for (int i = tid; i < 3*NCOL; i += 256) {
            int r = i / NCOL, col = i - r*NCOL;
            int yy = y + r - 1, xx = x0 - 1 + col;
            float v = 0.f;
            if ((unsigned)yy < HH && (unsigned)xx < WW) v = xc[yy*WW + xx];
            s_rows[r][col] = v;
        }
        const float2* wp = g_w2_om + c*9*32;
        for (int i = tid; i < 288; i += 256)
            ((ull*)s_w2)[i] = ((const ull*)wp)[i];
        __syncthreads();
#pragma unroll
        for (int ky = 0; ky < 3; ky++) {
            float iv[6];
#pragma unroll
            for (int j = 0; j < 6; j++) iv[j] = s_rows[ky][px0 + j];
            ull ivp[5];
#pragma unroll
            for (int s = 0; s < 5; s++) PACK2(ivp[s], iv[s], iv[s+1]);
#pragma unroll
            for (int kx = 0; kx < 3; kx++) {
                const ull* wrow = (const ull*)(s_w2 + (ky*3+kx)*32 + oc0);
                ull wv2[4];
#pragma unroll
                for (int i = 0; i < 4; i++) wv2[i] = wrow[i];
#pragma unroll
                for (int i = 0; i < 4; i++) {
                    FFMA2(acc2[i][0], wv2[i], ivp[kx]);
                    FFMA2(acc2[i][1], wv2[i], ivp[2+kx]);
                }
            }
        }
    }
#pragma unroll
    for (int i = 0; i < 4; i++) {
        int oc = oc0 + i;
        if (oc < 27) {
            float bo = b_om[oc];
            float* op = g_om + ((size_t)(b*27 + oc))*HWW + y*WW + x0 + px0;
            float v0, v1, v2, v3;
            UNPACK2(v0, v1, acc2[i][0]);
            UNPACK2(v2, v3, acc2[i][1]);
            op[0] = v0 + bo; op[1] = v1 + bo; op[2] = v2 + bo; op[3] = v3 + bo;
        }
    }
}

// ---------------------------------------------------------------------------
// Modulated deformable conv (DCNv2) + bn1 + relu -> g_h1. FFMA2 GEMM.
// ---------------------------------------------------------------------------
__global__ void __launch_bounds__(256)
dcn_kernel(const float* __restrict__ x,
           const float* __restrict__ bias,
           const float* __restrict__ bg, const float* __restrict__ bb,
           const float* __restrict__ bm, const float* __restrict__ bv) {
    const int x0 = blockIdx.x * 128;
    const int y  = blockIdx.y;
    const int b  = blockIdx.z;
    const int tid = threadIdx.x;
    const int pxg = tid & 31, ocg = tid >> 5;
    const int px0 = pxg * 4, oc0 = ocg * 8;

    __shared__ int   s_idx[9*128][4];
    __shared__ float s_gw [9*128][4];
    __shared__ float s_cols[9][128];
    __shared__ float2 s_w2[9*64];

    // geometry: bilinear corner indices + (mask * bilinear * valid) weights
    for (int s = tid; s < 9*128; s += 256) {
        int k = s >> 7, px = s & 127;
        int xx = x0 + px;
        float o1 = g_om[((b*27 +      k)*HH + y)*WW + xx];
        float o2 = g_om[((b*27 +  9 + k)*HH + y)*WW + xx];
        float ml = g_om[((b*27 + 18 + k)*HH + y)*WW + xx];
        float m  = 1.f / (1.f + expf(-ml));
        float py  = (float)(y  + (k/3) - 1) + o1;
        float pxf = (float)(xx + (k%3) - 1) + o2;
        float fy = floorf(py), fx = floorf(pxf);
        float wy1 = py - fy, wx1 = pxf - fx;
        int iy0 = (int)fy, ix0 = (int)fx;
#pragma unroll
        for (int j = 0; j < 4; j++) {
            int dy = j >> 1, dx = j & 1;
            int yi = iy0 + dy, xi = ix0 + dx;
            bool valid = ((unsigned)yi < HH) && ((unsigned)xi < WW);
            float wgt = (dy ? wy1 : 1.f - wy1) * (dx ? wx1 : 1.f - wx1);
            s_gw[s][j]  = valid ? m * wgt : 0.f;
            int yc = min(max(yi, 0), HH-1);
            int xc = min(max(xi, 0), WW-1);
            s_idx[s][j] = yc*WW + xc;
        }
    }

    ull acc2[8][2];
#pragma unroll
    for (int i = 0; i < 8; i++) { acc2[i][0] = 0ull; acc2[i][1] = 0ull; }

    for (int c = 0; c < CC; c++) {
        __syncthreads();
        const float* xc = x + ((size_t)(b*CC + c))*HWW;
        for (int s = tid; s < 9*128; s += 256) {
            float v = s_gw[s][0]*xc[s_idx[s][0]] + s_gw[s][1]*xc[s_idx[s][1]]
                    + s_gw[s][2]*xc[s_idx[s][2]] + s_gw[s][3]*xc[s_idx[s][3]];
            s_cols[s >> 7][s & 127] = v;
        }
        const float2* wp = g_w2_dcn + c*576;
        for (int i = tid; i < 576; i += 256)
            ((ull*)s_w2)[i] = ((const ull*)wp)[i];
        __syncthreads();
#pragma unroll
        for (int k = 0; k < 9; k++) {
            float4 a = *(const float4*)&s_cols[k][px0];
            ull iv0, iv1;
            PACK2(iv0, a.x, a.y);
            PACK2(iv1, a.z, a.w);
            const ull* wrow = (const ull*)(s_w2 + k*64 + oc0);
            ull wv2[8];
#pragma unroll
            for (int i = 0; i < 8; i++) wv2[i] = wrow[i];
#pragma unroll
            for (int i = 0; i < 8; i++) {
                FFMA2(acc2[i][0], wv2[i], iv0);
                FFMA2(acc2[i][1], wv2[i], iv1);
            }
        }
    }
#pragma unroll
    for (int i = 0; i < 8; i++) {
        int oc = oc0 + i;
        float s = bg[oc] * rsqrtf(bv[oc] + 1e-5f);
        float d = (bias[oc] - bm[oc]) * s + bb[oc];
        float* op = g_h1 + ((size_t)(b*CC + oc))*HWW + y*WW + x0 + px0;
        float v0, v1, v2, v3;
        UNPACK2(v0, v1, acc2[i][0]);
        UNPACK2(v2, v3, acc2[i][1]);
        float r0 = fmaf(v0, s, d), r1 = fmaf(v1, s, d);
        float r2 = fmaf(v2, s, d), r3 = fmaf(v3, s, d);
        op[0] = r0 > 0.f ? r0 : 0.f;
        op[1] = r1 > 0.f ? r1 : 0.f;
        op[2] = r2 > 0.f ? r2 : 0.f;
        op[3] = r3 > 0.f ? r3 : 0.f;
    }
}

// ---------------------------------------------------------------------------
// 64->64 3x3 conv, dilation 2, + bn + relu. FFMA2 inner GEMM.
// Pair starts for DIL=2 are even: ivp[t]=pack(iv[2t],iv[2t+1]), t=0..3.
// ---------------------------------------------------------------------------
__global__ void __launch_bounds__(256)
conv64_kernel(const float* __restrict__ in, const float2* __restrict__ wT2,
              const float* __restrict__ bias,
              const float* __restrict__ bg, const float* __restrict__ bb,
              const float* __restrict__ bm, const float* __restrict__ bv,
              float* __restrict__ out) {
    const int x0 = blockIdx.x * 128;
    const int y  = blockIdx.y;
    const int b  = blockIdx.z;
    const int tid = threadIdx.x;
    const int pxg = tid & 31, ocg = tid >> 5;
    const int px0 = pxg * 4, oc0 = ocg * 8;
    const int DIL = 2;
    const int NCOL = 132;

    __shared__ float s_rows[3][136];
    __shared__ float2 s_w2[9*64];

    ull acc2[8][2];
#pragma unroll
    for (int i = 0; i < 8; i++) { acc2[i][0] = 0ull; acc2[i][1] = 0ull; }

    for (int c = 0; c < CC; c++) {
        __syncthreads();
        const float* inc = in + ((size_t)(b*CC + c))*HWW;
        for (int i = tid; i < 3*NCOL; i += 256) {
            int r = i / NCOL, col = i - r*NCOL;
            int yy = y + (r-1)*DIL, xx = x0 - DIL + col;
            float v = 0.f;
            if ((unsigned)yy < HH && (unsigned)xx < WW) v = inc[yy*WW + xx];
            s_rows[r][col] = v;
        }
        const float2* wp = wT2 + c*576;
        for (int i = tid; i < 576; i += 256)
            ((ull*)s_w2)[i] = ((const ull*)wp)[i];
        __syncthreads();
#pragma unroll
        for (int ky = 0; ky < 3; ky++) {
            float4 a = *(const float4*)&s_rows[ky][px0];
            float4 e = *(const float4*)&s_rows[ky][px0 + 4];
            ull ivp[4];
            PACK2(ivp[0], a.x, a.y);
            PACK2(ivp[1], a.z, a.w);
            PACK2(ivp[2], e.x, e.y);
            PACK2(ivp[3], e.z, e.w);
#pragma unroll
            for (int kx = 0; kx < 3; kx++) {
                const ull* wrow = (const ull*)(s_w2 + (ky*3+kx)*64 + oc0);
                ull wv2[8];
#pragma unroll
                for (int i = 0; i < 8; i++) wv2[i] = wrow[i];
#pragma unroll
                for (int i = 0; i < 8; i++) {
                    FFMA2(acc2[i][0], wv2[i], ivp[kx]);
                    FFMA2(acc2[i][1], wv2[i], ivp[kx + 1]);
                }
            }
        }
    }
#pragma unroll
    for (int i = 0; i < 8; i++) {
        int oc = oc0 + i;
        float s = bg[oc] * rsqrtf(bv[oc] + 1e-5f);
        float d = (bias[oc] - bm[oc]) * s + bb[oc];
        float* op = out + ((size_t)(b*CC + oc))*HWW + y*WW + x0 + px0;
        float v0, v1, v2, v3;
        UNPACK2(v0, v1, acc2[i][0]);
        UNPACK2(v2, v3, acc2[i][1]);
        float r0 = fmaf(v0, s, d), r1 = fmaf(v1, s, d);
        float r2 = fmaf(v2, s, d), r3 = fmaf(v3, s, d);
        op[0] = r0 > 0.f ? r0 : 0.f;
        op[1] = r1 > 0.f ? r1 : 0.f;
        op[2] = r2 > 0.f ? r2 : 0.f;
        op[3] = r3 > 0.f ? r3 : 0.f;
    }
}

// ---------------------------------------------------------------------------
// Final 64->1 3x3 conv pad1 + sigmoid + clip.
// ---------------------------------------------------------------------------
__global__ void __launch_bounds__(256)
final_kernel(const float* __restrict__ w3, const float* __restrict__ b3,
             float* __restrict__ out) {
    const int y = blockIdx.x;
    const int b = blockIdx.y;
    const int tid = threadIdx.x;  // 256 = W

    __shared__ float s_rows[3][260];
    __shared__ float s_w3[576];
    for (int i = tid; i < 576; i += 256) s_w3[i] = w3[i];

    float acc = 0.f;
    for (int c = 0; c < CC; c++) {
        __syncthreads();
        const float* hc = g_h3 + ((size_t)(b*CC + c))*HWW;
        for (int i = tid; i < 3*258; i += 256) {
            int r = i / 258, col = i - r*258;
            int yy = y + r - 1, xx = col - 1;
            float v = 0.f;
            if ((unsigned)yy < HH && (unsigned)xx < WW) v = hc[yy*WW + xx];
            s_rows[r][col] = v;
        }
        __syncthreads();
        const float* wc = s_w3 + c*9;
#pragma unroll
        for (int ky = 0; ky < 3; ky++)
#pragma unroll
            for (int kx = 0; kx < 3; kx++)
                acc = fmaf(wc[ky*3+kx], s_rows[ky][tid + kx], acc);
    }
    float v = acc + b3[0];
    float sg = 1.f / (1.f + expf(-v));
    sg = fminf(fmaxf(sg, 1e-4f), 1.f - 1e-4f);
    out[((size_t)b*HH + y)*WW + tid] = sg;
}

// ---------------------------------------------------------------------------
extern "C" void kernel_launch(void* const* d_in, const int* in_sizes, int n_in,
                              void* d_out, int out_size) {
    (void)n_in; (void)out_size;
    const float* x     = (const float*)d_in[0];
    const float* w_om  = (const float*)d_in[1];
    const float* b_om  = (const float*)d_in[2];
    const float* w_dcn = (const float*)d_in[3];
    const float* b_dcn = (const float*)d_in[4];
    const float* bn1g  = (const float*)d_in[5];
    const float* bn1b  = (const float*)d_in[6];
    const float* bn1m  = (const float*)d_in[7];
    const float* bn1v  = (const float*)d_in[8];

    const float *w_h, *b_h, *w_w, *b_w, *w3, *b3;
    const float *bn2g, *bn2b, *bn2m, *bn2v, *bn3g, *bn3b, *bn3m, *bn3v;
    if (in_sizes[9] == CC) {
        // dict order
        bn2g = (const float*)d_in[9];  bn2b = (const float*)d_in[10];
        bn2m = (const float*)d_in[11]; bn2v = (const float*)d_in[12];
        bn3g = (const float*)d_in[13]; bn3b = (const float*)d_in[14];
        bn3m = (const float*)d_in[15]; bn3v = (const float*)d_in[16];
        w_h  = (const float*)d_in[17]; b_h  = (const float*)d_in[18];
        w_w  = (const float*)d_in[19]; b_w  = (const float*)d_in[20];
        w3   = (const float*)d_in[21]; b3   = (const float*)d_in[22];
    } else {
        // signature order
        w_h  = (const float*)d_in[9];  b_h  = (const float*)d_in[10];
        bn2g = (const float*)d_in[11]; bn2b = (const float*)d_in[12];
        bn2m = (const float*)d_in[13]; bn2v = (const float*)d_in[14];
        w_w  = (const float*)d_in[15]; b_w  = (const float*)d_in[16];
        bn3g = (const float*)d_in[17]; bn3b = (const float*)d_in[18];
        bn3m = (const float*)d_in[19]; bn3v = (const float*)d_in[20];
        w3   = (const float*)d_in[21]; b3   = (const float*)d_in[22];
    }
    float* out = (float*)d_out;

    float *p_h1, *p_h2, *p_h3;
    float2 *p_w2_h, *p_w2_w;
    cudaGetSymbolAddress((void**)&p_h1,   g_h1);
    cudaGetSymbolAddress((void**)&p_h2,   g_h2);
    cudaGetSymbolAddress((void**)&p_h3,   g_h3);
    cudaGetSymbolAddress((void**)&p_w2_h, g_w2_h);
    cudaGetSymbolAddress((void**)&p_w2_w, g_w2_w);

    prep_weights_kernel<<<72, 256>>>(w_om, w_dcn, w_h, w_w);

    dim3 gridc(WW/128, HH, BB);
    conv_om_kernel<<<gridc, 256>>>(x, b_om);
    dcn_kernel<<<gridc, 256>>>(x, b_dcn, bn1g, bn1b, bn1m, bn1v);
    conv64_kernel<<<gridc, 256>>>(p_h1, p_w2_h, b_h, bn2g, bn2b, bn2m, bn2v, p_h2);
    conv64_kernel<<<gridc, 256>>>(p_h2, p_w2_w, b_w, bn3g, bn3b, bn3m, bn3v, p_h3);
    final_kernel<<<dim3(HH, BB), 256>>>(w3, b3, out);
}

// round 9
// speedup vs baseline: 1.6092x; 1.6092x over previous
#include <cuda_runtime.h>
#include <math.h>
#include <stdint.h>

#define BB 2
#define CC 64
#define HH 256
#define WW 256
#define HWW (HH*WW)

// ---- scratch (device globals; no runtime allocation allowed) ----
__device__ float g_om[BB*27*HWW];       // offset/mask conv output
__device__ float g_h1[BB*CC*HWW];       // after DCN + bn1 + relu
__device__ float g_h2[BB*CC*HWW];       // after conv_h + bn2 + relu
__device__ float g_h3[BB*CC*HWW];       // after conv_w + bn3 + relu
__device__ float g_wT_om[CC*9*32];      // [c][tap][ocpad32]  (scalar om conv)
__device__ float g_wT_dcn[CC*9*CC];     // [c][tap][oc]       (scalar dcn GEMM)
// bf16 hi/lo split, swizzled [tap][oc][c] tiles for tensor conv64
__device__ __align__(16) unsigned short g_wBh_hi[9*64*64];
__device__ __align__(16) unsigned short g_wBh_lo[9*64*64];
__device__ __align__(16) unsigned short g_wBw_hi[9*64*64];
__device__ __align__(16) unsigned short g_wBw_lo[9*64*64];

// ---- bf16 round-to-nearest-even split helpers (bit tricks, no bf16 header) --
__device__ __forceinline__ uint32_t bf16_rne(float v) {
    uint32_t x = __float_as_uint(v);
    return (x + 0x7FFFu + ((x >> 16) & 1u)) >> 16;
}
__device__ __forceinline__ void bf16_split(float v, uint32_t& hb, uint32_t& lb) {
    hb = bf16_rne(v);
    float hf = __uint_as_float(hb << 16);
    lb = bf16_rne(v - hf);
}

// ---- warp-level tensor ops (non-'a' target: sm_80-lineage, valid on sm_103) -
__device__ __forceinline__ void ldm4(uint32_t* r, uint32_t addr) {
    asm volatile("ldmatrix.sync.aligned.m8n8.x4.shared.b16 {%0,%1,%2,%3}, [%4];"
                 : "=r"(r[0]), "=r"(r[1]), "=r"(r[2]), "=r"(r[3]) : "r"(addr));
}
__device__ __forceinline__ void mma_bf16(float* d, const uint32_t* a,
                                         const uint32_t* b) {
    asm volatile(
        "mma.sync.aligned.m16n8k16.row.col.f32.bf16.bf16.f32 "
        "{%0,%1,%2,%3}, {%4,%5,%6,%7}, {%8,%9}, {%0,%1,%2,%3};"
        : "+f"(d[0]), "+f"(d[1]), "+f"(d[2]), "+f"(d[3])
        : "r"(a[0]), "r"(a[1]), "r"(a[2]), "r"(a[3]), "r"(b[0]), "r"(b[1]));
}
__device__ __forceinline__ uint32_t smem_u32(const void* p) {
    uint32_t a;
    asm("{ .reg .u64 t; cvta.to.shared.u64 t, %1; cvt.u32.u64 %0, t; }"
        : "=r"(a) : "l"(p));
    return a;
}

// ===========================================================================
// Weight prep: scalar layouts for om/dcn + bf16 hi/lo swizzled tiles for h/w.
// Swizzled elt index (per tap tile): oc*64 + (((c>>3)^(oc&7))<<3) + (c&7)
// ===========================================================================
__global__ void prep_weights_kernel(const float* __restrict__ w_om,
                                    const float* __restrict__ w_dcn,
                                    const float* __restrict__ w_h,
                                    const float* __restrict__ w_w) {
    const int i0 = blockIdx.x * blockDim.x + threadIdx.x;
    const int stride = gridDim.x * blockDim.x;
    for (int i = i0; i < CC*9*32; i += stride) {
        int oc = i & 31; int ct = i >> 5; int c = ct / 9, tap = ct % 9;
        g_wT_om[i] = (oc < 27) ? w_om[(oc*CC + c)*9 + tap] : 0.f;
    }
    for (int i = i0; i < CC*9*CC; i += stride) {
        int oc = i & 63; int ct = i >> 6; int c = ct / 9, tap = ct % 9;
        g_wT_dcn[i] = w_dcn[(oc*CC + c)*9 + tap];
    }
    for (int i = i0; i < 9*CC*CC; i += stride) {
        int oc = i / 576; int r = i - oc*576; int c = r / 9, tap = r - c*9;
        int dst = tap*4096 + oc*64 + ((((c>>3) ^ (oc&7))) << 3) + (c & 7);
        uint32_t hb, lb;
        bf16_split(w_h[i], hb, lb);
        g_wBh_hi[dst] = (unsigned short)hb;
        g_wBh_lo[dst] = (unsigned short)lb;
        bf16_split(w_w[i], hb, lb);
        g_wBw_hi[dst] = (unsigned short)hb;
        g_wBw_lo[dst] = (unsigned short)lb;
    }
}

// ---------------------------------------------------------------------------
// Offset/mask conv: x[64ch] -> g_om[27ch], 3x3 pad1, + bias. (scalar, R3)
// ---------------------------------------------------------------------------
__global__ void __launch_bounds__(256)
conv_om_kernel(const float* __restrict__ x,
               const float* __restrict__ b_om) {
    const int x0 = blockIdx.x * 128;
    const int y  = blockIdx.y;
    const int b  = blockIdx.z;
    const int tid = threadIdx.x;
    const int pxg = tid & 31, ocg = tid >> 5;
    const int px0 = pxg * 4, oc0 = ocg * 4;
    const int NCOL = 130;

    __shared__ float s_rows[3][132];
    __shared__ float s_w[9*32];

    float acc[4][4] = {};

    for (int c = 0; c < CC; c++) {
        __syncthreads();
        const float* xc = x + ((size_t)(b*CC + c))*HWW;
        for (int i = tid; i < 3*NCOL; i += 256) {
            int r = i / NCOL, col = i - r*NCOL;
            int yy = y + r - 1, xx = x0 - 1 + col;
            float v = 0.f;
            if ((unsigned)yy < HH && (unsigned)xx < WW) v = xc[yy*WW + xx];
            s_rows[r][col] = v;
        }
        const float* wp = g_wT_om + c*9*32;
        for (int i = tid; i < 288; i += 256) s_w[i] = wp[i];
        __syncthreads();
#pragma unroll
        for (int ky = 0; ky < 3; ky++) {
            float iv[6];
#pragma unroll
            for (int j = 0; j < 6; j++) iv[j] = s_rows[ky][px0 + j];
#pragma unroll
            for (int kx = 0; kx < 3; kx++) {
                const float* wrow = s_w + (ky*3+kx)*32 + oc0;
                float wv[4];
#pragma unroll
                for (int i = 0; i < 4; i++) wv[i] = wrow[i];
#pragma unroll
                for (int i = 0; i < 4; i++)
#pragma unroll
                    for (int j = 0; j < 4; j++)
                        acc[i][j] = fmaf(wv[i], iv[j+kx], acc[i][j]);
            }
        }
    }
#pragma unroll
    for (int i = 0; i < 4; i++) {
        int oc = oc0 + i;
        if (oc < 27) {
            float bo = b_om[oc];
            float* op = g_om + ((size_t)(b*27 + oc))*HWW + y*WW + x0 + px0;
#pragma unroll
            for (int j = 0; j < 4; j++) op[j] = acc[i][j] + bo;
        }
    }
}

// ---------------------------------------------------------------------------
// Modulated deformable conv (DCNv2) + bn1 + relu -> g_h1. (scalar, R3)
// ---------------------------------------------------------------------------
__global__ void __launch_bounds__(256)
dcn_kernel(const float* __restrict__ x,
           const float* __restrict__ bias,
           const float* __restrict__ bg, const float* __restrict__ bb,
           const float* __restrict__ bm, const float* __restrict__ bv) {
    const int x0 = blockIdx.x * 128;
    const int y  = blockIdx.y;
    const int b  = blockIdx.z;
    const int tid = threadIdx.x;
    const int pxg = tid & 31, ocg = tid >> 5;
    const int px0 = pxg * 4, oc0 = ocg * 8;

    __shared__ int   s_idx[9*128][4];
    __shared__ float s_gw [9*128][4];
    __shared__ float s_cols[9][128];
    __shared__ float s_w[9*64];

    for (int s = tid; s < 9*128; s += 256) {
        int k = s >> 7, px = s & 127;
        int xx = x0 + px;
        float o1 = g_om[((b*27 +      k)*HH + y)*WW + xx];
        float o2 = g_om[((b*27 +  9 + k)*HH + y)*WW + xx];
        float ml = g_om[((b*27 + 18 + k)*HH + y)*WW + xx];
        float m  = 1.f / (1.f + expf(-ml));
        float py  = (float)(y  + (k/3) - 1) + o1;
        float pxf = (float)(xx + (k%3) - 1) + o2;
        float fy = floorf(py), fx = floorf(pxf);
        float wy1 = py - fy, wx1 = pxf - fx;
        int iy0 = (int)fy, ix0 = (int)fx;
#pragma unroll
        for (int j = 0; j < 4; j++) {
            int dy = j >> 1, dx = j & 1;
            int yi = iy0 + dy, xi = ix0 + dx;
            bool valid = ((unsigned)yi < HH) && ((unsigned)xi < WW);
            float wgt = (dy ? wy1 : 1.f - wy1) * (dx ? wx1 : 1.f - wx1);
            s_gw[s][j]  = valid ? m * wgt : 0.f;
            int yc = min(max(yi, 0), HH-1);
            int xc = min(max(xi, 0), WW-1);
            s_idx[s][j] = yc*WW + xc;
        }
    }

    float acc[8][4] = {};

    for (int c = 0; c < CC; c++) {
        __syncthreads();
        const float* xc = x + ((size_t)(b*CC + c))*HWW;
        for (int s = tid; s < 9*128; s += 256) {
            float v = s_gw[s][0]*xc[s_idx[s][0]] + s_gw[s][1]*xc[s_idx[s][1]]
                    + s_gw[s][2]*xc[s_idx[s][2]] + s_gw[s][3]*xc[s_idx[s][3]];
            s_cols[s >> 7][s & 127] = v;
        }
        const float* wp = g_wT_dcn + c*576;
        for (int i = tid; i < 576; i += 256) s_w[i] = wp[i];
        __syncthreads();
#pragma unroll
        for (int k = 0; k < 9; k++) {
            float iv[4];
#pragma unroll
            for (int j = 0; j < 4; j++) iv[j] = s_cols[k][px0 + j];
            const float* wrow = s_w + k*64 + oc0;
            float wv[8];
#pragma unroll
            for (int i = 0; i < 8; i++) wv[i] = wrow[i];
#pragma unroll
            for (int i = 0; i < 8; i++)
#pragma unroll
                for (int j = 0; j < 4; j++)
                    acc[i][j] = fmaf(wv[i], iv[j], acc[i][j]);
        }
    }
#pragma unroll
    for (int i = 0; i < 8; i++) {
        int oc = oc0 + i;
        float s = bg[oc] * rsqrtf(bv[oc] + 1e-5f);
        float d = (bias[oc] - bm[oc]) * s + bb[oc];
        float* op = g_h1 + ((size_t)(b*CC + oc))*HWW + y*WW + x0 + px0;
#pragma unroll
        for (int j = 0; j < 4; j++) {
            float v = fmaf(acc[i][j], s, d);
            op[j] = v > 0.f ? v : 0.f;
        }
    }
}

// ===========================================================================
// Tensor-core conv64 (dil=2) + bn + relu via mma.sync bf16 hi/lo (bf16x3).
// CTA: one row y, 128 px, 64 oc. 8 warps = 4 m-warps x 2 n-warps (32px x 32oc).
// smem: A_hi[128px][64c] @0 (16KB), A_lo @16K, B_hi[64oc][64c] @32K, B_lo @40K.
// Rows are 128B; 16B units XOR-swizzled by (row&7): conflict-free STS+ldmatrix.
// ===========================================================================
#define SMEM_TC 49152

__global__ void __launch_bounds__(256)
conv64_tc_kernel(const float* __restrict__ in,
                 const unsigned short* __restrict__ wHi,
                 const unsigned short* __restrict__ wLo,
                 const float* __restrict__ bias,
                 const float* __restrict__ bg, const float* __restrict__ bb,
                 const float* __restrict__ bm, const float* __restrict__ bv,
                 float* __restrict__ out) {
    extern __shared__ char smem[];
    const int x0 = blockIdx.x * 128;
    const int y  = blockIdx.y;
    const int b  = blockIdx.z;
    const int tid = threadIdx.x;
    const int warp = tid >> 5, lane = tid & 31;
    const int wm = warp & 3, wn = warp >> 2;
    const uint32_t sbase = smem_u32(smem);

    __shared__ float s_s[64], s_d[64];
    if (tid < 64) {
        float s = bg[tid] * rsqrtf(bv[tid] + 1e-5f);
        s_s[tid] = s;
        s_d[tid] = (bias[tid] - bm[tid]) * s + bb[tid];
    }

    float acc[2][4][4];
#pragma unroll
    for (int mt = 0; mt < 2; mt++)
#pragma unroll
        for (int nt = 0; nt < 4; nt++)
#pragma unroll
            for (int j = 0; j < 4; j++) acc[mt][nt][j] = 0.f;

    for (int tap = 0; tap < 9; tap++) {
        __syncthreads();   // protect previous iteration's reads
        // ---- build A_t (hi/lo) ----
        const int dy = tap / 3, kx = tap - dy*3;
        const int rowy = y + 2*dy - 2;
        const bool rowok = (unsigned)rowy < HH;
        for (int i = tid; i < 4096; i += 256) {
            int px = i & 127, c = (i >> 7) << 1;
            int xin = x0 + px + 2*kx - 2;
            float v0 = 0.f, v1 = 0.f;
            if (rowok && (unsigned)xin < WW) {
                const float* p = in + ((size_t)(b*CC + c))*HWW + rowy*WW + xin;
                v0 = p[0];
                v1 = p[HWW];
            }
            uint32_t h0, l0, h1, l1;
            bf16_split(v0, h0, l0);
            bf16_split(v1, h1, l1);
            uint32_t off = (uint32_t)px*128u
                         + ((((uint32_t)(c>>3)) ^ ((uint32_t)px & 7u)) << 4)
                         + ((uint32_t)c & 7u)*2u;
            *(uint32_t*)(smem + off)         = h0 | (h1 << 16);
            *(uint32_t*)(smem + 16384 + off) = l0 | (l1 << 16);
        }
        // ---- copy pre-swizzled B_t (hi/lo) ----
        {
            const uint4* sh = (const uint4*)(wHi + tap*4096);
            const uint4* sl = (const uint4*)(wLo + tap*4096);
            uint4* dh = (uint4*)(smem + 32768);
            uint4* dl = (uint4*)(smem + 40960);
            for (int i = tid; i < 512; i += 256) { dh[i] = sh[i]; dl[i] = sl[i]; }
        }
        __syncthreads();

        // ---- 4 k16-chunks of bf16x3 mma ----
#pragma unroll
        for (int ch = 0; ch < 4; ch++) {
            uint32_t ahi[2][4], alo[2][4], bhi[2][4], blo[2][4];
#pragma unroll
            for (int mt = 0; mt < 2; mt++) {
                int pxr = wm*32 + mt*16 + (lane & 15);
                uint32_t u = (uint32_t)(ch*2 + (lane >> 4));
                uint32_t addr = sbase + (uint32_t)pxr*128u
                              + ((u ^ ((uint32_t)pxr & 7u)) << 4);
                ldm4(ahi[mt], addr);
                ldm4(alo[mt], addr + 16384u);
            }
#pragma unroll
            for (int half = 0; half < 2; half++) {
                int ocr = wn*32 + half*16 + (lane & 7) + ((lane >> 4) << 3);
                uint32_t u = (uint32_t)(ch*2 + ((lane >> 3) & 1));
                uint32_t addr = sbase + 32768u + (uint32_t)ocr*128u
                              + ((u ^ ((uint32_t)ocr & 7u)) << 4);
                ldm4(bhi[half], addr);
                ldm4(blo[half], addr + 8192u);
            }
#pragma unroll
            for (int mt = 0; mt < 2; mt++)
#pragma unroll
                for (int nt = 0; nt < 4; nt++) {
                    const uint32_t* bh = &bhi[nt >> 1][(nt & 1)*2];
                    const uint32_t* bl = &blo[nt >> 1][(nt & 1)*2];
                    mma_bf16(acc[mt][nt], ahi[mt], bh);
                    mma_bf16(acc[mt][nt], ahi[mt], bl);
                    mma_bf16(acc[mt][nt], alo[mt], bh);
                }
        }
    }

    // ---- epilogue: BN + ReLU + STG ----
    __syncthreads();
#pragma unroll
    for (int mt = 0; mt < 2; mt++) {
#pragma unroll
        for (int nt = 0; nt < 4; nt++) {
            int pxr = wm*32 + mt*16 + (lane >> 2);
            int occ = wn*32 + nt*8 + ((lane & 3) << 1);
            float s0 = s_s[occ],   d0 = s_d[occ];
            float s1 = s_s[occ+1], d1 = s_d[occ+1];
            float* o0 = out + ((size_t)(b*CC + occ))*HWW + y*WW + x0;
            float* o1 = o0 + HWW;
            float v;
            v = fmaf(acc[mt][nt][0], s0, d0); o0[pxr]     = v > 0.f ? v : 0.f;
            v = fmaf(acc[mt][nt][1], s1, d1); o1[pxr]     = v > 0.f ? v : 0.f;
            v = fmaf(acc[mt][nt][2], s0, d0); o0[pxr + 8] = v > 0.f ? v : 0.f;
            v = fmaf(acc[mt][nt][3], s1, d1); o1[pxr + 8] = v > 0.f ? v : 0.f;
        }
    }
}

// ---------------------------------------------------------------------------
// Final 64->1 3x3 conv pad1 + sigmoid + clip. (scalar, R3)
// ---------------------------------------------------------------------------
__global__ void __launch_bounds__(256)
final_kernel(const float* __restrict__ w3, const float* __restrict__ b3,
             float* __restrict__ out) {
    const int y = blockIdx.x;
    const int b = blockIdx.y;
    const int tid = threadIdx.x;  // 256 = W

    __shared__ float s_rows[3][260];
    __shared__ float s_w3[576];
    for (int i = tid; i < 576; i += 256) s_w3[i] = w3[i];

    float acc = 0.f;
    for (int c = 0; c < CC; c++) {
        __syncthreads();
        const float* hc = g_h3 + ((size_t)(b*CC + c))*HWW;
        for (int i = tid; i < 3*258; i += 256) {
            int r = i / 258, col = i - r*258;
            int yy = y + r - 1, xx = col - 1;
            float v = 0.f;
            if ((unsigned)yy < HH && (unsigned)xx < WW) v = hc[yy*WW + xx];
            s_rows[r][col] = v;
        }
        __syncthreads();
        const float* wc = s_w3 + c*9;
#pragma unroll
        for (int ky = 0; ky < 3; ky++)
#pragma unroll
            for (int kx = 0; kx < 3; kx++)
                acc = fmaf(wc[ky*3+kx], s_rows[ky][tid + kx], acc);
    }
    float v = acc + b3[0];
    float sg = 1.f / (1.f + expf(-v));
    sg = fminf(fmaxf(sg, 1e-4f), 1.f - 1e-4f);
    out[((size_t)b*HH + y)*WW + tid] = sg;
}

// ---------------------------------------------------------------------------
extern "C" void kernel_launch(void* const* d_in, const int* in_sizes, int n_in,
                              void* d_out, int out_size) {
    (void)n_in; (void)out_size;
    const float* x     = (const float*)d_in[0];
    const float* w_om  = (const float*)d_in[1];
    const float* b_om  = (const float*)d_in[2];
    const float* w_dcn = (const float*)d_in[3];
    const float* b_dcn = (const float*)d_in[4];
    const float* bn1g  = (const float*)d_in[5];
    const float* bn1b  = (const float*)d_in[6];
    const float* bn1m  = (const float*)d_in[7];
    const float* bn1v  = (const float*)d_in[8];

    const float *w_h, *b_h, *w_w, *b_w, *w3, *b3;
    const float *bn2g, *bn2b, *bn2m, *bn2v, *bn3g, *bn3b, *bn3m, *bn3v;
    if (in_sizes[9] == CC) {
        // dict order
        bn2g = (const float*)d_in[9];  bn2b = (const float*)d_in[10];
        bn2m = (const float*)d_in[11]; bn2v = (const float*)d_in[12];
        bn3g = (const float*)d_in[13]; bn3b = (const float*)d_in[14];
        bn3m = (const float*)d_in[15]; bn3v = (const float*)d_in[16];
        w_h  = (const float*)d_in[17]; b_h  = (const float*)d_in[18];
        w_w  = (const float*)d_in[19]; b_w  = (const float*)d_in[20];
        w3   = (const float*)d_in[21]; b3   = (const float*)d_in[22];
    } else {
        // signature order
        w_h  = (const float*)d_in[9];  b_h  = (const float*)d_in[10];
        bn2g = (const float*)d_in[11]; bn2b = (const float*)d_in[12];
        bn2m = (const float*)d_in[13]; bn2v = (const float*)d_in[14];
        w_w  = (const float*)d_in[15]; b_w  = (const float*)d_in[16];
        bn3g = (const float*)d_in[17]; bn3b = (const float*)d_in[18];
        bn3m = (const float*)d_in[19]; bn3v = (const float*)d_in[20];
        w3   = (const float*)d_in[21]; b3   = (const float*)d_in[22];
    }
    float* out = (float*)d_out;

    float *p_h1, *p_h2, *p_h3;
    unsigned short *p_wBh_hi, *p_wBh_lo, *p_wBw_hi, *p_wBw_lo;
    cudaGetSymbolAddress((void**)&p_h1, g_h1);
    cudaGetSymbolAddress((void**)&p_h2, g_h2);
    cudaGetSymbolAddress((void**)&p_h3, g_h3);
    cudaGetSymbolAddress((void**)&p_wBh_hi, g_wBh_hi);
    cudaGetSymbolAddress((void**)&p_wBh_lo, g_wBh_lo);
    cudaGetSymbolAddress((void**)&p_wBw_hi, g_wBw_hi);
    cudaGetSymbolAddress((void**)&p_wBw_lo, g_wBw_lo);

    cudaFuncSetAttribute(conv64_tc_kernel,
                         cudaFuncAttributeMaxDynamicSharedMemorySize, SMEM_TC);

    prep_weights_kernel<<<72, 256>>>(w_om, w_dcn, w_h, w_w);

    dim3 gridc(WW/128, HH, BB);
    conv_om_kernel<<<gridc, 256>>>(x, b_om);
    dcn_kernel<<<gridc, 256>>>(x, b_dcn, bn1g, bn1b, bn1m, bn1v);
    conv64_tc_kernel<<<gridc, 256, SMEM_TC>>>(p_h1, p_wBh_hi, p_wBh_lo, b_h,
                                              bn2g, bn2b, bn2m, bn2v, p_h2);
    conv64_tc_kernel<<<gridc, 256, SMEM_TC>>>(p_h2, p_wBw_hi, p_wBw_lo, b_w,
                                              bn3g, bn3b, bn3m, bn3v, p_h3);
    final_kernel<<<dim3(HH, BB), 256>>>(w3, b3, out);
}

// round 10
// speedup vs baseline: 2.3737x; 1.4751x over previous
#include <cuda_runtime.h>
#include <math.h>
#include <stdint.h>

#define BB 2
#define CC 64
#define HH 256
#define WW 256
#define HWW (HH*WW)

// ---- scratch (device globals; no runtime allocation allowed) ----
__device__ float g_om[BB*27*HWW];                         // offset/mask conv out (fp32)
__device__ uint32_t g_xh[BB*32*HWW], g_xl[BB*32*HWW];     // x packed bf16 hi/lo c-pairs
__device__ uint32_t g_h1h[BB*32*HWW], g_h1l[BB*32*HWW];   // h1 packed
__device__ uint32_t g_h2h[BB*32*HWW], g_h2l[BB*32*HWW];   // h2 packed
__device__ uint32_t g_h3h[BB*32*HWW], g_h3l[BB*32*HWW];   // h3 packed
// bf16 hi/lo split, swizzled [tap][oc][c] B tiles
__device__ __align__(16) unsigned short g_wBom_hi[9*32*64], g_wBom_lo[9*32*64];
__device__ __align__(16) unsigned short g_wBd_hi[9*64*64],  g_wBd_lo[9*64*64];
__device__ __align__(16) unsigned short g_wBh_hi[9*64*64],  g_wBh_lo[9*64*64];
__device__ __align__(16) unsigned short g_wBw_hi[9*64*64],  g_wBw_lo[9*64*64];

// ---- bf16 round-to-nearest-even split helpers ----
__device__ __forceinline__ uint32_t bf16_rne(float v) {
    uint32_t x = __float_as_uint(v);
    return (x + 0x7FFFu + ((x >> 16) & 1u)) >> 16;
}
__device__ __forceinline__ void bf16_split(float v, uint32_t& hb, uint32_t& lb) {
    hb = bf16_rne(v);
    float hf = __uint_as_float(hb << 16);
    lb = bf16_rne(v - hf);
}
__device__ __forceinline__ uint32_t pack_split2(float v0, float v1, uint32_t& lw) {
    uint32_t h0, l0, h1, l1;
    bf16_split(v0, h0, l0);
    bf16_split(v1, h1, l1);
    lw = l0 | (l1 << 16);
    return h0 | (h1 << 16);
}

// ---- warp-level tensor ops (sm_80-lineage; valid on plain sm_103 target) ----
__device__ __forceinline__ void ldm4(uint32_t* r, uint32_t addr) {
    asm volatile("ldmatrix.sync.aligned.m8n8.x4.shared.b16 {%0,%1,%2,%3}, [%4];"
                 : "=r"(r[0]), "=r"(r[1]), "=r"(r[2]), "=r"(r[3]) : "r"(addr));
}
__device__ __forceinline__ void mma_bf16(float* d, const uint32_t* a,
                                         const uint32_t* b) {
    asm volatile(
        "mma.sync.aligned.m16n8k16.row.col.f32.bf16.bf16.f32 "
        "{%0,%1,%2,%3}, {%4,%5,%6,%7}, {%8,%9}, {%0,%1,%2,%3};"
        : "+f"(d[0]), "+f"(d[1]), "+f"(d[2]), "+f"(d[3])
        : "r"(a[0]), "r"(a[1]), "r"(a[2]), "r"(a[3]), "r"(b[0]), "r"(b[1]));
}
__device__ __forceinline__ uint32_t smem_u32(const void* p) {
    uint32_t a;
    asm("{ .reg .u64 t; cvta.to.shared.u64 t, %1; cvt.u32.u64 %0, t; }"
        : "=r"(a) : "l"(p));
    return a;
}

// ===========================================================================
// Weight prep: bf16 hi/lo swizzled B tiles for om (32-oc pad), dcn, h, w.
// Swizzled elt index (per tap tile): oc*64 + (((c>>3)^(oc&7))<<3) + (c&7)
// ===========================================================================
__global__ void prep_weights_kernel(const float* __restrict__ w_om,
                                    const float* __restrict__ w_dcn,
                                    const float* __restrict__ w_h,
                                    const float* __restrict__ w_w) {
    const int i0 = blockIdx.x * blockDim.x + threadIdx.x;
    const int stride = gridDim.x * blockDim.x;
    for (int i = i0; i < 32*CC*9; i += stride) {
        int oc = i / 576; int r = i - oc*576; int c = r / 9, tap = r - c*9;
        float v = (oc < 27) ? w_om[(oc*CC + c)*9 + tap] : 0.f;
        int dst = tap*2048 + oc*64 + (((c>>3) ^ (oc&7)) << 3) + (c & 7);
        uint32_t hb, lb;
        bf16_split(v, hb, lb);
        g_wBom_hi[dst] = (unsigned short)hb;
        g_wBom_lo[dst] = (unsigned short)lb;
    }
    for (int i = i0; i < CC*CC*9; i += stride) {
        int oc = i / 576; int r = i - oc*576; int c = r / 9, tap = r - c*9;
        int dst = tap*4096 + oc*64 + (((c>>3) ^ (oc&7)) << 3) + (c & 7);
        uint32_t hb, lb;
        bf16_split(w_dcn[i], hb, lb);
        g_wBd_hi[dst] = (unsigned short)hb;
        g_wBd_lo[dst] = (unsigned short)lb;
        bf16_split(w_h[i], hb, lb);
        g_wBh_hi[dst] = (unsigned short)hb;
        g_wBh_lo[dst] = (unsigned short)lb;
        bf16_split(w_w[i], hb, lb);
        g_wBw_hi[dst] = (unsigned short)hb;
        g_wBw_lo[dst] = (unsigned short)lb;
    }
}

// ===========================================================================
// x -> packed bf16 hi/lo c-pair planes (for om_tc A-tiles)
// ===========================================================================
__global__ void prep_xsplit_kernel(const float* __restrict__ x) {
    const int i0 = blockIdx.x * blockDim.x + threadIdx.x;
    const int stride = gridDim.x * blockDim.x;
    for (int i = i0; i < BB*32*HWW; i += stride) {
        int px = i & 65535;
        int cp = (i >> 16) & 31;
        int b  = i >> 21;
        const float* p = x + ((size_t)(b*CC + cp*2))*HWW + px;
        uint32_t lw;
        uint32_t hw = pack_split2(p[0], p[HWW], lw);
        g_xh[i] = hw;
        g_xl[i] = lw;
    }
}

// ===========================================================================
// om conv via mma (dil=1): 128px x 32oc(27 used), K=576.
// 8 warps = 4 m-warps x 2 n-warps; warp tile 32px x 16oc.
// smem: A_hi@0 16K, A_lo@16K, B_hi@32K 4K, B_lo@36K 4K  (40960 total)
// ===========================================================================
#define OM_SMEM 40960
__global__ void __launch_bounds__(256)
om_tc_kernel(const uint32_t* __restrict__ inH, const uint32_t* __restrict__ inL,
             const unsigned short* __restrict__ wHi,
             const unsigned short* __restrict__ wLo,
             const float* __restrict__ b_om) {
    extern __shared__ char smem[];
    const int x0 = blockIdx.x * 128;
    const int y  = blockIdx.y;
    const int b  = blockIdx.z;
    const int tid = threadIdx.x;
    const int warp = tid >> 5, lane = tid & 31;
    const int wm = warp & 3, wn = warp >> 2;
    const uint32_t sbase = smem_u32(smem);

    float acc[2][2][4];
#pragma unroll
    for (int mt = 0; mt < 2; mt++)
#pragma unroll
        for (int nt = 0; nt < 2; nt++)
#pragma unroll
            for (int j = 0; j < 4; j++) acc[mt][nt][j] = 0.f;

    for (int tap = 0; tap < 9; tap++) {
        __syncthreads();
        const int dy = tap / 3, kx = tap - dy*3;
        const int rowy = y + dy - 1;
        const bool rowok = (unsigned)rowy < HH;
        for (int i = tid; i < 4096; i += 256) {
            int px = i & 127, cp = i >> 7;
            int xin = x0 + px + kx - 1;
            uint32_t h = 0, l = 0;
            if (rowok && (unsigned)xin < WW) {
                size_t idx = ((size_t)(b*32 + cp))*HWW + rowy*WW + xin;
                h = inH[idx];
                l = inL[idx];
            }
            uint32_t off = (uint32_t)px*128u
                         + ((((uint32_t)(cp>>2)) ^ ((uint32_t)px & 7u)) << 4)
                         + ((uint32_t)cp & 3u)*4u;
            *(uint32_t*)(smem + off)         = h;
            *(uint32_t*)(smem + 16384 + off) = l;
        }
        {
            const uint4* sh = (const uint4*)(wHi + tap*2048);
            const uint4* sl = (const uint4*)(wLo + tap*2048);
            uint4* dh = (uint4*)(smem + 32768);
            uint4* dl = (uint4*)(smem + 36864);
            if (tid < 256) {
                for (int i = tid; i < 256; i += 256) { dh[i] = sh[i]; dl[i] = sl[i]; }
            }
        }
        __syncthreads();

#pragma unroll
        for (int ch = 0; ch < 4; ch++) {
            uint32_t ahi[2][4], alo[2][4], bhi[4], blo[4];
#pragma unroll
            for (int mt = 0; mt < 2; mt++) {
                int pxr = wm*32 + mt*16 + (lane & 15);
                uint32_t u = (uint32_t)(ch*2 + (lane >> 4));
                uint32_t addr = sbase + (uint32_t)pxr*128u
                              + ((u ^ ((uint32_t)pxr & 7u)) << 4);
                ldm4(ahi[mt], addr);
                ldm4(alo[mt], addr + 16384u);
            }
            {
                int ocr = wn*16 + (lane & 7) + ((lane >> 4) << 3);
                uint32_t u = (uint32_t)(ch*2 + ((lane >> 3) & 1));
                uint32_t addr = sbase + 32768u + (uint32_t)ocr*128u
                              + ((u ^ ((uint32_t)ocr & 7u)) << 4);
                ldm4(bhi, addr);
                ldm4(blo, addr + 4096u);
            }
#pragma unroll
            for (int mt = 0; mt < 2; mt++)
#pragma unroll
                for (int nt = 0; nt < 2; nt++) {
                    mma_bf16(acc[mt][nt], ahi[mt], &bhi[nt*2]);
                    mma_bf16(acc[mt][nt], ahi[mt], &blo[nt*2]);
                    mma_bf16(acc[mt][nt], alo[mt], &bhi[nt*2]);
                }
        }
    }

#pragma unroll
    for (int mt = 0; mt < 2; mt++)
#pragma unroll
        for (int nt = 0; nt < 2; nt++) {
            int pxr = wm*32 + mt*16 + (lane >> 2);
            int occ = wn*16 + nt*8 + ((lane & 3) << 1);
            if (occ < 27) {
                float bo = b_om[occ];
                float* o0 = g_om + ((size_t)(b*27 + occ))*HWW + y*WW + x0;
                o0[pxr]     = acc[mt][nt][0] + bo;
                o0[pxr + 8] = acc[mt][nt][2] + bo;
            }
            if (occ + 1 < 27) {
                float bo = b_om[occ+1];
                float* o1 = g_om + ((size_t)(b*27 + occ+1))*HWW + y*WW + x0;
                o1[pxr]     = acc[mt][nt][1] + bo;
                o1[pxr + 8] = acc[mt][nt][3] + bo;
            }
        }
}

// ===========================================================================
// DCNv2 + bn1 + relu via mma: per tap, bilinear-gather A tile then GEMM.
// smem: A_hi@0 16K, A_lo@16K, B_hi@32K 8K, B_lo@40K 8K, geom idx@48K 2K,
//       geom w@50K 2K  (53248 total)
// ===========================================================================
#define DCN_GI 49152
#define DCN_GW 51200
#define DCN_SMEM 53248
__global__ void __launch_bounds__(256)
dcn_tc_kernel(const float* __restrict__ x,
              const unsigned short* __restrict__ wHi,
              const unsigned short* __restrict__ wLo,
              const float* __restrict__ bias,
              const float* __restrict__ bg, const float* __restrict__ bb,
              const float* __restrict__ bm, const float* __restrict__ bv) {
    extern __shared__ char smem[];
    const int x0 = blockIdx.x * 128;
    const int y  = blockIdx.y;
    const int b  = blockIdx.z;
    const int tid = threadIdx.x;
    const int warp = tid >> 5, lane = tid & 31;
    const int wm = warp & 3, wn = warp >> 2;
    const uint32_t sbase = smem_u32(smem);

    __shared__ float s_s[64], s_d[64];
    if (tid < 64) {
        float s = bg[tid] * rsqrtf(bv[tid] + 1e-5f);
        s_s[tid] = s;
        s_d[tid] = (bias[tid] - bm[tid]) * s + bb[tid];
    }

    float acc[2][4][4];
#pragma unroll
    for (int mt = 0; mt < 2; mt++)
#pragma unroll
        for (int nt = 0; nt < 4; nt++)
#pragma unroll
            for (int j = 0; j < 4; j++) acc[mt][nt][j] = 0.f;

    int* s_idx = (int*)(smem + DCN_GI);
    float* s_gw = (float*)(smem + DCN_GW);

    for (int tap = 0; tap < 9; tap++) {
        __syncthreads();
        // geometry for this tap (one thread per px)
        if (tid < 128) {
            int px = tid, xx = x0 + px;
            float o1 = g_om[((b*27 +      tap)*HH + y)*WW + xx];
            float o2 = g_om[((b*27 +  9 + tap)*HH + y)*WW + xx];
            float ml = g_om[((b*27 + 18 + tap)*HH + y)*WW + xx];
            float m  = 1.f / (1.f + expf(-ml));
            float py  = (float)(y  + (tap/3) - 1) + o1;
            float pxf = (float)(xx + (tap%3) - 1) + o2;
            float fy = floorf(py), fx = floorf(pxf);
            float wy1 = py - fy, wx1 = pxf - fx;
            int iy0 = (int)fy, ix0 = (int)fx;
#pragma unroll
            for (int j = 0; j < 4; j++) {
                int dy = j >> 1, dx = j & 1;
                int yi = iy0 + dy, xi = ix0 + dx;
                bool valid = ((unsigned)yi < HH) && ((unsigned)xi < WW);
                float wgt = (dy ? wy1 : 1.f - wy1) * (dx ? wx1 : 1.f - wx1);
                s_gw[px*4 + j]  = valid ? m * wgt : 0.f;
                int yc = min(max(yi, 0), HH-1);
                int xc = min(max(xi, 0), WW-1);
                s_idx[px*4 + j] = yc*WW + xc;
            }
        }
        // B tiles for this tap
        {
            const uint4* sh = (const uint4*)(wHi + tap*4096);
            const uint4* sl = (const uint4*)(wLo + tap*4096);
            uint4* dh = (uint4*)(smem + 32768);
            uint4* dl = (uint4*)(smem + 40960);
            for (int i = tid; i < 512; i += 256) { dh[i] = sh[i]; dl[i] = sl[i]; }
        }
        __syncthreads();
        // A tile: bilinear-sample two channels per thread-iteration
        for (int i = tid; i < 4096; i += 256) {
            int px = i & 127, cp = i >> 7;
            const int*   ip = s_idx + px*4;
            const float* gp = s_gw + px*4;
            const float* xc0 = x + ((size_t)(b*CC + 2*cp))*HWW;
            const float* xc1 = xc0 + HWW;
            float g0 = gp[0], g1 = gp[1], g2 = gp[2], g3 = gp[3];
            int i0 = ip[0], i1 = ip[1], i2 = ip[2], i3 = ip[3];
            float v0 = g0*xc0[i0] + g1*xc0[i1] + g2*xc0[i2] + g3*xc0[i3];
            float v1 = g0*xc1[i0] + g1*xc1[i1] + g2*xc1[i2] + g3*xc1[i3];
            uint32_t lw;
            uint32_t hw = pack_split2(v0, v1, lw);
            uint32_t off = (uint32_t)px*128u
                         + ((((uint32_t)(cp>>2)) ^ ((uint32_t)px & 7u)) << 4)
                         + ((uint32_t)cp & 3u)*4u;
            *(uint32_t*)(smem + off)         = hw;
            *(uint32_t*)(smem + 16384 + off) = lw;
        }
        __syncthreads();

#pragma unroll
        for (int ch = 0; ch < 4; ch++) {
            uint32_t ahi[2][4], alo[2][4], bhi[2][4], blo[2][4];
#pragma unroll
            for (int mt = 0; mt < 2; mt++) {
                int pxr = wm*32 + mt*16 + (lane & 15);
                uint32_t u = (uint32_t)(ch*2 + (lane >> 4));
                uint32_t addr = sbase + (uint32_t)pxr*128u
                              + ((u ^ ((uint32_t)pxr & 7u)) << 4);
                ldm4(ahi[mt], addr);
                ldm4(alo[mt], addr + 16384u);
            }
#pragma unroll
            for (int half = 0; half < 2; half++) {
                int ocr = wn*32 + half*16 + (lane & 7) + ((lane >> 4) << 3);
                uint32_t u = (uint32_t)(ch*2 + ((lane >> 3) & 1));
                uint32_t addr = sbase + 32768u + (uint32_t)ocr*128u
                              + ((u ^ ((uint32_t)ocr & 7u)) << 4);
                ldm4(bhi[half], addr);
                ldm4(blo[half], addr + 8192u);
            }
#pragma unroll
            for (int mt = 0; mt < 2; mt++)
#pragma unroll
                for (int nt = 0; nt < 4; nt++) {
                    const uint32_t* bh = &bhi[nt >> 1][(nt & 1)*2];
                    const uint32_t* bl = &blo[nt >> 1][(nt & 1)*2];
                    mma_bf16(acc[mt][nt], ahi[mt], bh);
                    mma_bf16(acc[mt][nt], ahi[mt], bl);
                    mma_bf16(acc[mt][nt], alo[mt], bh);
                }
        }
    }

    // epilogue: bn1 + relu -> packed bf16 hi/lo planes
    __syncthreads();
#pragma unroll
    for (int mt = 0; mt < 2; mt++)
#pragma unroll
        for (int nt = 0; nt < 4; nt++) {
            int pxr = wm*32 + mt*16 + (lane >> 2);
            int occ = wn*32 + nt*8 + ((lane & 3) << 1);
            float s0 = s_s[occ],   d0 = s_d[occ];
            float s1 = s_s[occ+1], d1 = s_d[occ+1];
            size_t base = ((size_t)(b*32 + (occ >> 1)))*HWW + y*WW + x0;
            float v0 = fmaf(acc[mt][nt][0], s0, d0); v0 = v0 > 0.f ? v0 : 0.f;
            float v1 = fmaf(acc[mt][nt][1], s1, d1); v1 = v1 > 0.f ? v1 : 0.f;
            float v2 = fmaf(acc[mt][nt][2], s0, d0); v2 = v2 > 0.f ? v2 : 0.f;
            float v3 = fmaf(acc[mt][nt][3], s1, d1); v3 = v3 > 0.f ? v3 : 0.f;
            uint32_t lw0, lw1;
            uint32_t hw0 = pack_split2(v0, v1, lw0);
            uint32_t hw1 = pack_split2(v2, v3, lw1);
            g_h1h[base + pxr]     = hw0;
            g_h1l[base + pxr]     = lw0;
            g_h1h[base + pxr + 8] = hw1;
            g_h1l[base + pxr + 8] = lw1;
        }
}

// ===========================================================================
// conv64 (dil=2) + bn + relu via mma; packed bf16 hi/lo in AND out.
// smem: A_hi@0 16K, A_lo@16K, B_hi@32K 8K, B_lo@40K 8K  (49152 total)
// ===========================================================================
#define C64_SMEM 49152
__global__ void __launch_bounds__(256)
conv64_tc_kernel(const uint32_t* __restrict__ inH, const uint32_t* __restrict__ inL,
                 const unsigned short* __restrict__ wHi,
                 const unsigned short* __restrict__ wLo,
                 const float* __restrict__ bias,
                 const float* __restrict__ bg, const float* __restrict__ bb,
                 const float* __restrict__ bm, const float* __restrict__ bv,
                 uint32_t* __restrict__ outH, uint32_t* __restrict__ outL) {
    extern __shared__ char smem[];
    const int x0 = blockIdx.x * 128;
    const int y  = blockIdx.y;
    const int b  = blockIdx.z;
    const int tid = threadIdx.x;
    const int warp = tid >> 5, lane = tid & 31;
    const int wm = warp & 3, wn = warp >> 2;
    const uint32_t sbase = smem_u32(smem);

    __shared__ float s_s[64], s_d[64];
    if (tid < 64) {
        float s = bg[tid] * rsqrtf(bv[tid] + 1e-5f);
        s_s[tid] = s;
        s_d[tid] = (bias[tid] - bm[tid]) * s + bb[tid];
    }

    float acc[2][4][4];
#pragma unroll
    for (int mt = 0; mt < 2; mt++)
#pragma unroll
        for (int nt = 0; nt < 4; nt++)
#pragma unroll
            for (int j = 0; j < 4; j++) acc[mt][nt][j] = 0.f;

    for (int tap = 0; tap < 9; tap++) {
        __syncthreads();
        const int dy = tap / 3, kx = tap - dy*3;
        const int rowy = y + 2*dy - 2;
        const bool rowok = (unsigned)rowy < HH;
        for (int i = tid; i < 4096; i += 256) {
            int px = i & 127, cp = i >> 7;
            int xin = x0 + px + 2*kx - 2;
            uint32_t h = 0, l = 0;
            if (rowok && (unsigned)xin < WW) {
                size_t idx = ((size_t)(b*32 + cp))*HWW + rowy*WW + xin;
                h = inH[idx];
                l = inL[idx];
            }
            uint32_t off = (uint32_t)px*128u
                         + ((((uint32_t)(cp>>2)) ^ ((uint32_t)px & 7u)) << 4)
                         + ((uint32_t)cp & 3u)*4u;
            *(uint32_t*)(smem + off)         = h;
            *(uint32_t*)(smem + 16384 + off) = l;
        }
        {
            const uint4* sh = (const uint4*)(wHi + tap*4096);
            const uint4* sl = (const uint4*)(wLo + tap*4096);
            uint4* dh = (uint4*)(smem + 32768);
            uint4* dl = (uint4*)(smem + 40960);
            for (int i = tid; i < 512; i += 256) { dh[i] = sh[i]; dl[i] = sl[i]; }
        }
        __syncthreads();

#pragma unroll
        for (int ch = 0; ch < 4; ch++) {
            uint32_t ahi[2][4], alo[2][4], bhi[2][4], blo[2][4];
#pragma unroll
            for (int mt = 0; mt < 2; mt++) {
                int pxr = wm*32 + mt*16 + (lane & 15);
                uint32_t u = (uint32_t)(ch*2 + (lane >> 4));
                uint32_t addr = sbase + (uint32_t)pxr*128u
                              + ((u ^ ((uint32_t)pxr & 7u)) << 4);
                ldm4(ahi[mt], addr);
                ldm4(alo[mt], addr + 16384u);
            }
#pragma unroll
            for (int half = 0; half < 2; half++) {
                int ocr = wn*32 + half*16 + (lane & 7) + ((lane >> 4) << 3);
                uint32_t u = (uint32_t)(ch*2 + ((lane >> 3) & 1));
                uint32_t addr = sbase + 32768u + (uint32_t)ocr*128u
                              + ((u ^ ((uint32_t)ocr & 7u)) << 4);
                ldm4(bhi[half], addr);
                ldm4(blo[half], addr + 8192u);
            }
#pragma unroll
            for (int mt = 0; mt < 2; mt++)
#pragma unroll
                for (int nt = 0; nt < 4; nt++) {
                    const uint32_t* bh = &bhi[nt >> 1][(nt & 1)*2];
                    const uint32_t* bl = &blo[nt >> 1][(nt & 1)*2];
                    mma_bf16(acc[mt][nt], ahi[mt], bh);
                    mma_bf16(acc[mt][nt], ahi[mt], bl);
                    mma_bf16(acc[mt][nt], alo[mt], bh);
                }
        }
    }

    // epilogue: bn + relu -> packed bf16 hi/lo planes
    __syncthreads();
#pragma unroll
    for (int mt = 0; mt < 2; mt++)
#pragma unroll
        for (int nt = 0; nt < 4; nt++) {
            int pxr = wm*32 + mt*16 + (lane >> 2);
            int occ = wn*32 + nt*8 + ((lane & 3) << 1);
            float s0 = s_s[occ],   d0 = s_d[occ];
            float s1 = s_s[occ+1], d1 = s_d[occ+1];
            size_t base = ((size_t)(b*32 + (occ >> 1)))*HWW + y*WW + x0;
            float v0 = fmaf(acc[mt][nt][0], s0, d0); v0 = v0 > 0.f ? v0 : 0.f;
            float v1 = fmaf(acc[mt][nt][1], s1, d1); v1 = v1 > 0.f ? v1 : 0.f;
            float v2 = fmaf(acc[mt][nt][2], s0, d0); v2 = v2 > 0.f ? v2 : 0.f;
            float v3 = fmaf(acc[mt][nt][3], s1, d1); v3 = v3 > 0.f ? v3 : 0.f;
            uint32_t lw0, lw1;
            uint32_t hw0 = pack_split2(v0, v1, lw0);
            uint32_t hw1 = pack_split2(v2, v3, lw1);
            outH[base + pxr]     = hw0;
            outL[base + pxr]     = lw0;
            outH[base + pxr + 8] = hw1;
            outL[base + pxr + 8] = lw1;
        }
}

// ---------------------------------------------------------------------------
// Final 64->1 3x3 conv pad1 + sigmoid + clip; reads packed h3 planes.
// ---------------------------------------------------------------------------
__global__ void __launch_bounds__(256)
final_kernel(const float* __restrict__ w3, const float* __restrict__ b3,
             float* __restrict__ out) {
    const int y = blockIdx.x;
    const int b = blockIdx.y;
    const int tid = threadIdx.x;  // 256 = W

    __shared__ uint32_t s_rh[3][260], s_rl[3][260];
    __shared__ float s_w3[576];
    for (int i = tid; i < 576; i += 256) s_w3[i] = w3[i];

    float acc = 0.f;
    for (int cp = 0; cp < 32; cp++) {
        __syncthreads();
        const uint32_t* hp = g_h3h + ((size_t)(b*32 + cp))*HWW;
        const uint32_t* lp = g_h3l + ((size_t)(b*32 + cp))*HWW;
        for (int i = tid; i < 3*258; i += 256) {
            int r = i / 258, col = i - r*258;
            int yy = y + r - 1, xx = col - 1;
            uint32_t h = 0, l = 0;
            if ((unsigned)yy < HH && (unsigned)xx < WW) {
                h = hp[yy*WW + xx];
                l = lp[yy*WW + xx];
            }
            s_rh[r][col] = h;
            s_rl[r][col] = l;
        }
        __syncthreads();
        const float* w0 = s_w3 + (2*cp)*9;
        const float* w1 = w0 + 9;
#pragma unroll
        for (int ky = 0; ky < 3; ky++)
#pragma unroll
            for (int kx = 0; kx < 3; kx++) {
                uint32_t h = s_rh[ky][tid + kx];
                uint32_t l = s_rl[ky][tid + kx];
                float v0 = __uint_as_float(h << 16) + __uint_as_float(l << 16);
                float v1 = __uint_as_float(h & 0xFFFF0000u)
                         + __uint_as_float(l & 0xFFFF0000u);
                acc = fmaf(w0[ky*3+kx], v0, acc);
                acc = fmaf(w1[ky*3+kx], v1, acc);
            }
    }
    float v = acc + b3[0];
    float sg = 1.f / (1.f + expf(-v));
    sg = fminf(fmaxf(sg, 1e-4f), 1.f - 1e-4f);
    out[((size_t)b*HH + y)*WW + tid] = sg;
}

// ---------------------------------------------------------------------------
extern "C" void kernel_launch(void* const* d_in, const int* in_sizes, int n_in,
                              void* d_out, int out_size) {
    (void)n_in; (void)out_size;
    const float* x     = (const float*)d_in[0];
    const float* w_om  = (const float*)d_in[1];
    const float* b_om  = (const float*)d_in[2];
    const float* w_dcn = (const float*)d_in[3];
    const float* b_dcn = (const float*)d_in[4];
    const float* bn1g  = (const float*)d_in[5];
    const float* bn1b  = (const float*)d_in[6];
    const float* bn1m  = (const float*)d_in[7];
    const float* bn1v  = (const float*)d_in[8];

    const float *w_h, *b_h, *w_w, *b_w, *w3, *b3;
    const float *bn2g, *bn2b, *bn2m, *bn2v, *bn3g, *bn3b, *bn3m, *bn3v;
    if (in_sizes[9] == CC) {
        // dict order
        bn2g = (const float*)d_in[9];  bn2b = (const float*)d_in[10];
        bn2m = (const float*)d_in[11]; bn2v = (const float*)d_in[12];
        bn3g = (const float*)d_in[13]; bn3b = (const float*)d_in[14];
        bn3m = (const float*)d_in[15]; bn3v = (const float*)d_in[16];
        w_h  = (const float*)d_in[17]; b_h  = (const float*)d_in[18];
        w_w  = (const float*)d_in[19]; b_w  = (const float*)d_in[20];
        w3   = (const float*)d_in[21]; b3   = (const float*)d_in[22];
    } else {
        // signature order
        w_h  = (const float*)d_in[9];  b_h  = (const float*)d_in[10];
        bn2g = (const float*)d_in[11]; bn2b = (const float*)d_in[12];
        bn2m = (const float*)d_in[13]; bn2v = (const float*)d_in[14];
        w_w  = (const float*)d_in[15]; b_w  = (const float*)d_in[16];
        bn3g = (const float*)d_in[17]; bn3b = (const float*)d_in[18];
        bn3m = (const float*)d_in[19]; bn3v = (const float*)d_in[20];
        w3   = (const float*)d_in[21]; b3   = (const float*)d_in[22];
    }
    float* out = (float*)d_out;

    uint32_t *p_xh, *p_xl, *p_h1h, *p_h1l, *p_h2h, *p_h2l, *p_h3h, *p_h3l;
    unsigned short *p_wBom_hi, *p_wBom_lo, *p_wBd_hi, *p_wBd_lo;
    unsigned short *p_wBh_hi, *p_wBh_lo, *p_wBw_hi, *p_wBw_lo;
    cudaGetSymbolAddress((void**)&p_xh,  g_xh);
    cudaGetSymbolAddress((void**)&p_xl,  g_xl);
    cudaGetSymbolAddress((void**)&p_h1h, g_h1h);
    cudaGetSymbolAddress((void**)&p_h1l, g_h1l);
    cudaGetSymbolAddress((void**)&p_h2h, g_h2h);
    cudaGetSymbolAddress((void**)&p_h2l, g_h2l);
    cudaGetSymbolAddress((void**)&p_h3h, g_h3h);
    cudaGetSymbolAddress((void**)&p_h3l, g_h3l);
    cudaGetSymbolAddress((void**)&p_wBom_hi, g_wBom_hi);
    cudaGetSymbolAddress((void**)&p_wBom_lo, g_wBom_lo);
    cudaGetSymbolAddress((void**)&p_wBd_hi, g_wBd_hi);
    cudaGetSymbolAddress((void**)&p_wBd_lo, g_wBd_lo);
    cudaGetSymbolAddress((void**)&p_wBh_hi, g_wBh_hi);
    cudaGetSymbolAddress((void**)&p_wBh_lo, g_wBh_lo);
    cudaGetSymbolAddress((void**)&p_wBw_hi, g_wBw_hi);
    cudaGetSymbolAddress((void**)&p_wBw_lo, g_wBw_lo);

    cudaFuncSetAttribute(om_tc_kernel,
                         cudaFuncAttributeMaxDynamicSharedMemorySize, OM_SMEM);
    cudaFuncSetAttribute(dcn_tc_kernel,
                         cudaFuncAttributeMaxDynamicSharedMemorySize, DCN_SMEM);
    cudaFuncSetAttribute(conv64_tc_kernel,
                         cudaFuncAttributeMaxDynamicSharedMemorySize, C64_SMEM);

    prep_weights_kernel<<<72, 256>>>(w_om, w_dcn, w_h, w_w);
    prep_xsplit_kernel<<<2048, 256>>>(x);

    dim3 gridc(WW/128, HH, BB);
    om_tc_kernel<<<gridc, 256, OM_SMEM>>>(p_xh, p_xl, p_wBom_hi, p_wBom_lo, b_om);
    dcn_tc_kernel<<<gridc, 256, DCN_SMEM>>>(x, p_wBd_hi, p_wBd_lo, b_dcn,
                                            bn1g, bn1b, bn1m, bn1v);
    conv64_tc_kernel<<<gridc, 256, C64_SMEM>>>(p_h1h, p_h1l, p_wBh_hi, p_wBh_lo,
                                               b_h, bn2g, bn2b, bn2m, bn2v,
                                               p_h2h, p_h2l);
    conv64_tc_kernel<<<gridc, 256, C64_SMEM>>>(p_h2h, p_h2l, p_wBw_hi, p_wBw_lo,
                                               b_w, bn3g, bn3b, bn3m, bn3v,
                                               p_h3h, p_h3l);
    final_kernel<<<dim3(HH, BB), 256>>>(w3, b3, out);
}

// round 11
// speedup vs baseline: 2.5410x; 1.0705x over previous
#include <cuda_runtime.h>
#include <math.h>
#include <stdint.h>

#define BB 2
#define CC 64
#define HH 256
#define WW 256
#define HWW (HH*WW)

// ---- scratch (device globals; no runtime allocation allowed) ----
__device__ float g_om[BB*27*HWW];                         // offset/mask conv out (fp32)
__device__ float g_xt[BB*HWW*64];                         // x transposed NHWC fp32
__device__ uint32_t g_xh[BB*32*HWW], g_xl[BB*32*HWW];     // x packed bf16 hi/lo c-pairs
__device__ uint32_t g_h1h[BB*32*HWW], g_h1l[BB*32*HWW];   // h1 packed
__device__ uint32_t g_h2h[BB*32*HWW], g_h2l[BB*32*HWW];   // h2 packed
__device__ uint32_t g_h3h[BB*32*HWW], g_h3l[BB*32*HWW];   // h3 packed
// bf16 hi/lo split, swizzled [tap][oc][c] B tiles
__device__ __align__(16) unsigned short g_wBom_hi[9*32*64], g_wBom_lo[9*32*64];
__device__ __align__(16) unsigned short g_wBd_hi[9*64*64],  g_wBd_lo[9*64*64];
__device__ __align__(16) unsigned short g_wBh_hi[9*64*64],  g_wBh_lo[9*64*64];
__device__ __align__(16) unsigned short g_wBw_hi[9*64*64],  g_wBw_lo[9*64*64];

// ---- bf16 round-to-nearest-even split helpers ----
__device__ __forceinline__ uint32_t bf16_rne(float v) {
    uint32_t x = __float_as_uint(v);
    return (x + 0x7FFFu + ((x >> 16) & 1u)) >> 16;
}
__device__ __forceinline__ void bf16_split(float v, uint32_t& hb, uint32_t& lb) {
    hb = bf16_rne(v);
    float hf = __uint_as_float(hb << 16);
    lb = bf16_rne(v - hf);
}
__device__ __forceinline__ uint32_t pack_split2(float v0, float v1, uint32_t& lw) {
    uint32_t h0, l0, h1, l1;
    bf16_split(v0, h0, l0);
    bf16_split(v1, h1, l1);
    lw = l0 | (l1 << 16);
    return h0 | (h1 << 16);
}

// ---- warp-level tensor ops (sm_80-lineage; valid on plain sm_103 target) ----
__device__ __forceinline__ void ldm4(uint32_t* r, uint32_t addr) {
    asm volatile("ldmatrix.sync.aligned.m8n8.x4.shared.b16 {%0,%1,%2,%3}, [%4];"
                 : "=r"(r[0]), "=r"(r[1]), "=r"(r[2]), "=r"(r[3]) : "r"(addr));
}
__device__ __forceinline__ void mma_bf16(float* d, const uint32_t* a,
                                         const uint32_t* b) {
    asm volatile(
        "mma.sync.aligned.m16n8k16.row.col.f32.bf16.bf16.f32 "
        "{%0,%1,%2,%3}, {%4,%5,%6,%7}, {%8,%9}, {%0,%1,%2,%3};"
        : "+f"(d[0]), "+f"(d[1]), "+f"(d[2]), "+f"(d[3])
        : "r"(a[0]), "r"(a[1]), "r"(a[2]), "r"(a[3]), "r"(b[0]), "r"(b[1]));
}
__device__ __forceinline__ uint32_t smem_u32(const void* p) {
    uint32_t a;
    asm("{ .reg .u64 t; cvta.to.shared.u64 t, %1; cvt.u32.u64 %0, t; }"
        : "=r"(a) : "l"(p));
    return a;
}

// ===========================================================================
// Weight prep: bf16 hi/lo swizzled B tiles for om (32-oc pad), dcn, h, w.
// ===========================================================================
__global__ void prep_weights_kernel(const float* __restrict__ w_om,
                                    const float* __restrict__ w_dcn,
                                    const float* __restrict__ w_h,
                                    const float* __restrict__ w_w) {
    const int i0 = blockIdx.x * blockDim.x + threadIdx.x;
    const int stride = gridDim.x * blockDim.x;
    for (int i = i0; i < 32*CC*9; i += stride) {
        int oc = i / 576; int r = i - oc*576; int c = r / 9, tap = r - c*9;
        float v = (oc < 27) ? w_om[(oc*CC + c)*9 + tap] : 0.f;
        int dst = tap*2048 + oc*64 + (((c>>3) ^ (oc&7)) << 3) + (c & 7);
        uint32_t hb, lb;
        bf16_split(v, hb, lb);
        g_wBom_hi[dst] = (unsigned short)hb;
        g_wBom_lo[dst] = (unsigned short)lb;
    }
    for (int i = i0; i < CC*CC*9; i += stride) {
        int oc = i / 576; int r = i - oc*576; int c = r / 9, tap = r - c*9;
        int dst = tap*4096 + oc*64 + (((c>>3) ^ (oc&7)) << 3) + (c & 7);
        uint32_t hb, lb;
        bf16_split(w_dcn[i], hb, lb);
        g_wBd_hi[dst] = (unsigned short)hb;
        g_wBd_lo[dst] = (unsigned short)lb;
        bf16_split(w_h[i], hb, lb);
        g_wBh_hi[dst] = (unsigned short)hb;
        g_wBh_lo[dst] = (unsigned short)lb;
        bf16_split(w_w[i], hb, lb);
        g_wBw_hi[dst] = (unsigned short)hb;
        g_wBw_lo[dst] = (unsigned short)lb;
    }
}

// ===========================================================================
// x prep: tiled transpose -> x_t NHWC fp32, plus packed bf16 hi/lo planes.
// Block handles 64 px x 64 c. smem stride 65 words = conflict-free both ways.
// ===========================================================================
__global__ void __launch_bounds__(256)
prep_x_kernel(const float* __restrict__ x) {
    __shared__ float s[64*65];
    const int px0 = blockIdx.x * 64;
    const int b   = blockIdx.y;
    const int tid = threadIdx.x;
    for (int i = tid; i < 4096; i += 256) {
        int c = i >> 6, p = i & 63;
        s[p*65 + c] = x[((size_t)(b*CC + c))*HWW + px0 + p];
    }
    __syncthreads();
    for (int i = tid; i < 4096; i += 256) {
        int p = i >> 6, c = i & 63;
        g_xt[((size_t)b*HWW + px0 + p)*64 + c] = s[p*65 + c];
    }
    for (int i = tid; i < 2048; i += 256) {
        int cp = i >> 6, p = i & 63;
        uint32_t lw;
        uint32_t hw = pack_split2(s[p*65 + 2*cp], s[p*65 + 2*cp + 1], lw);
        size_t o = ((size_t)(b*32 + cp))*HWW + px0 + p;
        g_xh[o] = hw;
        g_xl[o] = lw;
    }
}

// ===========================================================================
// om conv via mma (dil=1): 128px x 32oc(27 used), K=576.
// smem: A_hi@0 16K, A_lo@16K, B_hi@32K 4K, B_lo@36K 4K  (40960 total)
// ===========================================================================
#define OM_SMEM 40960
__global__ void __launch_bounds__(256)
om_tc_kernel(const uint32_t* __restrict__ inH, const uint32_t* __restrict__ inL,
             const unsigned short* __restrict__ wHi,
             const unsigned short* __restrict__ wLo,
             const float* __restrict__ b_om) {
    extern __shared__ char smem[];
    const int x0 = blockIdx.x * 128;
    const int y  = blockIdx.y;
    const int b  = blockIdx.z;
    const int tid = threadIdx.x;
    const int warp = tid >> 5, lane = tid & 31;
    const int wm = warp & 3, wn = warp >> 2;
    const uint32_t sbase = smem_u32(smem);

    float acc[2][2][4];
#pragma unroll
    for (int mt = 0; mt < 2; mt++)
#pragma unroll
        for (int nt = 0; nt < 2; nt++)
#pragma unroll
            for (int j = 0; j < 4; j++) acc[mt][nt][j] = 0.f;

    for (int tap = 0; tap < 9; tap++) {
        __syncthreads();
        const int dy = tap / 3, kx = tap - dy*3;
        const int rowy = y + dy - 1;
        const bool rowok = (unsigned)rowy < HH;
        for (int i = tid; i < 4096; i += 256) {
            int px = i & 127, cp = i >> 7;
            int xin = x0 + px + kx - 1;
            uint32_t h = 0, l = 0;
            if (rowok && (unsigned)xin < WW) {
                size_t idx = ((size_t)(b*32 + cp))*HWW + rowy*WW + xin;
                h = inH[idx];
                l = inL[idx];
            }
            uint32_t off = (uint32_t)px*128u
                         + ((((uint32_t)(cp>>2)) ^ ((uint32_t)px & 7u)) << 4)
                         + ((uint32_t)cp & 3u)*4u;
            *(uint32_t*)(smem + off)         = h;
            *(uint32_t*)(smem + 16384 + off) = l;
        }
        {
            const uint4* sh = (const uint4*)(wHi + tap*2048);
            const uint4* sl = (const uint4*)(wLo + tap*2048);
            uint4* dh = (uint4*)(smem + 32768);
            uint4* dl = (uint4*)(smem + 36864);
            for (int i = tid; i < 256; i += 256) { dh[i] = sh[i]; dl[i] = sl[i]; }
        }
        __syncthreads();

#pragma unroll
        for (int ch = 0; ch < 4; ch++) {
            uint32_t ahi[2][4], alo[2][4], bhi[4], blo[4];
#pragma unroll
            for (int mt = 0; mt < 2; mt++) {
                int pxr = wm*32 + mt*16 + (lane & 15);
                uint32_t u = (uint32_t)(ch*2 + (lane >> 4));
                uint32_t addr = sbase + (uint32_t)pxr*128u
                              + ((u ^ ((uint32_t)pxr & 7u)) << 4);
                ldm4(ahi[mt], addr);
                ldm4(alo[mt], addr + 16384u);
            }
            {
                int ocr = wn*16 + (lane & 7) + ((lane >> 4) << 3);
                uint32_t u = (uint32_t)(ch*2 + ((lane >> 3) & 1));
                uint32_t addr = sbase + 32768u + (uint32_t)ocr*128u
                              + ((u ^ ((uint32_t)ocr & 7u)) << 4);
                ldm4(bhi, addr);
                ldm4(blo, addr + 4096u);
            }
#pragma unroll
            for (int mt = 0; mt < 2; mt++)
#pragma unroll
                for (int nt = 0; nt < 2; nt++) {
                    mma_bf16(acc[mt][nt], ahi[mt], &bhi[nt*2]);
                    mma_bf16(acc[mt][nt], ahi[mt], &blo[nt*2]);
                    mma_bf16(acc[mt][nt], alo[mt], &bhi[nt*2]);
                }
        }
    }

#pragma unroll
    for (int mt = 0; mt < 2; mt++)
#pragma unroll
        for (int nt = 0; nt < 2; nt++) {
            int pxr = wm*32 + mt*16 + (lane >> 2);
            int occ = wn*16 + nt*8 + ((lane & 3) << 1);
            if (occ < 27) {
                float bo = b_om[occ];
                float* o0 = g_om + ((size_t)(b*27 + occ))*HWW + y*WW + x0;
                o0[pxr]     = acc[mt][nt][0] + bo;
                o0[pxr + 8] = acc[mt][nt][2] + bo;
            }
            if (occ + 1 < 27) {
                float bo = b_om[occ+1];
                float* o1 = g_om + ((size_t)(b*27 + occ+1))*HWW + y*WW + x0;
                o1[pxr]     = acc[mt][nt][1] + bo;
                o1[pxr + 8] = acc[mt][nt][3] + bo;
            }
        }
}

// ===========================================================================
// DCNv2 + bn1 + relu via mma, NHWC coalesced gather from g_xt.
// Gather mapping: cp = lane (coalesced float2), px warp-uniform.
// smem: A_hi@0 16K, A_lo@16K, B_hi@32K 8K, B_lo@40K 8K, geom idx@48K 2K,
//       geom w@50K 2K  (53248 total)
// ===========================================================================
#define DCN_GI 49152
#define DCN_GW 51200
#define DCN_SMEM 53248
__global__ void __launch_bounds__(256)
dcn_tc_kernel(const unsigned short* __restrict__ wHi,
              const unsigned short* __restrict__ wLo,
              const float* __restrict__ bias,
              const float* __restrict__ bg, const float* __restrict__ bb,
              const float* __restrict__ bm, const float* __restrict__ bv) {
    extern __shared__ char smem[];
    const int x0 = blockIdx.x * 128;
    const int y  = blockIdx.y;
    const int b  = blockIdx.z;
    const int tid = threadIdx.x;
    const int warp = tid >> 5, lane = tid & 31;
    const int wm = warp & 3, wn = warp >> 2;
    const uint32_t sbase = smem_u32(smem);
    const float* __restrict__ xb = g_xt + (size_t)b*HWW*64;

    __shared__ float s_s[64], s_d[64];
    if (tid < 64) {
        float s = bg[tid] * rsqrtf(bv[tid] + 1e-5f);
        s_s[tid] = s;
        s_d[tid] = (bias[tid] - bm[tid]) * s + bb[tid];
    }

    float acc[2][4][4];
#pragma unroll
    for (int mt = 0; mt < 2; mt++)
#pragma unroll
        for (int nt = 0; nt < 4; nt++)
#pragma unroll
            for (int j = 0; j < 4; j++) acc[mt][nt][j] = 0.f;

    int* s_idx = (int*)(smem + DCN_GI);
    float* s_gw = (float*)(smem + DCN_GW);

    for (int tap = 0; tap < 9; tap++) {
        __syncthreads();
        // geometry for this tap: 2 threads per px (each handles 2 corners)
        {
            int px = tid >> 1, half = tid & 1;
            int xx = x0 + px;
            float o1 = g_om[((b*27 +      tap)*HH + y)*WW + xx];
            float o2 = g_om[((b*27 +  9 + tap)*HH + y)*WW + xx];
            float ml = g_om[((b*27 + 18 + tap)*HH + y)*WW + xx];
            float m  = 1.f / (1.f + expf(-ml));
            float py  = (float)(y  + (tap/3) - 1) + o1;
            float pxf = (float)(xx + (tap%3) - 1) + o2;
            float fy = floorf(py), fx = floorf(pxf);
            float wy1 = py - fy, wx1 = pxf - fx;
            int iy0 = (int)fy, ix0 = (int)fx;
#pragma unroll
            for (int jj = 0; jj < 2; jj++) {
                int j = half*2 + jj;
                int dy = j >> 1, dx = j & 1;
                int yi = iy0 + dy, xi = ix0 + dx;
                bool valid = ((unsigned)yi < HH) && ((unsigned)xi < WW);
                float wgt = (dy ? wy1 : 1.f - wy1) * (dx ? wx1 : 1.f - wx1);
                s_gw[px*4 + j]  = valid ? m * wgt : 0.f;
                int yc = min(max(yi, 0), HH-1);
                int xc = min(max(xi, 0), WW-1);
                s_idx[px*4 + j] = yc*WW + xc;
            }
        }
        // B tiles for this tap
        {
            const uint4* sh = (const uint4*)(wHi + tap*4096);
            const uint4* sl = (const uint4*)(wLo + tap*4096);
            uint4* dh = (uint4*)(smem + 32768);
            uint4* dl = (uint4*)(smem + 40960);
            for (int i = tid; i < 512; i += 256) { dh[i] = sh[i]; dl[i] = sl[i]; }
        }
        __syncthreads();
        // A tile: coalesced NHWC bilinear gather (cp = lane, px warp-uniform)
        for (int i = tid; i < 4096; i += 256) {
            int cp = i & 31, px = i >> 5;
            const int*   ip = s_idx + px*4;
            const float* gp = s_gw + px*4;
            float g0 = gp[0], g1 = gp[1], g2 = gp[2], g3 = gp[3];
            const float2* p0 = (const float2*)(xb + (size_t)ip[0]*64 + 2*cp);
            const float2* p1 = (const float2*)(xb + (size_t)ip[1]*64 + 2*cp);
            const float2* p2 = (const float2*)(xb + (size_t)ip[2]*64 + 2*cp);
            const float2* p3 = (const float2*)(xb + (size_t)ip[3]*64 + 2*cp);
            float2 u0 = *p0, u1 = *p1, u2 = *p2, u3 = *p3;
            float v0 = g0*u0.x + g1*u1.x + g2*u2.x + g3*u3.x;
            float v1 = g0*u0.y + g1*u1.y + g2*u2.y + g3*u3.y;
            uint32_t lw;
            uint32_t hw = pack_split2(v0, v1, lw);
            uint32_t off = (uint32_t)px*128u
                         + ((((uint32_t)(cp>>2)) ^ ((uint32_t)px & 7u)) << 4)
                         + ((uint32_t)cp & 3u)*4u;
            *(uint32_t*)(smem + off)         = hw;
            *(uint32_t*)(smem + 16384 + off) = lw;
        }
        __syncthreads();

#pragma unroll
        for (int ch = 0; ch < 4; ch++) {
            uint32_t ahi[2][4], alo[2][4], bhi[2][4], blo[2][4];
#pragma unroll
            for (int mt = 0; mt < 2; mt++) {
                int pxr = wm*32 + mt*16 + (lane & 15);
                uint32_t u = (uint32_t)(ch*2 + (lane >> 4));
                uint32_t addr = sbase + (uint32_t)pxr*128u
                              + ((u ^ ((uint32_t)pxr & 7u)) << 4);
                ldm4(ahi[mt], addr);
                ldm4(alo[mt], addr + 16384u);
            }
#pragma unroll
            for (int half = 0; half < 2; half++) {
                int ocr = wn*32 + half*16 + (lane & 7) + ((lane >> 4) << 3);
                uint32_t u = (uint32_t)(ch*2 + ((lane >> 3) & 1));
                uint32_t addr = sbase + 32768u + (uint32_t)ocr*128u
                              + ((u ^ ((uint32_t)ocr & 7u)) << 4);
                ldm4(bhi[half], addr);
                ldm4(blo[half], addr + 8192u);
            }
#pragma unroll
            for (int mt = 0; mt < 2; mt++)
#pragma unroll
                for (int nt = 0; nt < 4; nt++) {
                    const uint32_t* bh = &bhi[nt >> 1][(nt & 1)*2];
                    const uint32_t* bl = &blo[nt >> 1][(nt & 1)*2];
                    mma_bf16(acc[mt][nt], ahi[mt], bh);
                    mma_bf16(acc[mt][nt], ahi[mt], bl);
                    mma_bf16(acc[mt][nt], alo[mt], bh);
                }
        }
    }

    // epilogue: bn1 + relu -> packed bf16 hi/lo planes
    __syncthreads();
#pragma unroll
    for (int mt = 0; mt < 2; mt++)
#pragma unroll
        for (int nt = 0; nt < 4; nt++) {
            int pxr = wm*32 + mt*16 + (lane >> 2);
            int occ = wn*32 + nt*8 + ((lane & 3) << 1);
            float s0 = s_s[occ],   d0 = s_d[occ];
            float s1 = s_s[occ+1], d1 = s_d[occ+1];
            size_t base = ((size_t)(b*32 + (occ >> 1)))*HWW + y*WW + x0;
            float v0 = fmaf(acc[mt][nt][0], s0, d0); v0 = v0 > 0.f ? v0 : 0.f;
            float v1 = fmaf(acc[mt][nt][1], s1, d1); v1 = v1 > 0.f ? v1 : 0.f;
            float v2 = fmaf(acc[mt][nt][2], s0, d0); v2 = v2 > 0.f ? v2 : 0.f;
            float v3 = fmaf(acc[mt][nt][3], s1, d1); v3 = v3 > 0.f ? v3 : 0.f;
            uint32_t lw0, lw1;
            uint32_t hw0 = pack_split2(v0, v1, lw0);
            uint32_t hw1 = pack_split2(v2, v3, lw1);
            g_h1h[base + pxr]     = hw0;
            g_h1l[base + pxr]     = lw0;
            g_h1h[base + pxr + 8] = hw1;
            g_h1l[base + pxr + 8] = lw1;
        }
}

// ===========================================================================
// conv64 (dil=2) + bn + relu via mma; packed bf16 hi/lo in AND out.
// smem: A_hi@0 16K, A_lo@16K, B_hi@32K 8K, B_lo@40K 8K  (49152 total)
// ===========================================================================
#define C64_SMEM 49152
__global__ void __launch_bounds__(256)
conv64_tc_kernel(const uint32_t* __restrict__ inH, const uint32_t* __restrict__ inL,
                 const unsigned short* __restrict__ wHi,
                 const unsigned short* __restrict__ wLo,
                 const float* __restrict__ bias,
                 const float* __restrict__ bg, const float* __restrict__ bb,
                 const float* __restrict__ bm, const float* __restrict__ bv,
                 uint32_t* __restrict__ outH, uint32_t* __restrict__ outL) {
    extern __shared__ char smem[];
    const int x0 = blockIdx.x * 128;
    const int y  = blockIdx.y;
    const int b  = blockIdx.z;
    const int tid = threadIdx.x;
    const int warp = tid >> 5, lane = tid & 31;
    const int wm = warp & 3, wn = warp >> 2;
    const uint32_t sbase = smem_u32(smem);

    __shared__ float s_s[64], s_d[64];
    if (tid < 64) {
        float s = bg[tid] * rsqrtf(bv[tid] + 1e-5f);
        s_s[tid] = s;
        s_d[tid] = (bias[tid] - bm[tid]) * s + bb[tid];
    }

    float acc[2][4][4];
#pragma unroll
    for (int mt = 0; mt < 2; mt++)
#pragma unroll
        for (int nt = 0; nt < 4; nt++)
#pragma unroll
            for (int j = 0; j < 4; j++) acc[mt][nt][j] = 0.f;

    for (int tap = 0; tap < 9; tap++) {
        __syncthreads();
        const int dy = tap / 3, kx = tap - dy*3;
        const int rowy = y + 2*dy - 2;
        const bool rowok = (unsigned)rowy < HH;
        for (int i = tid; i < 4096; i += 256) {
            int px = i & 127, cp = i >> 7;
            int xin = x0 + px + 2*kx - 2;
            uint32_t h = 0, l = 0;
            if (rowok && (unsigned)xin < WW) {
                size_t idx = ((size_t)(b*32 + cp))*HWW + rowy*WW + xin;
                h = inH[idx];
                l = inL[idx];
            }
            uint32_t off = (uint32_t)px*128u
                         + ((((uint32_t)(cp>>2)) ^ ((uint32_t)px & 7u)) << 4)
                         + ((uint32_t)cp & 3u)*4u;
            *(uint32_t*)(smem + off)         = h;
            *(uint32_t*)(smem + 16384 + off) = l;
        }
        {
            const uint4* sh = (const uint4*)(wHi + tap*4096);
            const uint4* sl = (const uint4*)(wLo + tap*4096);
            uint4* dh = (uint4*)(smem + 32768);
            uint4* dl = (uint4*)(smem + 40960);
            for (int i = tid; i < 512; i += 256) { dh[i] = sh[i]; dl[i] = sl[i]; }
        }
        __syncthreads();

#pragma unroll
        for (int ch = 0; ch < 4; ch++) {
            uint32_t ahi[2][4], alo[2][4], bhi[2][4], blo[2][4];
#pragma unroll
            for (int mt = 0; mt < 2; mt++) {
                int pxr = wm*32 + mt*16 + (lane & 15);
                uint32_t u = (uint32_t)(ch*2 + (lane >> 4));
                uint32_t addr = sbase + (uint32_t)pxr*128u
                              + ((u ^ ((uint32_t)pxr & 7u)) << 4);
                ldm4(ahi[mt], addr);
                ldm4(alo[mt], addr + 16384u);
            }
#pragma unroll
            for (int half = 0; half < 2; half++) {
                int ocr = wn*32 + half*16 + (lane & 7) + ((lane >> 4) << 3);
                uint32_t u = (uint32_t)(ch*2 + ((lane >> 3) & 1));
                uint32_t addr = sbase + 32768u + (uint32_t)ocr*128u
                              + ((u ^ ((uint32_t)ocr & 7u)) << 4);
                ldm4(bhi[half], addr);
                ldm4(blo[half], addr + 8192u);
            }
#pragma unroll
            for (int mt = 0; mt < 2; mt++)
#pragma unroll
                for (int nt = 0; nt < 4; nt++) {
                    const uint32_t* bh = &bhi[nt >> 1][(nt & 1)*2];
                    const uint32_t* bl = &blo[nt >> 1][(nt & 1)*2];
                    mma_bf16(acc[mt][nt], ahi[mt], bh);
                    mma_bf16(acc[mt][nt], ahi[mt], bl);
                    mma_bf16(acc[mt][nt], alo[mt], bh);
                }
        }
    }

    // epilogue: bn + relu -> packed bf16 hi/lo planes
    __syncthreads();
#pragma unroll
    for (int mt = 0; mt < 2; mt++)
#pragma unroll
        for (int nt = 0; nt < 4; nt++) {
            int pxr = wm*32 + mt*16 + (lane >> 2);
            int occ = wn*32 + nt*8 + ((lane & 3) << 1);
            float s0 = s_s[occ],   d0 = s_d[occ];
            float s1 = s_s[occ+1], d1 = s_d[occ+1];
            size_t base = ((size_t)(b*32 + (occ >> 1)))*HWW + y*WW + x0;
            float v0 = fmaf(acc[mt][nt][0], s0, d0); v0 = v0 > 0.f ? v0 : 0.f;
            float v1 = fmaf(acc[mt][nt][1], s1, d1); v1 = v1 > 0.f ? v1 : 0.f;
            float v2 = fmaf(acc[mt][nt][2], s0, d0); v2 = v2 > 0.f ? v2 : 0.f;
            float v3 = fmaf(acc[mt][nt][3], s1, d1); v3 = v3 > 0.f ? v3 : 0.f;
            uint32_t lw0, lw1;
            uint32_t hw0 = pack_split2(v0, v1, lw0);
            uint32_t hw1 = pack_split2(v2, v3, lw1);
            outH[base + pxr]     = hw0;
            outL[base + pxr]     = lw0;
            outH[base + pxr + 8] = hw1;
            outL[base + pxr + 8] = lw1;
        }
}

// ---------------------------------------------------------------------------
// Final 64->1 3x3 conv pad1 + sigmoid + clip; direct coalesced LDG, no smem
// staging, no per-channel barriers.
// ---------------------------------------------------------------------------
__global__ void __launch_bounds__(256)
final_kernel(const float* __restrict__ w3, const float* __restrict__ b3,
             float* __restrict__ out) {
    const int y = blockIdx.x;
    const int b = blockIdx.y;
    const int tid = threadIdx.x;  // 256 = W (x coordinate)

    __shared__ float s_w3[576];
    for (int i = tid; i < 576; i += 256) s_w3[i] = w3[i];
    __syncthreads();

    float acc = 0.f;
#pragma unroll 2
    for (int cp = 0; cp < 32; cp++) {
        const uint32_t* hp = g_h3h + ((size_t)(b*32 + cp))*HWW;
        const uint32_t* lp = g_h3l + ((size_t)(b*32 + cp))*HWW;
        const float* w0 = s_w3 + (2*cp)*9;
        const float* w1 = w0 + 9;
#pragma unroll
        for (int ky = 0; ky < 3; ky++) {
            int yy = y + ky - 1;
            if ((unsigned)yy >= HH) continue;
#pragma unroll
            for (int kx = 0; kx < 3; kx++) {
                int xx = tid + kx - 1;
                if ((unsigned)xx >= WW) continue;
                uint32_t h = hp[yy*WW + xx];
                uint32_t l = lp[yy*WW + xx];
                float v0 = __uint_as_float(h << 16) + __uint_as_float(l << 16);
                float v1 = __uint_as_float(h & 0xFFFF0000u)
                         + __uint_as_float(l & 0xFFFF0000u);
                acc = fmaf(w0[ky*3+kx], v0, acc);
                acc = fmaf(w1[ky*3+kx], v1, acc);
            }
        }
    }
    float v = acc + b3[0];
    float sg = 1.f / (1.f + expf(-v));
    sg = fminf(fmaxf(sg, 1e-4f), 1.f - 1e-4f);
    out[((size_t)b*HH + y)*WW + tid] = sg;
}

// ---------------------------------------------------------------------------
extern "C" void kernel_launch(void* const* d_in, const int* in_sizes, int n_in,
                              void* d_out, int out_size) {
    (void)n_in; (void)out_size;
    const float* x     = (const float*)d_in[0];
    const float* w_om  = (const float*)d_in[1];
    const float* b_om  = (const float*)d_in[2];
    const float* w_dcn = (const float*)d_in[3];
    const float* b_dcn = (const float*)d_in[4];
    const float* bn1g  = (const float*)d_in[5];
    const float* bn1b  = (const float*)d_in[6];
    const float* bn1m  = (const float*)d_in[7];
    const float* bn1v  = (const float*)d_in[8];

    const float *w_h, *b_h, *w_w, *b_w, *w3, *b3;
    const float *bn2g, *bn2b, *bn2m, *bn2v, *bn3g, *bn3b, *bn3m, *bn3v;
    if (in_sizes[9] == CC) {
        // dict order
        bn2g = (const float*)d_in[9];  bn2b = (const float*)d_in[10];
        bn2m = (const float*)d_in[11]; bn2v = (const float*)d_in[12];
        bn3g = (const float*)d_in[13]; bn3b = (const float*)d_in[14];
        bn3m = (const float*)d_in[15]; bn3v = (const float*)d_in[16];
        w_h  = (const float*)d_in[17]; b_h  = (const float*)d_in[18];
        w_w  = (const float*)d_in[19]; b_w  = (const float*)d_in[20];
        w3   = (const float*)d_in[21]; b3   = (const float*)d_in[22];
    } else {
        // signature order
        w_h  = (const float*)d_in[9];  b_h  = (const float*)d_in[10];
        bn2g = (const float*)d_in[11]; bn2b = (const float*)d_in[12];
        bn2m = (const float*)d_in[13]; bn2v = (const float*)d_in[14];
        w_w  = (const float*)d_in[15]; b_w  = (const float*)d_in[16];
        bn3g = (const float*)d_in[17]; bn3b = (const float*)d_in[18];
        bn3m = (const float*)d_in[19]; bn3v = (const float*)d_in[20];
        w3   = (const float*)d_in[21]; b3   = (const float*)d_in[22];
    }
    float* out = (float*)d_out;

    uint32_t *p_xh, *p_xl, *p_h1h, *p_h1l, *p_h2h, *p_h2l, *p_h3h, *p_h3l;
    unsigned short *p_wBom_hi, *p_wBom_lo, *p_wBd_hi, *p_wBd_lo;
    unsigned short *p_wBh_hi, *p_wBh_lo, *p_wBw_hi, *p_wBw_lo;
    cudaGetSymbolAddress((void**)&p_xh,  g_xh);
    cudaGetSymbolAddress((void**)&p_xl,  g_xl);
    cudaGetSymbolAddress((void**)&p_h1h, g_h1h);
    cudaGetSymbolAddress((void**)&p_h1l, g_h1l);
    cudaGetSymbolAddress((void**)&p_h2h, g_h2h);
    cudaGetSymbolAddress((void**)&p_h2l, g_h2l);
    cudaGetSymbolAddress((void**)&p_h3h, g_h3h);
    cudaGetSymbolAddress((void**)&p_h3l, g_h3l);
    cudaGetSymbolAddress((void**)&p_wBom_hi, g_wBom_hi);
    cudaGetSymbolAddress((void**)&p_wBom_lo, g_wBom_lo);
    cudaGetSymbolAddress((void**)&p_wBd_hi, g_wBd_hi);
    cudaGetSymbolAddress((void**)&p_wBd_lo, g_wBd_lo);
    cudaGetSymbolAddress((void**)&p_wBh_hi, g_wBh_hi);
    cudaGetSymbolAddress((void**)&p_wBh_lo, g_wBh_lo);
    cudaGetSymbolAddress((void**)&p_wBw_hi, g_wBw_hi);
    cudaGetSymbolAddress((void**)&p_wBw_lo, g_wBw_lo);

    cudaFuncSetAttribute(om_tc_kernel,
                         cudaFuncAttributeMaxDynamicSharedMemorySize, OM_SMEM);
    cudaFuncSetAttribute(dcn_tc_kernel,
                         cudaFuncAttributeMaxDynamicSharedMemorySize, DCN_SMEM);
    cudaFuncSetAttribute(conv64_tc_kernel,
                         cudaFuncAttributeMaxDynamicSharedMemorySize, C64_SMEM);

    prep_weights_kernel<<<72, 256>>>(w_om, w_dcn, w_h, w_w);
    prep_x_kernel<<<dim3(HWW/64, BB), 256>>>(x);

    dim3 gridc(WW/128, HH, BB);
    om_tc_kernel<<<gridc, 256, OM_SMEM>>>(p_xh, p_xl, p_wBom_hi, p_wBom_lo, b_om);
    dcn_tc_kernel<<<gridc, 256, DCN_SMEM>>>(p_wBd_hi, p_wBd_lo, b_dcn,
                                            bn1g, bn1b, bn1m, bn1v);
    conv64_tc_kernel<<<gridc, 256, C64_SMEM>>>(p_h1h, p_h1l, p_wBh_hi, p_wBh_lo,
                                               b_h, bn2g, bn2b, bn2m, bn2v,
                                               p_h2h, p_h2l);
    conv64_tc_kernel<<<gridc, 256, C64_SMEM>>>(p_h2h, p_h2l, p_wBw_hi, p_wBw_lo,
                                               b_w, bn3g, bn3b, bn3m, bn3v,
                                               p_h3h, p_h3l);
    final_kernel<<<dim3(HH, BB), 256>>>(w3, b3, out);
}

// round 12
// speedup vs baseline: 2.9008x; 1.1416x over previous
#include <cuda_runtime.h>
#include <math.h>
#include <stdint.h>

#define BB 2
#define CC 64
#define HH 256
#define WW 256
#define HWW (HH*WW)

// ---- scratch (device globals; no runtime allocation allowed) ----
__device__ float g_om[BB*27*HWW];                         // offset/mask conv out (fp32)
__device__ float g_xt[BB*HWW*64];                         // x transposed NHWC fp32
__device__ uint32_t g_xh[BB*32*HWW], g_xl[BB*32*HWW];     // x packed bf16 hi/lo c-pairs
__device__ uint32_t g_h1h[BB*32*HWW], g_h1l[BB*32*HWW];   // h1 packed
__device__ uint32_t g_h2h[BB*32*HWW], g_h2l[BB*32*HWW];   // h2 packed
__device__ uint32_t g_h3h[BB*32*HWW], g_h3l[BB*32*HWW];   // h3 packed
// bf16 hi/lo split, swizzled [tap][oc][c] B tiles
__device__ __align__(16) unsigned short g_wBom_hi[9*32*64], g_wBom_lo[9*32*64];
__device__ __align__(16) unsigned short g_wBd_hi[9*64*64],  g_wBd_lo[9*64*64];
__device__ __align__(16) unsigned short g_wBh_hi[9*64*64],  g_wBh_lo[9*64*64];
__device__ __align__(16) unsigned short g_wBw_hi[9*64*64],  g_wBw_lo[9*64*64];

// ---- bf16 round-to-nearest-even split helpers ----
__device__ __forceinline__ uint32_t bf16_rne(float v) {
    uint32_t x = __float_as_uint(v);
    return (x + 0x7FFFu + ((x >> 16) & 1u)) >> 16;
}
__device__ __forceinline__ void bf16_split(float v, uint32_t& hb, uint32_t& lb) {
    hb = bf16_rne(v);
    float hf = __uint_as_float(hb << 16);
    lb = bf16_rne(v - hf);
}
__device__ __forceinline__ uint32_t pack_split2(float v0, float v1, uint32_t& lw) {
    uint32_t h0, l0, h1, l1;
    bf16_split(v0, h0, l0);
    bf16_split(v1, h1, l1);
    lw = l0 | (l1 << 16);
    return h0 | (h1 << 16);
}

// ---- warp-level tensor ops (sm_80-lineage; valid on plain sm_103 target) ----
__device__ __forceinline__ void ldm4(uint32_t* r, uint32_t addr) {
    asm volatile("ldmatrix.sync.aligned.m8n8.x4.shared.b16 {%0,%1,%2,%3}, [%4];"
                 : "=r"(r[0]), "=r"(r[1]), "=r"(r[2]), "=r"(r[3]) : "r"(addr));
}
__device__ __forceinline__ void mma_bf16(float* d, const uint32_t* a,
                                         const uint32_t* b) {
    asm volatile(
        "mma.sync.aligned.m16n8k16.row.col.f32.bf16.bf16.f32 "
        "{%0,%1,%2,%3}, {%4,%5,%6,%7}, {%8,%9}, {%0,%1,%2,%3};"
        : "+f"(d[0]), "+f"(d[1]), "+f"(d[2]), "+f"(d[3])
        : "r"(a[0]), "r"(a[1]), "r"(a[2]), "r"(a[3]), "r"(b[0]), "r"(b[1]));
}
__device__ __forceinline__ uint32_t smem_u32(const void* p) {
    uint32_t a;
    asm("{ .reg .u64 t; cvta.to.shared.u64 t, %1; cvt.u32.u64 %0, t; }"
        : "=r"(a) : "l"(p));
    return a;
}

// ===========================================================================
// Weight prep
// ===========================================================================
__global__ void prep_weights_kernel(const float* __restrict__ w_om,
                                    const float* __restrict__ w_dcn,
                                    const float* __restrict__ w_h,
                                    const float* __restrict__ w_w) {
    const int i0 = blockIdx.x * blockDim.x + threadIdx.x;
    const int stride = gridDim.x * blockDim.x;
    for (int i = i0; i < 32*CC*9; i += stride) {
        int oc = i / 576; int r = i - oc*576; int c = r / 9, tap = r - c*9;
        float v = (oc < 27) ? w_om[(oc*CC + c)*9 + tap] : 0.f;
        int dst = tap*2048 + oc*64 + (((c>>3) ^ (oc&7)) << 3) + (c & 7);
        uint32_t hb, lb;
        bf16_split(v, hb, lb);
        g_wBom_hi[dst] = (unsigned short)hb;
        g_wBom_lo[dst] = (unsigned short)lb;
    }
    for (int i = i0; i < CC*CC*9; i += stride) {
        int oc = i / 576; int r = i - oc*576; int c = r / 9, tap = r - c*9;
        int dst = tap*4096 + oc*64 + (((c>>3) ^ (oc&7)) << 3) + (c & 7);
        uint32_t hb, lb;
        bf16_split(w_dcn[i], hb, lb);
        g_wBd_hi[dst] = (unsigned short)hb;
        g_wBd_lo[dst] = (unsigned short)lb;
        bf16_split(w_h[i], hb, lb);
        g_wBh_hi[dst] = (unsigned short)hb;
        g_wBh_lo[dst] = (unsigned short)lb;
        bf16_split(w_w[i], hb, lb);
        g_wBw_hi[dst] = (unsigned short)hb;
        g_wBw_lo[dst] = (unsigned short)lb;
    }
}

// ===========================================================================
// x prep: tiled transpose -> x_t NHWC fp32, plus packed bf16 hi/lo planes.
// ===========================================================================
__global__ void __launch_bounds__(256)
prep_x_kernel(const float* __restrict__ x) {
    __shared__ float s[64*65];
    const int px0 = blockIdx.x * 64;
    const int b   = blockIdx.y;
    const int tid = threadIdx.x;
    for (int i = tid; i < 4096; i += 256) {
        int c = i >> 6, p = i & 63;
        s[p*65 + c] = x[((size_t)(b*CC + c))*HWW + px0 + p];
    }
    __syncthreads();
    for (int i = tid; i < 4096; i += 256) {
        int p = i >> 6, c = i & 63;
        g_xt[((size_t)b*HWW + px0 + p)*64 + c] = s[p*65 + c];
    }
    for (int i = tid; i < 2048; i += 256) {
        int cp = i >> 6, p = i & 63;
        uint32_t lw;
        uint32_t hw = pack_split2(s[p*65 + 2*cp], s[p*65 + 2*cp + 1], lw);
        size_t o = ((size_t)(b*32 + cp))*HWW + px0 + p;
        g_xh[o] = hw;
        g_xl[o] = lw;
    }
}

// ===========================================================================
// om conv via mma (dil=1), halo-shared A across kx taps.
// A: 130 rows (px -1..128) x 64c hi/lo; 3 dy phases x 3 kx taps.
// smem: A_hi@0 17408, A_lo@17408, B_hi@34816 12288 (3 taps), B_lo@47104 12288
// total 59392
// ===========================================================================
#define OM_SMEM 59392
__global__ void __launch_bounds__(256)
om_tc_kernel(const uint32_t* __restrict__ inH, const uint32_t* __restrict__ inL,
             const unsigned short* __restrict__ wHi,
             const unsigned short* __restrict__ wLo,
             const float* __restrict__ b_om) {
    extern __shared__ char smem[];
    const int x0 = blockIdx.x * 128;
    const int y  = blockIdx.y;
    const int b  = blockIdx.z;
    const int tid = threadIdx.x;
    const int warp = tid >> 5, lane = tid & 31;
    const int wm = warp & 3, wn = warp >> 2;
    const uint32_t sbase = smem_u32(smem);

    float acc[2][2][4];
#pragma unroll
    for (int mt = 0; mt < 2; mt++)
#pragma unroll
        for (int nt = 0; nt < 2; nt++)
#pragma unroll
            for (int j = 0; j < 4; j++) acc[mt][nt][j] = 0.f;

    for (int dyi = 0; dyi < 3; dyi++) {
        __syncthreads();
        const int rowy = y + dyi - 1;
        const bool rowok = (unsigned)rowy < HH;
        // A tile: 130 rows x 32 cps (row r -> global x = x0 - 1 + r)
        for (int i = tid; i < 4160; i += 256) {
            int cp = i / 130, r = i - cp*130;
            int xin = x0 + r - 1;
            uint32_t h = 0, l = 0;
            if (rowok && (unsigned)xin < WW) {
                size_t idx = ((size_t)(b*32 + cp))*HWW + rowy*WW + xin;
                h = inH[idx];
                l = inL[idx];
            }
            uint32_t off = (uint32_t)r*128u
                         + ((((uint32_t)(cp>>2)) ^ ((uint32_t)r & 7u)) << 4)
                         + ((uint32_t)cp & 3u)*4u;
            *(uint32_t*)(smem + off)         = h;
            *(uint32_t*)(smem + 17408 + off) = l;
        }
        // B tiles: 3 contiguous kx taps for this dy
        {
            const uint4* sh = (const uint4*)(wHi + dyi*3*2048);
            const uint4* sl = (const uint4*)(wLo + dyi*3*2048);
            uint4* dh = (uint4*)(smem + 34816);
            uint4* dl = (uint4*)(smem + 47104);
            for (int i = tid; i < 768; i += 256) { dh[i] = sh[i]; dl[i] = sl[i]; }
        }
        __syncthreads();

#pragma unroll
        for (int kx = 0; kx < 3; kx++) {
#pragma unroll
            for (int ch = 0; ch < 4; ch++) {
                uint32_t ahi[2][4], alo[2][4], bhi[4], blo[4];
#pragma unroll
                for (int mt = 0; mt < 2; mt++) {
                    int r = wm*32 + mt*16 + (lane & 15) + kx;
                    uint32_t u = (uint32_t)(ch*2 + (lane >> 4));
                    uint32_t addr = sbase + (uint32_t)r*128u
                                  + ((u ^ ((uint32_t)r & 7u)) << 4);
                    ldm4(ahi[mt], addr);
                    ldm4(alo[mt], addr + 17408u);
                }
                {
                    int ocr = wn*16 + (lane & 7) + ((lane >> 4) << 3);
                    uint32_t u = (uint32_t)(ch*2 + ((lane >> 3) & 1));
                    uint32_t addr = sbase + 34816u + (uint32_t)kx*4096u
                                  + (uint32_t)ocr*128u
                                  + ((u ^ ((uint32_t)ocr & 7u)) << 4);
                    ldm4(bhi, addr);
                    ldm4(blo, addr + 12288u);
                }
#pragma unroll
                for (int mt = 0; mt < 2; mt++)
#pragma unroll
                    for (int nt = 0; nt < 2; nt++) {
                        mma_bf16(acc[mt][nt], ahi[mt], &bhi[nt*2]);
                        mma_bf16(acc[mt][nt], ahi[mt], &blo[nt*2]);
                        mma_bf16(acc[mt][nt], alo[mt], &bhi[nt*2]);
                    }
            }
        }
    }

#pragma unroll
    for (int mt = 0; mt < 2; mt++)
#pragma unroll
        for (int nt = 0; nt < 2; nt++) {
            int pxr = wm*32 + mt*16 + (lane >> 2);
            int occ = wn*16 + nt*8 + ((lane & 3) << 1);
            if (occ < 27) {
                float bo = b_om[occ];
                float* o0 = g_om + ((size_t)(b*27 + occ))*HWW + y*WW + x0;
                o0[pxr]     = acc[mt][nt][0] + bo;
                o0[pxr + 8] = acc[mt][nt][2] + bo;
            }
            if (occ + 1 < 27) {
                float bo = b_om[occ+1];
                float* o1 = g_om + ((size_t)(b*27 + occ+1))*HWW + y*WW + x0;
                o1[pxr]     = acc[mt][nt][1] + bo;
                o1[pxr + 8] = acc[mt][nt][3] + bo;
            }
        }
}

// ===========================================================================
// DCNv2 + bn1 + relu via mma, NHWC coalesced gather (unchanged from R11).
// ===========================================================================
#define DCN_GI 49152
#define DCN_GW 51200
#define DCN_SMEM 53248
__global__ void __launch_bounds__(256)
dcn_tc_kernel(const unsigned short* __restrict__ wHi,
              const unsigned short* __restrict__ wLo,
              const float* __restrict__ bias,
              const float* __restrict__ bg, const float* __restrict__ bb,
              const float* __restrict__ bm, const float* __restrict__ bv) {
    extern __shared__ char smem[];
    const int x0 = blockIdx.x * 128;
    const int y  = blockIdx.y;
    const int b  = blockIdx.z;
    const int tid = threadIdx.x;
    const int warp = tid >> 5, lane = tid & 31;
    const int wm = warp & 3, wn = warp >> 2;
    const uint32_t sbase = smem_u32(smem);
    const float* __restrict__ xb = g_xt + (size_t)b*HWW*64;

    __shared__ float s_s[64], s_d[64];
    if (tid < 64) {
        float s = bg[tid] * rsqrtf(bv[tid] + 1e-5f);
        s_s[tid] = s;
        s_d[tid] = (bias[tid] - bm[tid]) * s + bb[tid];
    }

    float acc[2][4][4];
#pragma unroll
    for (int mt = 0; mt < 2; mt++)
#pragma unroll
        for (int nt = 0; nt < 4; nt++)
#pragma unroll
            for (int j = 0; j < 4; j++) acc[mt][nt][j] = 0.f;

    int* s_idx = (int*)(smem + DCN_GI);
    float* s_gw = (float*)(smem + DCN_GW);

    for (int tap = 0; tap < 9; tap++) {
        __syncthreads();
        {
            int px = tid >> 1, half = tid & 1;
            int xx = x0 + px;
            float o1 = g_om[((b*27 +      tap)*HH + y)*WW + xx];
            float o2 = g_om[((b*27 +  9 + tap)*HH + y)*WW + xx];
            float ml = g_om[((b*27 + 18 + tap)*HH + y)*WW + xx];
            float m  = 1.f / (1.f + expf(-ml));
            float py  = (float)(y  + (tap/3) - 1) + o1;
            float pxf = (float)(xx + (tap%3) - 1) + o2;
            float fy = floorf(py), fx = floorf(pxf);
            float wy1 = py - fy, wx1 = pxf - fx;
            int iy0 = (int)fy, ix0 = (int)fx;
#pragma unroll
            for (int jj = 0; jj < 2; jj++) {
                int j = half*2 + jj;
                int dy = j >> 1, dx = j & 1;
                int yi = iy0 + dy, xi = ix0 + dx;
                bool valid = ((unsigned)yi < HH) && ((unsigned)xi < WW);
                float wgt = (dy ? wy1 : 1.f - wy1) * (dx ? wx1 : 1.f - wx1);
                s_gw[px*4 + j]  = valid ? m * wgt : 0.f;
                int yc = min(max(yi, 0), HH-1);
                int xc = min(max(xi, 0), WW-1);
                s_idx[px*4 + j] = yc*WW + xc;
            }
        }
        {
            const uint4* sh = (const uint4*)(wHi + tap*4096);
            const uint4* sl = (const uint4*)(wLo + tap*4096);
            uint4* dh = (uint4*)(smem + 32768);
            uint4* dl = (uint4*)(smem + 40960);
            for (int i = tid; i < 512; i += 256) { dh[i] = sh[i]; dl[i] = sl[i]; }
        }
        __syncthreads();
        for (int i = tid; i < 4096; i += 256) {
            int cp = i & 31, px = i >> 5;
            const int*   ip = s_idx + px*4;
            const float* gp = s_gw + px*4;
            float g0 = gp[0], g1 = gp[1], g2 = gp[2], g3 = gp[3];
            const float2* p0 = (const float2*)(xb + (size_t)ip[0]*64 + 2*cp);
            const float2* p1 = (const float2*)(xb + (size_t)ip[1]*64 + 2*cp);
            const float2* p2 = (const float2*)(xb + (size_t)ip[2]*64 + 2*cp);
            const float2* p3 = (const float2*)(xb + (size_t)ip[3]*64 + 2*cp);
            float2 u0 = *p0, u1 = *p1, u2 = *p2, u3 = *p3;
            float v0 = g0*u0.x + g1*u1.x + g2*u2.x + g3*u3.x;
            float v1 = g0*u0.y + g1*u1.y + g2*u2.y + g3*u3.y;
            uint32_t lw;
            uint32_t hw = pack_split2(v0, v1, lw);
            uint32_t off = (uint32_t)px*128u
                         + ((((uint32_t)(cp>>2)) ^ ((uint32_t)px & 7u)) << 4)
                         + ((uint32_t)cp & 3u)*4u;
            *(uint32_t*)(smem + off)         = hw;
            *(uint32_t*)(smem + 16384 + off) = lw;
        }
        __syncthreads();

#pragma unroll
        for (int ch = 0; ch < 4; ch++) {
            uint32_t ahi[2][4], alo[2][4], bhi[2][4], blo[2][4];
#pragma unroll
            for (int mt = 0; mt < 2; mt++) {
                int pxr = wm*32 + mt*16 + (lane & 15);
                uint32_t u = (uint32_t)(ch*2 + (lane >> 4));
                uint32_t addr = sbase + (uint32_t)pxr*128u
                              + ((u ^ ((uint32_t)pxr & 7u)) << 4);
                ldm4(ahi[mt], addr);
                ldm4(alo[mt], addr + 16384u);
            }
#pragma unroll
            for (int half = 0; half < 2; half++) {
                int ocr = wn*32 + half*16 + (lane & 7) + ((lane >> 4) << 3);
                uint32_t u = (uint32_t)(ch*2 + ((lane >> 3) & 1));
                uint32_t addr = sbase + 32768u + (uint32_t)ocr*128u
                              + ((u ^ ((uint32_t)ocr & 7u)) << 4);
                ldm4(bhi[half], addr);
                ldm4(blo[half], addr + 8192u);
            }
#pragma unroll
            for (int mt = 0; mt < 2; mt++)
#pragma unroll
                for (int nt = 0; nt < 4; nt++) {
                    const uint32_t* bh = &bhi[nt >> 1][(nt & 1)*2];
                    const uint32_t* bl = &blo[nt >> 1][(nt & 1)*2];
                    mma_bf16(acc[mt][nt], ahi[mt], bh);
                    mma_bf16(acc[mt][nt], ahi[mt], bl);
                    mma_bf16(acc[mt][nt], alo[mt], bh);
                }
        }
    }

    __syncthreads();
#pragma unroll
    for (int mt = 0; mt < 2; mt++)
#pragma unroll
        for (int nt = 0; nt < 4; nt++) {
            int pxr = wm*32 + mt*16 + (lane >> 2);
            int occ = wn*32 + nt*8 + ((lane & 3) << 1);
            float s0 = s_s[occ],   d0 = s_d[occ];
            float s1 = s_s[occ+1], d1 = s_d[occ+1];
            size_t base = ((size_t)(b*32 + (occ >> 1)))*HWW + y*WW + x0;
            float v0 = fmaf(acc[mt][nt][0], s0, d0); v0 = v0 > 0.f ? v0 : 0.f;
            float v1 = fmaf(acc[mt][nt][1], s1, d1); v1 = v1 > 0.f ? v1 : 0.f;
            float v2 = fmaf(acc[mt][nt][2], s0, d0); v2 = v2 > 0.f ? v2 : 0.f;
            float v3 = fmaf(acc[mt][nt][3], s1, d1); v3 = v3 > 0.f ? v3 : 0.f;
            uint32_t lw0, lw1;
            uint32_t hw0 = pack_split2(v0, v1, lw0);
            uint32_t hw1 = pack_split2(v2, v3, lw1);
            g_h1h[base + pxr]     = hw0;
            g_h1l[base + pxr]     = lw0;
            g_h1h[base + pxr + 8] = hw1;
            g_h1l[base + pxr + 8] = lw1;
        }
}

// ===========================================================================
// conv64 (dil=2) + bn + relu via mma, halo-shared A across kx taps.
// A: 132 rows (px -2..129) x 64c hi/lo; 3 dy phases x 3 kx taps.
// smem: A_hi@0 17408, A_lo@17408, B_hi@34816 24576 (3 taps), B_lo@59392 24576
// total 83968
// ===========================================================================
#define C64_SMEM 83968
__global__ void __launch_bounds__(256)
conv64_tc_kernel(const uint32_t* __restrict__ inH, const uint32_t* __restrict__ inL,
                 const unsigned short* __restrict__ wHi,
                 const unsigned short* __restrict__ wLo,
                 const float* __restrict__ bias,
                 const float* __restrict__ bg, const float* __restrict__ bb,
                 const float* __restrict__ bm, const float* __restrict__ bv,
                 uint32_t* __restrict__ outH, uint32_t* __restrict__ outL) {
    extern __shared__ char smem[];
    const int x0 = blockIdx.x * 128;
    const int y  = blockIdx.y;
    const int b  = blockIdx.z;
    const int tid = threadIdx.x;
    const int warp = tid >> 5, lane = tid & 31;
    const int wm = warp & 3, wn = warp >> 2;
    const uint32_t sbase = smem_u32(smem);

    __shared__ float s_s[64], s_d[64];
    if (tid < 64) {
        float s = bg[tid] * rsqrtf(bv[tid] + 1e-5f);
        s_s[tid] = s;
        s_d[tid] = (bias[tid] - bm[tid]) * s + bb[tid];
    }

    float acc[2][4][4];
#pragma unroll
    for (int mt = 0; mt < 2; mt++)
#pragma unroll
        for (int nt = 0; nt < 4; nt++)
#pragma unroll
            for (int j = 0; j < 4; j++) acc[mt][nt][j] = 0.f;

    for (int dyi = 0; dyi < 3; dyi++) {
        __syncthreads();
        const int rowy = y + 2*dyi - 2;
        const bool rowok = (unsigned)rowy < HH;
        // A tile: 132 rows x 32 cps (row r -> global x = x0 - 2 + r)
        for (int i = tid; i < 4224; i += 256) {
            int cp = i / 132, r = i - cp*132;
            int xin = x0 + r - 2;
            uint32_t h = 0, l = 0;
            if (rowok && (unsigned)xin < WW) {
                size_t idx = ((size_t)(b*32 + cp))*HWW + rowy*WW + xin;
                h = inH[idx];
                l = inL[idx];
            }
            uint32_t off = (uint32_t)r*128u
                         + ((((uint32_t)(cp>>2)) ^ ((uint32_t)r & 7u)) << 4)
                         + ((uint32_t)cp & 3u)*4u;
            *(uint32_t*)(smem + off)         = h;
            *(uint32_t*)(smem + 17408 + off) = l;
        }
        // B tiles: 3 contiguous kx taps for this dy
        {
            const uint4* sh = (const uint4*)(wHi + dyi*3*4096);
            const uint4* sl = (const uint4*)(wLo + dyi*3*4096);
            uint4* dh = (uint4*)(smem + 34816);
            uint4* dl = (uint4*)(smem + 59392);
            for (int i = tid; i < 1536; i += 256) { dh[i] = sh[i]; dl[i] = sl[i]; }
        }
        __syncthreads();

#pragma unroll
        for (int kx = 0; kx < 3; kx++) {
#pragma unroll
            for (int ch = 0; ch < 4; ch++) {
                uint32_t ahi[2][4], alo[2][4], bhi[2][4], blo[2][4];
#pragma unroll
                for (int mt = 0; mt < 2; mt++) {
                    int r = wm*32 + mt*16 + (lane & 15) + 2*kx;
                    uint32_t u = (uint32_t)(ch*2 + (lane >> 4));
                    uint32_t addr = sbase + (uint32_t)r*128u
                                  + ((u ^ ((uint32_t)r & 7u)) << 4);
                    ldm4(ahi[mt], addr);
                    ldm4(alo[mt], addr + 17408u);
                }
#pragma unroll
                for (int half = 0; half < 2; half++) {
                    int ocr = wn*32 + half*16 + (lane & 7) + ((lane >> 4) << 3);
                    uint32_t u = (uint32_t)(ch*2 + ((lane >> 3) & 1));
                    uint32_t addr = sbase + 34816u + (uint32_t)kx*8192u
                                  + (uint32_t)ocr*128u
                                  + ((u ^ ((uint32_t)ocr & 7u)) << 4);
                    ldm4(bhi[half], addr);
                    ldm4(blo[half], addr + 24576u);
                }
#pragma unroll
                for (int mt = 0; mt < 2; mt++)
#pragma unroll
                    for (int nt = 0; nt < 4; nt++) {
                        const uint32_t* bh = &bhi[nt >> 1][(nt & 1)*2];
                        const uint32_t* bl = &blo[nt >> 1][(nt & 1)*2];
                        mma_bf16(acc[mt][nt], ahi[mt], bh);
                        mma_bf16(acc[mt][nt], ahi[mt], bl);
                        mma_bf16(acc[mt][nt], alo[mt], bh);
                    }
            }
        }
    }

    // epilogue: bn + relu -> packed bf16 hi/lo planes
    __syncthreads();
#pragma unroll
    for (int mt = 0; mt < 2; mt++)
#pragma unroll
        for (int nt = 0; nt < 4; nt++) {
            int pxr = wm*32 + mt*16 + (lane >> 2);
            int occ = wn*32 + nt*8 + ((lane & 3) << 1);
            float s0 = s_s[occ],   d0 = s_d[occ];
            float s1 = s_s[occ+1], d1 = s_d[occ+1];
            size_t base = ((size_t)(b*32 + (occ >> 1)))*HWW + y*WW + x0;
            float v0 = fmaf(acc[mt][nt][0], s0, d0); v0 = v0 > 0.f ? v0 : 0.f;
            float v1 = fmaf(acc[mt][nt][1], s1, d1); v1 = v1 > 0.f ? v1 : 0.f;
            float v2 = fmaf(acc[mt][nt][2], s0, d0); v2 = v2 > 0.f ? v2 : 0.f;
            float v3 = fmaf(acc[mt][nt][3], s1, d1); v3 = v3 > 0.f ? v3 : 0.f;
            uint32_t lw0, lw1;
            uint32_t hw0 = pack_split2(v0, v1, lw0);
            uint32_t hw1 = pack_split2(v2, v3, lw1);
            outH[base + pxr]     = hw0;
            outL[base + pxr]     = lw0;
            outH[base + pxr + 8] = hw1;
            outL[base + pxr + 8] = lw1;
        }
}

// ---------------------------------------------------------------------------
// Final 64->1 3x3 conv pad1 + sigmoid + clip; direct coalesced LDG.
// ---------------------------------------------------------------------------
__global__ void __launch_bounds__(256)
final_kernel(const float* __restrict__ w3, const float* __restrict__ b3,
             float* __restrict__ out) {
    const int y = blockIdx.x;
    const int b = blockIdx.y;
    const int tid = threadIdx.x;  // 256 = W (x coordinate)

    __shared__ float s_w3[576];
    for (int i = tid; i < 576; i += 256) s_w3[i] = w3[i];
    __syncthreads();

    float acc = 0.f;
#pragma unroll 2
    for (int cp = 0; cp < 32; cp++) {
        const uint32_t* hp = g_h3h + ((size_t)(b*32 + cp))*HWW;
        const uint32_t* lp = g_h3l + ((size_t)(b*32 + cp))*HWW;
        const float* w0 = s_w3 + (2*cp)*9;
        const float* w1 = w0 + 9;
#pragma unroll
        for (int ky = 0; ky < 3; ky++) {
            int yy = y + ky - 1;
            if ((unsigned)yy >= HH) continue;
#pragma unroll
            for (int kx = 0; kx < 3; kx++) {
                int xx = tid + kx - 1;
                if ((unsigned)xx >= WW) continue;
                uint32_t h = hp[yy*WW + xx];
                uint32_t l = lp[yy*WW + xx];
                float v0 = __uint_as_float(h << 16) + __uint_as_float(l << 16);
                float v1 = __uint_as_float(h & 0xFFFF0000u)
                         + __uint_as_float(l & 0xFFFF0000u);
                acc = fmaf(w0[ky*3+kx], v0, acc);
                acc = fmaf(w1[ky*3+kx], v1, acc);
            }
        }
    }
    float v = acc + b3[0];
    float sg = 1.f / (1.f + expf(-v));
    sg = fminf(fmaxf(sg, 1e-4f), 1.f - 1e-4f);
    out[((size_t)b*HH + y)*WW + tid] = sg;
}

// ---------------------------------------------------------------------------
extern "C" void kernel_launch(void* const* d_in, const int* in_sizes, int n_in,
                              void* d_out, int out_size) {
    (void)n_in; (void)out_size;
    const float* x     = (const float*)d_in[0];
    const float* w_om  = (const float*)d_in[1];
    const float* b_om  = (const float*)d_in[2];
    const float* w_dcn = (const float*)d_in[3];
    const float* b_dcn = (const float*)d_in[4];
    const float* bn1g  = (const float*)d_in[5];
    const float* bn1b  = (const float*)d_in[6];
    const float* bn1m  = (const float*)d_in[7];
    const float* bn1v  = (const float*)d_in[8];

    const float *w_h, *b_h, *w_w, *b_w, *w3, *b3;
    const float *bn2g, *bn2b, *bn2m, *bn2v, *bn3g, *bn3b, *bn3m, *bn3v;
    if (in_sizes[9] == CC) {
        bn2g = (const float*)d_in[9];  bn2b = (const float*)d_in[10];
        bn2m = (const float*)d_in[11]; bn2v = (const float*)d_in[12];
        bn3g = (const float*)d_in[13]; bn3b = (const float*)d_in[14];
        bn3m = (const float*)d_in[15]; bn3v = (const float*)d_in[16];
        w_h  = (const float*)d_in[17]; b_h  = (const float*)d_in[18];
        w_w  = (const float*)d_in[19]; b_w  = (const float*)d_in[20];
        w3   = (const float*)d_in[21]; b3   = (const float*)d_in[22];
    } else {
        w_h  = (const float*)d_in[9];  b_h  = (const float*)d_in[10];
        bn2g = (const float*)d_in[11]; bn2b = (const float*)d_in[12];
        bn2m = (const float*)d_in[13]; bn2v = (const float*)d_in[14];
        w_w  = (const float*)d_in[15]; b_w  = (const float*)d_in[16];
        bn3g = (const float*)d_in[17]; bn3b = (const float*)d_in[18];
        bn3m = (const float*)d_in[19]; bn3v = (const float*)d_in[20];
        w3   = (const float*)d_in[21]; b3   = (const float*)d_in[22];
    }
    float* out = (float*)d_out;

    uint32_t *p_xh, *p_xl, *p_h1h, *p_h1l, *p_h2h, *p_h2l, *p_h3h, *p_h3l;
    unsigned short *p_wBom_hi, *p_wBom_lo, *p_wBd_hi, *p_wBd_lo;
    unsigned short *p_wBh_hi, *p_wBh_lo, *p_wBw_hi, *p_wBw_lo;
    cudaGetSymbolAddress((void**)&p_xh,  g_xh);
    cudaGetSymbolAddress((void**)&p_xl,  g_xl);
    cudaGetSymbolAddress((void**)&p_h1h, g_h1h);
    cudaGetSymbolAddress((void**)&p_h1l, g_h1l);
    cudaGetSymbolAddress((void**)&p_h2h, g_h2h);
    cudaGetSymbolAddress((void**)&p_h2l, g_h2l);
    cudaGetSymbolAddress((void**)&p_h3h, g_h3h);
    cudaGetSymbolAddress((void**)&p_h3l, g_h3l);
    cudaGetSymbolAddress((void**)&p_wBom_hi, g_wBom_hi);
    cudaGetSymbolAddress((void**)&p_wBom_lo, g_wBom_lo);
    cudaGetSymbolAddress((void**)&p_wBd_hi, g_wBd_hi);
    cudaGetSymbolAddress((void**)&p_wBd_lo, g_wBd_lo);
    cudaGetSymbolAddress((void**)&p_wBh_hi, g_wBh_hi);
    cudaGetSymbolAddress((void**)&p_wBh_lo, g_wBh_lo);
    cudaGetSymbolAddress((void**)&p_wBw_hi, g_wBw_hi);
    cudaGetSymbolAddress((void**)&p_wBw_lo, g_wBw_lo);

    cudaFuncSetAttribute(om_tc_kernel,
                         cudaFuncAttributeMaxDynamicSharedMemorySize, OM_SMEM);
    cudaFuncSetAttribute(dcn_tc_kernel,
                         cudaFuncAttributeMaxDynamicSharedMemorySize, DCN_SMEM);
    cudaFuncSetAttribute(conv64_tc_kernel,
                         cudaFuncAttributeMaxDynamicSharedMemorySize, C64_SMEM);

    prep_weights_kernel<<<72, 256>>>(w_om, w_dcn, w_h, w_w);
    prep_x_kernel<<<dim3(HWW/64, BB), 256>>>(x);

    dim3 gridc(WW/128, HH, BB);
    om_tc_kernel<<<gridc, 256, OM_SMEM>>>(p_xh, p_xl, p_wBom_hi, p_wBom_lo, b_om);
    dcn_tc_kernel<<<gridc, 256, DCN_SMEM>>>(p_wBd_hi, p_wBd_lo, b_dcn,
                                            bn1g, bn1b, bn1m, bn1v);
    conv64_tc_kernel<<<gridc, 256, C64_SMEM>>>(p_h1h, p_h1l, p_wBh_hi, p_wBh_lo,
                                               b_h, bn2g, bn2b, bn2m, bn2v,
                                               p_h2h, p_h2l);
    conv64_tc_kernel<<<gridc, 256, C64_SMEM>>>(p_h2h, p_h2l, p_wBw_hi, p_wBw_lo,
                                               b_w, bn3g, bn3b, bn3m, bn3v,
                                               p_h3h, p_h3l);
    final_kernel<<<dim3(HH, BB), 256>>>(w3, b3, out);
}

// round 15
// speedup vs baseline: 3.3951x; 1.1704x over previous
#include <cuda_runtime.h>
#include <math.h>
#include <stdint.h>

#define BB 2
#define CC 64
#define HH 256
#define WW 256
#define HWW (HH*WW)

// ---- scratch (device globals; no runtime allocation allowed) ----
__device__ float g_om[BB*27*HWW];                        // offset/mask conv out (fp32)
__device__ __align__(16) float g_xt[BB*HWW*64];          // x transposed NHWC fp32
__device__ uint2 g_x2[BB*32*HWW];                        // x packed {hi,lo} c-pairs
__device__ uint2 g_h12[BB*32*HWW];                       // h1 packed {hi,lo}
__device__ uint2 g_h22[BB*32*HWW];                       // h2 packed {hi,lo}
__device__ uint2 g_h32[BB*32*HWW];                       // h3 packed {hi,lo}
// bf16 hi/lo split, swizzled [tap][oc][c] B tiles
__device__ __align__(16) unsigned short g_wBom_hi[9*32*64], g_wBom_lo[9*32*64];
__device__ __align__(16) unsigned short g_wBd_hi[9*64*64],  g_wBd_lo[9*64*64];
__device__ __align__(16) unsigned short g_wBh_hi[9*64*64],  g_wBh_lo[9*64*64];
__device__ __align__(16) unsigned short g_wBw_hi[9*64*64],  g_wBw_lo[9*64*64];

// ---- bf16 split helpers ----
__device__ __forceinline__ uint32_t bf16_rne(float v) {
    uint32_t x = __float_as_uint(v);
    return (x + 0x7FFFu + ((x >> 16) & 1u)) >> 16;
}
__device__ __forceinline__ void bf16_split(float v, uint32_t& hb, uint32_t& lb) {
    hb = bf16_rne(v);
    float hf = __uint_as_float(hb << 16);
    lb = bf16_rne(v - hf);
}
// HW F2FP pack: hw = {bf16(v1) << 16 | bf16(v0)}, lw = lo-residual pair
__device__ __forceinline__ uint32_t pack_split2(float v0, float v1, uint32_t& lw) {
    uint32_t hw;
    asm("cvt.rn.bf16x2.f32 %0, %1, %2;" : "=r"(hw) : "f"(v1), "f"(v0));
    float h0 = __uint_as_float(hw << 16);
    float h1 = __uint_as_float(hw & 0xFFFF0000u);
    float l0 = v0 - h0, l1 = v1 - h1;
    asm("cvt.rn.bf16x2.f32 %0, %1, %2;" : "=r"(lw) : "f"(l1), "f"(l0));
    return hw;
}

// ---- warp-level tensor ops ----
__device__ __forceinline__ void ldm4(uint32_t* r, uint32_t addr) {
    asm volatile("ldmatrix.sync.aligned.m8n8.x4.shared.b16 {%0,%1,%2,%3}, [%4];"
                 : "=r"(r[0]), "=r"(r[1]), "=r"(r[2]), "=r"(r[3]) : "r"(addr));
}
__device__ __forceinline__ void mma_bf16(float* d, const uint32_t* a,
                                         const uint32_t* b) {
    asm volatile(
        "mma.sync.aligned.m16n8k16.row.col.f32.bf16.bf16.f32 "
        "{%0,%1,%2,%3}, {%4,%5,%6,%7}, {%8,%9}, {%0,%1,%2,%3};"
        : "+f"(d[0]), "+f"(d[1]), "+f"(d[2]), "+f"(d[3])
        : "r"(a[0]), "r"(a[1]), "r"(a[2]), "r"(a[3]), "r"(b[0]), "r"(b[1]));
}
__device__ __forceinline__ uint32_t smem_u32(const void* p) {
    uint32_t a;
    asm("{ .reg .u64 t; cvta.to.shared.u64 t, %1; cvt.u32.u64 %0, t; }"
        : "=r"(a) : "l"(p));
    return a;
}

// ===========================================================================
// Weight prep
// ===========================================================================
__global__ void prep_weights_kernel(const float* __restrict__ w_om,
                                    const float* __restrict__ w_dcn,
                                    const float* __restrict__ w_h,
                                    const float* __restrict__ w_w) {
    const int i0 = blockIdx.x * blockDim.x + threadIdx.x;
    const int stride = gridDim.x * blockDim.x;
    for (int i = i0; i < 32*CC*9; i += stride) {
        int oc = i / 576; int r = i - oc*576; int c = r / 9, tap = r - c*9;
        float v = (oc < 27) ? w_om[(oc*CC + c)*9 + tap] : 0.f;
        int dst = tap*2048 + oc*64 + (((c>>3) ^ (oc&7)) << 3) + (c & 7);
        uint32_t hb, lb;
        bf16_split(v, hb, lb);
        g_wBom_hi[dst] = (unsigned short)hb;
        g_wBom_lo[dst] = (unsigned short)lb;
    }
    for (int i = i0; i < CC*CC*9; i += stride) {
        int oc = i / 576; int r = i - oc*576; int c = r / 9, tap = r - c*9;
        int dst = tap*4096 + oc*64 + (((c>>3) ^ (oc&7)) << 3) + (c & 7);
        uint32_t hb, lb;
        bf16_split(w_dcn[i], hb, lb);
        g_wBd_hi[dst] = (unsigned short)hb;
        g_wBd_lo[dst] = (unsigned short)lb;
        bf16_split(w_h[i], hb, lb);
        g_wBh_hi[dst] = (unsigned short)hb;
        g_wBh_lo[dst] = (unsigned short)lb;
        bf16_split(w_w[i], hb, lb);
        g_wBw_hi[dst] = (unsigned short)hb;
        g_wBw_lo[dst] = (unsigned short)lb;
    }
}

// ===========================================================================
// x prep: tiled transpose -> x_t NHWC fp32, plus packed {hi,lo} planes.
// ===========================================================================
__global__ void __launch_bounds__(256)
prep_x_kernel(const float* __restrict__ x) {
    __shared__ float s[64*65];
    const int px0 = blockIdx.x * 64;
    const int b   = blockIdx.y;
    const int tid = threadIdx.x;
    for (int i = tid; i < 4096; i += 256) {
        int c = i >> 6, p = i & 63;
        s[p*65 + c] = x[((size_t)(b*CC + c))*HWW + px0 + p];
    }
    __syncthreads();
    for (int i = tid; i < 4096; i += 256) {
        int p = i >> 6, c = i & 63;
        g_xt[((size_t)b*HWW + px0 + p)*64 + c] = s[p*65 + c];
    }
    for (int i = tid; i < 2048; i += 256) {
        int cp = i >> 6, p = i & 63;
        uint32_t lw;
        uint32_t hw = pack_split2(s[p*65 + 2*cp], s[p*65 + 2*cp + 1], lw);
        g_x2[((size_t)(b*32 + cp))*HWW + px0 + p] = make_uint2(hw, lw);
    }
}

// ===========================================================================
// om conv via mma (dil=1), halo-shared A across kx taps. A: 130 rows.
// smem: A_hi@0, A_lo@17408, B_hi@34816 (3 taps 12K), B_lo@47104 (12K) = 59392
// ===========================================================================
#define OM_SMEM 59392
__global__ void __launch_bounds__(256)
om_tc_kernel(const uint2* __restrict__ in2,
             const unsigned short* __restrict__ wHi,
             const unsigned short* __restrict__ wLo,
             const float* __restrict__ b_om) {
    extern __shared__ char smem[];
    const int x0 = blockIdx.x * 128;
    const int y  = blockIdx.y;
    const int b  = blockIdx.z;
    const int tid = threadIdx.x;
    const int warp = tid >> 5, lane = tid & 31;
    const int wm = warp & 3, wn = warp >> 2;
    const uint32_t sbase = smem_u32(smem);

    float acc[2][2][4];
#pragma unroll
    for (int mt = 0; mt < 2; mt++)
#pragma unroll
        for (int nt = 0; nt < 2; nt++)
#pragma unroll
            for (int j = 0; j < 4; j++) acc[mt][nt][j] = 0.f;

    for (int dyi = 0; dyi < 3; dyi++) {
        __syncthreads();
        const int rowy = y + dyi - 1;
        const bool rowok = (unsigned)rowy < HH;
        for (int i = tid; i < 4160; i += 256) {
            int cp = i / 130, r = i - cp*130;
            int xin = x0 + r - 1;
            uint2 v = make_uint2(0u, 0u);
            if (rowok && (unsigned)xin < WW)
                v = in2[((size_t)(b*32 + cp))*HWW + rowy*WW + xin];
            uint32_t off = (uint32_t)r*128u
                         + ((((uint32_t)(cp>>2)) ^ ((uint32_t)r & 7u)) << 4)
                         + ((uint32_t)cp & 3u)*4u;
            *(uint32_t*)(smem + off)         = v.x;
            *(uint32_t*)(smem + 17408 + off) = v.y;
        }
        {
            const uint4* sh = (const uint4*)(wHi + dyi*3*2048);
            const uint4* sl = (const uint4*)(wLo + dyi*3*2048);
            uint4* dh = (uint4*)(smem + 34816);
            uint4* dl = (uint4*)(smem + 47104);
            for (int i = tid; i < 768; i += 256) { dh[i] = sh[i]; dl[i] = sl[i]; }
        }
        __syncthreads();

#pragma unroll
        for (int kx = 0; kx < 3; kx++) {
#pragma unroll
            for (int ch = 0; ch < 4; ch++) {
                uint32_t ahi[2][4], alo[2][4], bhi[4], blo[4];
#pragma unroll
                for (int mt = 0; mt < 2; mt++) {
                    int r = wm*32 + mt*16 + (lane & 15) + kx;
                    uint32_t u = (uint32_t)(ch*2 + (lane >> 4));
                    uint32_t addr = sbase + (uint32_t)r*128u
                                  + ((u ^ ((uint32_t)r & 7u)) << 4);
                    ldm4(ahi[mt], addr);
                    ldm4(alo[mt], addr + 17408u);
                }
                {
                    int ocr = wn*16 + (lane & 7) + ((lane >> 4) << 3);
                    uint32_t u = (uint32_t)(ch*2 + ((lane >> 3) & 1));
                    uint32_t addr = sbase + 34816u + (uint32_t)kx*4096u
                                  + (uint32_t)ocr*128u
                                  + ((u ^ ((uint32_t)ocr & 7u)) << 4);
                    ldm4(bhi, addr);
                    ldm4(blo, addr + 12288u);
                }
#pragma unroll
                for (int mt = 0; mt < 2; mt++)
#pragma unroll
                    for (int nt = 0; nt < 2; nt++) {
                        mma_bf16(acc[mt][nt], ahi[mt], &bhi[nt*2]);
                        mma_bf16(acc[mt][nt], ahi[mt], &blo[nt*2]);
                        mma_bf16(acc[mt][nt], alo[mt], &bhi[nt*2]);
                    }
            }
        }
    }

#pragma unroll
    for (int mt = 0; mt < 2; mt++)
#pragma unroll
        for (int nt = 0; nt < 2; nt++) {
            int pxr = wm*32 + mt*16 + (lane >> 2);
            int occ = wn*16 + nt*8 + ((lane & 3) << 1);
            if (occ < 27) {
                float bo = b_om[occ];
                float* o0 = g_om + ((size_t)(b*27 + occ))*HWW + y*WW + x0;
                o0[pxr]     = acc[mt][nt][0] + bo;
                o0[pxr + 8] = acc[mt][nt][2] + bo;
            }
            if (occ + 1 < 27) {
                float bo = b_om[occ+1];
                float* o1 = g_om + ((size_t)(b*27 + occ+1))*HWW + y*WW + x0;
                o1[pxr]     = acc[mt][nt][1] + bo;
                o1[pxr + 8] = acc[mt][nt][3] + bo;
            }
        }
}

// ===========================================================================
// DCNv2 + bn1 + relu via mma; float4 NHWC gather (4 ch/lane, 16 lanes/px).
// smem: A_hi@0 16K, A_lo@16K, B_hi@32K 8K, B_lo@40K 8K, idx@48K 2K, gw@50K 2K
// ===========================================================================
#define DCN_GI 49152
#define DCN_GW 51200
#define DCN_SMEM 53248
__global__ void __launch_bounds__(256)
dcn_tc_kernel(const unsigned short* __restrict__ wHi,
              const unsigned short* __restrict__ wLo,
              const float* __restrict__ bias,
              const float* __restrict__ bg, const float* __restrict__ bb,
              const float* __restrict__ bm, const float* __restrict__ bv) {
    extern __shared__ char smem[];
    const int x0 = blockIdx.x * 128;
    const int y  = blockIdx.y;
    const int b  = blockIdx.z;
    const int tid = threadIdx.x;
    const int warp = tid >> 5, lane = tid & 31;
    const int wm = warp & 3, wn = warp >> 2;
    const uint32_t sbase = smem_u32(smem);
    const float* __restrict__ xb = g_xt + (size_t)b*HWW*64;

    __shared__ float s_s[64], s_d[64];
    if (tid < 64) {
        float s = bg[tid] * rsqrtf(bv[tid] + 1e-5f);
        s_s[tid] = s;
        s_d[tid] = (bias[tid] - bm[tid]) * s + bb[tid];
    }

    float acc[2][4][4];
#pragma unroll
    for (int mt = 0; mt < 2; mt++)
#pragma unroll
        for (int nt = 0; nt < 4; nt++)
#pragma unroll
            for (int j = 0; j < 4; j++) acc[mt][nt][j] = 0.f;

    int* s_idx = (int*)(smem + DCN_GI);
    float* s_gw = (float*)(smem + DCN_GW);

    for (int tap = 0; tap < 9; tap++) {
        __syncthreads();
        // geometry for this tap: 2 threads per px (each handles 2 corners)
        {
            int px = tid >> 1, half = tid & 1;
            int xx = x0 + px;
            float o1 = g_om[((b*27 +      tap)*HH + y)*WW + xx];
            float o2 = g_om[((b*27 +  9 + tap)*HH + y)*WW + xx];
            float ml = g_om[((b*27 + 18 + tap)*HH + y)*WW + xx];
            float m  = 1.f / (1.f + expf(-ml));
            float py  = (float)(y  + (tap/3) - 1) + o1;
            float pxf = (float)(xx + (tap%3) - 1) + o2;
            float fy = floorf(py), fx = floorf(pxf);
            float wy1 = py - fy, wx1 = pxf - fx;
            int iy0 = (int)fy, ix0 = (int)fx;
#pragma unroll
            for (int jj = 0; jj < 2; jj++) {
                int j = half*2 + jj;
                int dy = j >> 1, dx = j & 1;
                int yi = iy0 + dy, xi = ix0 + dx;
                bool valid = ((unsigned)yi < HH) && ((unsigned)xi < WW);
                float wgt = (dy ? wy1 : 1.f - wy1) * (dx ? wx1 : 1.f - wx1);
                s_gw[px*4 + j]  = valid ? m * wgt : 0.f;
                int yc = min(max(yi, 0), HH-1);
                int xc = min(max(xi, 0), WW-1);
                s_idx[px*4 + j] = yc*WW + xc;
            }
        }
        {
            const uint4* sh = (const uint4*)(wHi + tap*4096);
            const uint4* sl = (const uint4*)(wLo + tap*4096);
            uint4* dh = (uint4*)(smem + 32768);
            uint4* dl = (uint4*)(smem + 40960);
            for (int i = tid; i < 512; i += 256) { dh[i] = sh[i]; dl[i] = sl[i]; }
        }
        __syncthreads();
        // A tile: float4 gather — 2048 items, 4 channels each
        for (int i = tid; i < 2048; i += 256) {
            int cq = i & 15, px = i >> 4;
            int4   ip = *(const int4*)(s_idx + px*4);
            float4 gp = *(const float4*)(s_gw + px*4);
            const float4* p0 = (const float4*)(xb + (size_t)ip.x*64 + 4*cq);
            const float4* p1 = (const float4*)(xb + (size_t)ip.y*64 + 4*cq);
            const float4* p2 = (const float4*)(xb + (size_t)ip.z*64 + 4*cq);
            const float4* p3 = (const float4*)(xb + (size_t)ip.w*64 + 4*cq);
            float4 u0 = *p0, u1 = *p1, u2 = *p2, u3 = *p3;
            float v0 = gp.x*u0.x + gp.y*u1.x + gp.z*u2.x + gp.w*u3.x;
            float v1 = gp.x*u0.y + gp.y*u1.y + gp.z*u2.y + gp.w*u3.y;
            float v2 = gp.x*u0.z + gp.y*u1.z + gp.z*u2.z + gp.w*u3.z;
            float v3 = gp.x*u0.w + gp.y*u1.w + gp.z*u2.w + gp.w*u3.w;
            uint32_t lw0, lw1;
            uint32_t hw0 = pack_split2(v0, v1, lw0);
            uint32_t hw1 = pack_split2(v2, v3, lw1);
            // pairs 2cq and 2cq+1 are adjacent words in the same 16B unit
            uint32_t off = (uint32_t)px*128u
                         + ((((uint32_t)(cq>>1)) ^ ((uint32_t)px & 7u)) << 4)
                         + ((uint32_t)(cq & 1))*8u;
            *(uint2*)(smem + off)         = make_uint2(hw0, hw1);
            *(uint2*)(smem + 16384 + off) = make_uint2(lw0, lw1);
        }
        __syncthreads();

#pragma unroll
        for (int ch = 0; ch < 4; ch++) {
            uint32_t ahi[2][4], alo[2][4], bhi[2][4], blo[2][4];
#pragma unroll
            for (int mt = 0; mt < 2; mt++) {
                int pxr = wm*32 + mt*16 + (lane & 15);
                uint32_t u = (uint32_t)(ch*2 + (lane >> 4));
                uint32_t addr = sbase + (uint32_t)pxr*128u
                              + ((u ^ ((uint32_t)pxr & 7u)) << 4);
                ldm4(ahi[mt], addr);
                ldm4(alo[mt], addr + 16384u);
            }
#pragma unroll
            for (int half = 0; half < 2; half++) {
                int ocr = wn*32 + half*16 + (lane & 7) + ((lane >> 4) << 3);
                uint32_t u = (uint32_t)(ch*2 + ((lane >> 3) & 1));
                uint32_t addr = sbase + 32768u + (uint32_t)ocr*128u
                              + ((u ^ ((uint32_t)ocr & 7u)) << 4);
                ldm4(bhi[half], addr);
                ldm4(blo[half], addr + 8192u);
            }
#pragma unroll
            for (int mt = 0; mt < 2; mt++)
#pragma unroll
                for (int nt = 0; nt < 4; nt++) {
                    const uint32_t* bh = &bhi[nt >> 1][(nt & 1)*2];
                    const uint32_t* bl = &blo[nt >> 1][(nt & 1)*2];
                    mma_bf16(acc[mt][nt], ahi[mt], bh);
                    mma_bf16(acc[mt][nt], ahi[mt], bl);
                    mma_bf16(acc[mt][nt], alo[mt], bh);
                }
        }
    }

    __syncthreads();
#pragma unroll
    for (int mt = 0; mt < 2; mt++)
#pragma unroll
        for (int nt = 0; nt < 4; nt++) {
            int pxr = wm*32 + mt*16 + (lane >> 2);
            int occ = wn*32 + nt*8 + ((lane & 3) << 1);
            float s0 = s_s[occ],   d0 = s_d[occ];
            float s1 = s_s[occ+1], d1 = s_d[occ+1];
            size_t base = ((size_t)(b*32 + (occ >> 1)))*HWW + y*WW + x0;
            float v0 = fmaf(acc[mt][nt][0], s0, d0); v0 = v0 > 0.f ? v0 : 0.f;
            float v1 = fmaf(acc[mt][nt][1], s1, d1); v1 = v1 > 0.f ? v1 : 0.f;
            float v2 = fmaf(acc[mt][nt][2], s0, d0); v2 = v2 > 0.f ? v2 : 0.f;
            float v3 = fmaf(acc[mt][nt][3], s1, d1); v3 = v3 > 0.f ? v3 : 0.f;
            uint32_t lw0, lw1;
            uint32_t hw0 = pack_split2(v0, v1, lw0);
            uint32_t hw1 = pack_split2(v2, v3, lw1);
            g_h12[base + pxr]     = make_uint2(hw0, lw0);
            g_h12[base + pxr + 8] = make_uint2(hw1, lw1);
        }
}

// ===========================================================================
// conv64 (dil=2) + bn + relu via mma, halo-shared A. A: 132 rows.
// smem: A_hi@0, A_lo@17408, B_hi@34816 (3 taps 24K), B_lo@59392 (24K) = 83968
// ===========================================================================
#define C64_SMEM 83968
__global__ void __launch_bounds__(256)
conv64_tc_kernel(const uint2* __restrict__ in2,
                 const unsigned short* __restrict__ wHi,
                 const unsigned short* __restrict__ wLo,
                 const float* __restrict__ bias,
                 const float* __restrict__ bg, const float* __restrict__ bb,
                 const float* __restrict__ bm, const float* __restrict__ bv,
                 uint2* __restrict__ out2) {
    extern __shared__ char smem[];
    const int x0 = blockIdx.x * 128;
    const int y  = blockIdx.y;
    const int b  = blockIdx.z;
    const int tid = threadIdx.x;
    const int warp = tid >> 5, lane = tid & 31;
    const int wm = warp & 3, wn = warp >> 2;
    const uint32_t sbase = smem_u32(smem);

    __shared__ float s_s[64], s_d[64];
    if (tid < 64) {
        float s = bg[tid] * rsqrtf(bv[tid] + 1e-5f);
        s_s[tid] = s;
        s_d[tid] = (bias[tid] - bm[tid]) * s + bb[tid];
    }

    float acc[2][4][4];
#pragma unroll
    for (int mt = 0; mt < 2; mt++)
#pragma unroll
        for (int nt = 0; nt < 4; nt++)
#pragma unroll
            for (int j = 0; j < 4; j++) acc[mt][nt][j] = 0.f;

    for (int dyi = 0; dyi < 3; dyi++) {
        __syncthreads();
        const int rowy = y + 2*dyi - 2;
        const bool rowok = (unsigned)rowy < HH;
        for (int i = tid; i < 4224; i += 256) {
            int cp = i / 132, r = i - cp*132;
            int xin = x0 + r - 2;
            uint2 v = make_uint2(0u, 0u);
            if (rowok && (unsigned)xin < WW)
                v = in2[((size_t)(b*32 + cp))*HWW + rowy*WW + xin];
            uint32_t off = (uint32_t)r*128u
                         + ((((uint32_t)(cp>>2)) ^ ((uint32_t)r & 7u)) << 4)
                         + ((uint32_t)cp & 3u)*4u;
            *(uint32_t*)(smem + off)         = v.x;
            *(uint32_t*)(smem + 17408 + off) = v.y;
        }
        {
            const uint4* sh = (const uint4*)(wHi + dyi*3*4096);
            const uint4* sl = (const uint4*)(wLo + dyi*3*4096);
            uint4* dh = (uint4*)(smem + 34816);
            uint4* dl = (uint4*)(smem + 59392);
            for (int i = tid; i < 1536; i += 256) { dh[i] = sh[i]; dl[i] = sl[i]; }
        }
        __syncthreads();

#pragma unroll
        for (int kx = 0; kx < 3; kx++) {
#pragma unroll
            for (int ch = 0; ch < 4; ch++) {
                uint32_t ahi[2][4], alo[2][4], bhi[2][4], blo[2][4];
#pragma unroll
                for (int mt = 0; mt < 2; mt++) {
                    int r = wm*32 + mt*16 + (lane & 15) + 2*kx;
                    uint32_t u = (uint32_t)(ch*2 + (lane >> 4));
                    uint32_t addr = sbase + (uint32_t)r*128u
                                  + ((u ^ ((uint32_t)r & 7u)) << 4);
                    ldm4(ahi[mt], addr);
                    ldm4(alo[mt], addr + 17408u);
                }
#pragma unroll
                for (int half = 0; half < 2; half++) {
                    int ocr = wn*32 + half*16 + (lane & 7) + ((lane >> 4) << 3);
                    uint32_t u = (uint32_t)(ch*2 + ((lane >> 3) & 1));
                    uint32_t addr = sbase + 34816u + (uint32_t)kx*8192u
                                  + (uint32_t)ocr*128u
                                  + ((u ^ ((uint32_t)ocr & 7u)) << 4);
                    ldm4(bhi[half], addr);
                    ldm4(blo[half], addr + 24576u);
                }
#pragma unroll
                for (int mt = 0; mt < 2; mt++)
#pragma unroll
                    for (int nt = 0; nt < 4; nt++) {
                        const uint32_t* bh = &bhi[nt >> 1][(nt & 1)*2];
                        const uint32_t* bl = &blo[nt >> 1][(nt & 1)*2];
                        mma_bf16(acc[mt][nt], ahi[mt], bh);
                        mma_bf16(acc[mt][nt], ahi[mt], bl);
                        mma_bf16(acc[mt][nt], alo[mt], bh);
                    }
            }
        }
    }

    __syncthreads();
#pragma unroll
    for (int mt = 0; mt < 2; mt++)
#pragma unroll
        for (int nt = 0; nt < 4; nt++) {
            int pxr = wm*32 + mt*16 + (lane >> 2);
            int occ = wn*32 + nt*8 + ((lane & 3) << 1);
            float s0 = s_s[occ],   d0 = s_d[occ];
            float s1 = s_s[occ+1], d1 = s_d[occ+1];
            size_t base = ((size_t)(b*32 + (occ >> 1)))*HWW + y*WW + x0;
            float v0 = fmaf(acc[mt][nt][0], s0, d0); v0 = v0 > 0.f ? v0 : 0.f;
            float v1 = fmaf(acc[mt][nt][1], s1, d1); v1 = v1 > 0.f ? v1 : 0.f;
            float v2 = fmaf(acc[mt][nt][2], s0, d0); v2 = v2 > 0.f ? v2 : 0.f;
            float v3 = fmaf(acc[mt][nt][3], s1, d1); v3 = v3 > 0.f ? v3 : 0.f;
            uint32_t lw0, lw1;
            uint32_t hw0 = pack_split2(v0, v1, lw0);
            uint32_t hw1 = pack_split2(v2, v3, lw1);
            out2[base + pxr]     = make_uint2(hw0, lw0);
            out2[base + pxr + 8] = make_uint2(hw1, lw1);
        }
}

// ---------------------------------------------------------------------------
// Final 64->1 3x3 conv pad1 + sigmoid + clip; direct coalesced LDG.64.
// ---------------------------------------------------------------------------
__global__ void __launch_bounds__(256)
final_kernel(const float* __restrict__ w3, const float* __restrict__ b3,
             float* __restrict__ out) {
    const int y = blockIdx.x;
    const int b = blockIdx.y;
    const int tid = threadIdx.x;  // 256 = W (x coordinate)

    __shared__ float s_w3[576];
    for (int i = tid; i < 576; i += 256) s_w3[i] = w3[i];
    __syncthreads();

    float acc = 0.f;
#pragma unroll 2
    for (int cp = 0; cp < 32; cp++) {
        const uint2* hp = g_h32 + ((size_t)(b*32 + cp))*HWW;
        const float* w0 = s_w3 + (2*cp)*9;
        const float* w1 = w0 + 9;
#pragma unroll
        for (int ky = 0; ky < 3; ky++) {
            int yy = y + ky - 1;
            if ((unsigned)yy >= HH) continue;
#pragma unroll
            for (int kx = 0; kx < 3; kx++) {
                int xx = tid + kx - 1;
                if ((unsigned)xx >= WW) continue;
                uint2 hl = hp[yy*WW + xx];
                float v0 = __uint_as_float(hl.x << 16) + __uint_as_float(hl.y << 16);
                float v1 = __uint_as_float(hl.x & 0xFFFF0000u)
                         + __uint_as_float(hl.y & 0xFFFF0000u);
                acc = fmaf(w0[ky*3+kx], v0, acc);
                acc = fmaf(w1[ky*3+kx], v1, acc);
            }
        }
    }
    float v = acc + b3[0];
    float sg = 1.f / (1.f + expf(-v));
    sg = fminf(fmaxf(sg, 1e-4f), 1.f - 1e-4f);
    out[((size_t)b*HH + y)*WW + tid] = sg;
}

// ---------------------------------------------------------------------------
extern "C" void kernel_launch(void* const* d_in, const int* in_sizes, int n_in,
                              void* d_out, int out_size) {
    (void)n_in; (void)out_size;
    const float* x     = (const float*)d_in[0];
    const float* w_om  = (const float*)d_in[1];
    const float* b_om  = (const float*)d_in[2];
    const float* w_dcn = (const float*)d_in[3];
    const float* b_dcn = (const float*)d_in[4];
    const float* bn1g  = (const float*)d_in[5];
    const float* bn1b  = (const float*)d_in[6];
    const float* bn1m  = (const float*)d_in[7];
    const float* bn1v  = (const float*)d_in[8];

    const float *w_h, *b_h, *w_w, *b_w, *w3, *b3;
    const float *bn2g, *bn2b, *bn2m, *bn2v, *bn3g, *bn3b, *bn3m, *bn3v;
    if (in_sizes[9] == CC) {
        bn2g = (const float*)d_in[9];  bn2b = (const float*)d_in[10];
        bn2m = (const float*)d_in[11]; bn2v = (const float*)d_in[12];
        bn3g = (const float*)d_in[13]; bn3b = (const float*)d_in[14];
        bn3m = (const float*)d_in[15]; bn3v = (const float*)d_in[16];
        w_h  = (const float*)d_in[17]; b_h  = (const float*)d_in[18];
        w_w  = (const float*)d_in[19]; b_w  = (const float*)d_in[20];
        w3   = (const float*)d_in[21]; b3   = (const float*)d_in[22];
    } else {
        w_h  = (const float*)d_in[9];  b_h  = (const float*)d_in[10];
        bn2g = (const float*)d_in[11]; bn2b = (const float*)d_in[12];
        bn2m = (const float*)d_in[13]; bn2v = (const float*)d_in[14];
        w_w  = (const float*)d_in[15]; b_w  = (const float*)d_in[16];
        bn3g = (const float*)d_in[17]; bn3b = (const float*)d_in[18];
        bn3m = (const float*)d_in[19]; bn3v = (const float*)d_in[20];
        w3   = (const float*)d_in[21]; b3   = (const float*)d_in[22];
    }
    float* out = (float*)d_out;

    uint2 *p_x2, *p_h12, *p_h22, *p_h32;
    unsigned short *p_wBom_hi, *p_wBom_lo, *p_wBd_hi, *p_wBd_lo;
    unsigned short *p_wBh_hi, *p_wBh_lo, *p_wBw_hi, *p_wBw_lo;
    cudaGetSymbolAddress((void**)&p_x2,  g_x2);
    cudaGetSymbolAddress((void**)&p_h12, g_h12);
    cudaGetSymbolAddress((void**)&p_h22, g_h22);
    cudaGetSymbolAddress((void**)&p_h32, g_h32);
    cudaGetSymbolAddress((void**)&p_wBom_hi, g_wBom_hi);
    cudaGetSymbolAddress((void**)&p_wBom_lo, g_wBom_lo);
    cudaGetSymbolAddress((void**)&p_wBd_hi, g_wBd_hi);
    cudaGetSymbolAddress((void**)&p_wBd_lo, g_wBd_lo);
    cudaGetSymbolAddress((void**)&p_wBh_hi, g_wBh_hi);
    cudaGetSymbolAddress((void**)&p_wBh_lo, g_wBh_lo);
    cudaGetSymbolAddress((void**)&p_wBw_hi, g_wBw_hi);
    cudaGetSymbolAddress((void**)&p_wBw_lo, g_wBw_lo);

    cudaFuncSetAttribute(om_tc_kernel,
                         cudaFuncAttributeMaxDynamicSharedMemorySize, OM_SMEM);
    cudaFuncSetAttribute(dcn_tc_kernel,
                         cudaFuncAttributeMaxDynamicSharedMemorySize, DCN_SMEM);
    cudaFuncSetAttribute(conv64_tc_kernel,
                         cudaFuncAttributeMaxDynamicSharedMemorySize, C64_SMEM);

    prep_weights_kernel<<<72, 256>>>(w_om, w_dcn, w_h, w_w);
    prep_x_kernel<<<dim3(HWW/64, BB), 256>>>(x);

    dim3 gridc(WW/128, HH, BB);
    om_tc_kernel<<<gridc, 256, OM_SMEM>>>(p_x2, p_wBom_hi, p_wBom_lo, b_om);
    dcn_tc_kernel<<<gridc, 256, DCN_SMEM>>>(p_wBd_hi, p_wBd_lo, b_dcn,
                                            bn1g, bn1b, bn1m, bn1v);
    conv64_tc_kernel<<<gridc, 256, C64_SMEM>>>(p_h12, p_wBh_hi, p_wBh_lo,
                                               b_h, bn2g, bn2b, bn2m, bn2v, p_h22);
    conv64_tc_kernel<<<gridc, 256, C64_SMEM>>>(p_h22, p_wBw_hi, p_wBw_lo,
                                               b_w, bn3g, bn3b, bn3m, bn3v, p_h32);
    final_kernel<<<dim3(HH, BB), 256>>>(w3, b3, out);
}

// round 16
// speedup vs baseline: 3.5341x; 1.0410x over previous
#include <cuda_runtime.h>
#include <cuda_fp16.h>
#include <math.h>
#include <stdint.h>

#define BB 2
#define CC 64
#define HH 256
#define WW 256
#define HWW (HH*WW)

// ---- scratch (device globals; no runtime allocation allowed) ----
__device__ float g_om[BB*27*HWW];                        // offset/mask conv out (fp32)
__device__ __align__(16) __half g_xh16[BB*HWW*64];       // x transposed NHWC fp16
__device__ uint2 g_x2[BB*32*HWW];                        // x packed {hi,lo} c-pairs
__device__ uint2 g_h12[BB*32*HWW];                       // h1 packed {hi,lo}
__device__ uint2 g_h22[BB*32*HWW];                       // h2 packed {hi,lo}
__device__ uint2 g_h32[BB*32*HWW];                       // h3 packed {hi,lo}
// bf16 hi/lo split, swizzled [tap][oc][c] B tiles
__device__ __align__(16) unsigned short g_wBom_hi[9*32*64], g_wBom_lo[9*32*64];
__device__ __align__(16) unsigned short g_wBd_hi[9*64*64],  g_wBd_lo[9*64*64];
__device__ __align__(16) unsigned short g_wBh_hi[9*64*64],  g_wBh_lo[9*64*64];
__device__ __align__(16) unsigned short g_wBw_hi[9*64*64],  g_wBw_lo[9*64*64];

// ---- bf16 split helpers ----
__device__ __forceinline__ uint32_t bf16_rne(float v) {
    uint32_t x = __float_as_uint(v);
    return (x + 0x7FFFu + ((x >> 16) & 1u)) >> 16;
}
__device__ __forceinline__ void bf16_split(float v, uint32_t& hb, uint32_t& lb) {
    hb = bf16_rne(v);
    float hf = __uint_as_float(hb << 16);
    lb = bf16_rne(v - hf);
}
// HW F2FP pack: hw = {bf16(v1) << 16 | bf16(v0)}, lw = lo-residual pair
__device__ __forceinline__ uint32_t pack_split2(float v0, float v1, uint32_t& lw) {
    uint32_t hw;
    asm("cvt.rn.bf16x2.f32 %0, %1, %2;" : "=r"(hw) : "f"(v1), "f"(v0));
    float h0 = __uint_as_float(hw << 16);
    float h1 = __uint_as_float(hw & 0xFFFF0000u);
    float l0 = v0 - h0, l1 = v1 - h1;
    asm("cvt.rn.bf16x2.f32 %0, %1, %2;" : "=r"(lw) : "f"(l1), "f"(l0));
    return hw;
}

// ---- warp-level tensor ops ----
__device__ __forceinline__ void ldm4(uint32_t* r, uint32_t addr) {
    asm volatile("ldmatrix.sync.aligned.m8n8.x4.shared.b16 {%0,%1,%2,%3}, [%4];"
                 : "=r"(r[0]), "=r"(r[1]), "=r"(r[2]), "=r"(r[3]) : "r"(addr));
}
__device__ __forceinline__ void mma_bf16(float* d, const uint32_t* a,
                                         const uint32_t* b) {
    asm volatile(
        "mma.sync.aligned.m16n8k16.row.col.f32.bf16.bf16.f32 "
        "{%0,%1,%2,%3}, {%4,%5,%6,%7}, {%8,%9}, {%0,%1,%2,%3};"
        : "+f"(d[0]), "+f"(d[1]), "+f"(d[2]), "+f"(d[3])
        : "r"(a[0]), "r"(a[1]), "r"(a[2]), "r"(a[3]), "r"(b[0]), "r"(b[1]));
}
__device__ __forceinline__ uint32_t smem_u32(const void* p) {
    uint32_t a;
    asm("{ .reg .u64 t; cvta.to.shared.u64 t, %1; cvt.u32.u64 %0, t; }"
        : "=r"(a) : "l"(p));
    return a;
}
__device__ __forceinline__ void cpasync16(uint32_t dst, const void* src) {
    asm volatile("cp.async.cg.shared.global [%0], [%1], 16;"
                 :: "r"(dst), "l"(src) : "memory");
}

// ===========================================================================
// Weight prep
// ===========================================================================
__global__ void prep_weights_kernel(const float* __restrict__ w_om,
                                    const float* __restrict__ w_dcn,
                                    const float* __restrict__ w_h,
                                    const float* __restrict__ w_w) {
    const int i0 = blockIdx.x * blockDim.x + threadIdx.x;
    const int stride = gridDim.x * blockDim.x;
    for (int i = i0; i < 32*CC*9; i += stride) {
        int oc = i / 576; int r = i - oc*576; int c = r / 9, tap = r - c*9;
        float v = (oc < 27) ? w_om[(oc*CC + c)*9 + tap] : 0.f;
        int dst = tap*2048 + oc*64 + (((c>>3) ^ (oc&7)) << 3) + (c & 7);
        uint32_t hb, lb;
        bf16_split(v, hb, lb);
        g_wBom_hi[dst] = (unsigned short)hb;
        g_wBom_lo[dst] = (unsigned short)lb;
    }
    for (int i = i0; i < CC*CC*9; i += stride) {
        int oc = i / 576; int r = i - oc*576; int c = r / 9, tap = r - c*9;
        int dst = tap*4096 + oc*64 + (((c>>3) ^ (oc&7)) << 3) + (c & 7);
        uint32_t hb, lb;
        bf16_split(w_dcn[i], hb, lb);
        g_wBd_hi[dst] = (unsigned short)hb;
        g_wBd_lo[dst] = (unsigned short)lb;
        bf16_split(w_h[i], hb, lb);
        g_wBh_hi[dst] = (unsigned short)hb;
        g_wBh_lo[dst] = (unsigned short)lb;
        bf16_split(w_w[i], hb, lb);
        g_wBw_hi[dst] = (unsigned short)hb;
        g_wBw_lo[dst] = (unsigned short)lb;
    }
}

// ===========================================================================
// x prep: tiled transpose -> fp16 NHWC plane + packed bf16 {hi,lo} planes.
// ===========================================================================
__global__ void __launch_bounds__(256)
prep_x_kernel(const float* __restrict__ x) {
    __shared__ float s[64*65];
    const int px0 = blockIdx.x * 64;
    const int b   = blockIdx.y;
    const int tid = threadIdx.x;
    for (int i = tid; i < 4096; i += 256) {
        int c = i >> 6, p = i & 63;
        s[p*65 + c] = x[((size_t)(b*CC + c))*HWW + px0 + p];
    }
    __syncthreads();
    // fp16 NHWC plane (cp inner for coalesced 128B/warp stores)
    for (int i = tid; i < 2048; i += 256) {
        int cp = i & 31, p = i >> 5;
        __half2 hh = __floats2half2_rn(s[p*65 + 2*cp], s[p*65 + 2*cp + 1]);
        *(__half2*)(g_xh16 + ((size_t)b*HWW + px0 + p)*64 + 2*cp) = hh;
    }
    // packed bf16 hi/lo c-pair planes (px inner for coalesced stores)
    for (int i = tid; i < 2048; i += 256) {
        int cp = i >> 6, p = i & 63;
        uint32_t lw;
        uint32_t hw = pack_split2(s[p*65 + 2*cp], s[p*65 + 2*cp + 1], lw);
        g_x2[((size_t)(b*32 + cp))*HWW + px0 + p] = make_uint2(hw, lw);
    }
}

// ===========================================================================
// om conv via mma (dil=1), halo-shared A across kx taps. A: 130 rows.
// smem: A_hi@0, A_lo@17408, B_hi@34816 (3 taps 12K), B_lo@47104 (12K) = 59392
// ===========================================================================
#define OM_SMEM 59392
__global__ void __launch_bounds__(256)
om_tc_kernel(const uint2* __restrict__ in2,
             const unsigned short* __restrict__ wHi,
             const unsigned short* __restrict__ wLo,
             const float* __restrict__ b_om) {
    extern __shared__ char smem[];
    const int x0 = blockIdx.x * 128;
    const int y  = blockIdx.y;
    const int b  = blockIdx.z;
    const int tid = threadIdx.x;
    const int warp = tid >> 5, lane = tid & 31;
    const int wm = warp & 3, wn = warp >> 2;
    const uint32_t sbase = smem_u32(smem);

    float acc[2][2][4];
#pragma unroll
    for (int mt = 0; mt < 2; mt++)
#pragma unroll
        for (int nt = 0; nt < 2; nt++)
#pragma unroll
            for (int j = 0; j < 4; j++) acc[mt][nt][j] = 0.f;

    for (int dyi = 0; dyi < 3; dyi++) {
        __syncthreads();
        const int rowy = y + dyi - 1;
        const bool rowok = (unsigned)rowy < HH;
        for (int i = tid; i < 4160; i += 256) {
            int cp = i / 130, r = i - cp*130;
            int xin = x0 + r - 1;
            uint2 v = make_uint2(0u, 0u);
            if (rowok && (unsigned)xin < WW)
                v = in2[((size_t)(b*32 + cp))*HWW + rowy*WW + xin];
            uint32_t off = (uint32_t)r*128u
                         + ((((uint32_t)(cp>>2)) ^ ((uint32_t)r & 7u)) << 4)
                         + ((uint32_t)cp & 3u)*4u;
            *(uint32_t*)(smem + off)         = v.x;
            *(uint32_t*)(smem + 17408 + off) = v.y;
        }
        {
            const uint4* sh = (const uint4*)(wHi + dyi*3*2048);
            const uint4* sl = (const uint4*)(wLo + dyi*3*2048);
            uint4* dh = (uint4*)(smem + 34816);
            uint4* dl = (uint4*)(smem + 47104);
            for (int i = tid; i < 768; i += 256) { dh[i] = sh[i]; dl[i] = sl[i]; }
        }
        __syncthreads();

#pragma unroll
        for (int kx = 0; kx < 3; kx++) {
#pragma unroll
            for (int ch = 0; ch < 4; ch++) {
                uint32_t ahi[2][4], alo[2][4], bhi[4], blo[4];
#pragma unroll
                for (int mt = 0; mt < 2; mt++) {
                    int r = wm*32 + mt*16 + (lane & 15) + kx;
                    uint32_t u = (uint32_t)(ch*2 + (lane >> 4));
                    uint32_t addr = sbase + (uint32_t)r*128u
                                  + ((u ^ ((uint32_t)r & 7u)) << 4);
                    ldm4(ahi[mt], addr);
                    ldm4(alo[mt], addr + 17408u);
                }
                {
                    int ocr = wn*16 + (lane & 7) + ((lane >> 4) << 3);
                    uint32_t u = (uint32_t)(ch*2 + ((lane >> 3) & 1));
                    uint32_t addr = sbase + 34816u + (uint32_t)kx*4096u
                                  + (uint32_t)ocr*128u
                                  + ((u ^ ((uint32_t)ocr & 7u)) << 4);
                    ldm4(bhi, addr);
                    ldm4(blo, addr + 12288u);
                }
#pragma unroll
                for (int mt = 0; mt < 2; mt++)
#pragma unroll
                    for (int nt = 0; nt < 2; nt++) {
                        mma_bf16(acc[mt][nt], ahi[mt], &bhi[nt*2]);
                        mma_bf16(acc[mt][nt], ahi[mt], &blo[nt*2]);
                        mma_bf16(acc[mt][nt], alo[mt], &bhi[nt*2]);
                    }
            }
        }
    }

#pragma unroll
    for (int mt = 0; mt < 2; mt++)
#pragma unroll
        for (int nt = 0; nt < 2; nt++) {
            int pxr = wm*32 + mt*16 + (lane >> 2);
            int occ = wn*16 + nt*8 + ((lane & 3) << 1);
            if (occ < 27) {
                float bo = b_om[occ];
                float* o0 = g_om + ((size_t)(b*27 + occ))*HWW + y*WW + x0;
                o0[pxr]     = acc[mt][nt][0] + bo;
                o0[pxr + 8] = acc[mt][nt][2] + bo;
            }
            if (occ + 1 < 27) {
                float bo = b_om[occ+1];
                float* o1 = g_om + ((size_t)(b*27 + occ+1))*HWW + y*WW + x0;
                o1[pxr]     = acc[mt][nt][1] + bo;
                o1[pxr + 8] = acc[mt][nt][3] + bo;
            }
        }
}

// ===========================================================================
// DCNv2 + bn1 + relu via mma; fp16 NHWC gather + cp.async double-buffered B.
// smem: A_hi@0 16K, A_lo@16K, B buf0 hi@32768 lo@40960, buf1 hi@49152 lo@57344,
//       idx@65536 2K, gw@67584 2K  -> 69632 total
// ===========================================================================
#define DCN_GI 65536
#define DCN_GW 67584
#define DCN_SMEM 69632
__global__ void __launch_bounds__(256)
dcn_tc_kernel(const unsigned short* __restrict__ wHi,
              const unsigned short* __restrict__ wLo,
              const float* __restrict__ bias,
              const float* __restrict__ bg, const float* __restrict__ bb,
              const float* __restrict__ bm, const float* __restrict__ bv) {
    extern __shared__ char smem[];
    const int x0 = blockIdx.x * 128;
    const int y  = blockIdx.y;
    const int b  = blockIdx.z;
    const int tid = threadIdx.x;
    const int warp = tid >> 5, lane = tid & 31;
    const int wm = warp & 3, wn = warp >> 2;
    const uint32_t sbase = smem_u32(smem);
    const __half* __restrict__ xb = g_xh16 + (size_t)b*HWW*64;

    __shared__ float s_s[64], s_d[64];
    if (tid < 64) {
        float s = bg[tid] * rsqrtf(bv[tid] + 1e-5f);
        s_s[tid] = s;
        s_d[tid] = (bias[tid] - bm[tid]) * s + bb[tid];
    }

    float acc[2][4][4];
#pragma unroll
    for (int mt = 0; mt < 2; mt++)
#pragma unroll
        for (int nt = 0; nt < 4; nt++)
#pragma unroll
            for (int j = 0; j < 4; j++) acc[mt][nt][j] = 0.f;

    int* s_idx = (int*)(smem + DCN_GI);
    float* s_gw = (float*)(smem + DCN_GW);

    // prefetch B(tap 0) into buf0
    for (int i = tid; i < 1024; i += 256) {
        int j = i & 511;
        uint32_t dst = sbase + ((i < 512) ? 32768u : 40960u) + (uint32_t)j*16u;
        const void* src = (i < 512) ? (const void*)(wHi + j*8)
                                    : (const void*)(wLo + j*8);
        cpasync16(dst, src);
    }
    asm volatile("cp.async.commit_group;" ::: "memory");

    for (int tap = 0; tap < 9; tap++) {
        __syncthreads();
        // prefetch B(tap+1) into the other buffer
        if (tap + 1 < 9) {
            uint32_t bufo = ((tap + 1) & 1) ? 49152u : 32768u;
            for (int i = tid; i < 1024; i += 256) {
                int j = i & 511;
                uint32_t dst = sbase + bufo + ((i < 512) ? 0u : 8192u)
                             + (uint32_t)j*16u;
                const void* src = (i < 512)
                    ? (const void*)(wHi + (tap+1)*4096 + j*8)
                    : (const void*)(wLo + (tap+1)*4096 + j*8);
                cpasync16(dst, src);
            }
            asm volatile("cp.async.commit_group;" ::: "memory");
        }
        // geometry for this tap: 2 threads per px (each handles 2 corners)
        {
            int px = tid >> 1, half = tid & 1;
            int xx = x0 + px;
            float o1 = g_om[((b*27 +      tap)*HH + y)*WW + xx];
            float o2 = g_om[((b*27 +  9 + tap)*HH + y)*WW + xx];
            float ml = g_om[((b*27 + 18 + tap)*HH + y)*WW + xx];
            float m  = 1.f / (1.f + expf(-ml));
            float py  = (float)(y  + (tap/3) - 1) + o1;
            float pxf = (float)(xx + (tap%3) - 1) + o2;
            float fy = floorf(py), fx = floorf(pxf);
            float wy1 = py - fy, wx1 = pxf - fx;
            int iy0 = (int)fy, ix0 = (int)fx;
#pragma unroll
            for (int jj = 0; jj < 2; jj++) {
                int j = half*2 + jj;
                int dy = j >> 1, dx = j & 1;
                int yi = iy0 + dy, xi = ix0 + dx;
                bool valid = ((unsigned)yi < HH) && ((unsigned)xi < WW);
                float wgt = (dy ? wy1 : 1.f - wy1) * (dx ? wx1 : 1.f - wx1);
                s_gw[px*4 + j]  = valid ? m * wgt : 0.f;
                int yc = min(max(yi, 0), HH-1);
                int xc = min(max(xi, 0), WW-1);
                s_idx[px*4 + j] = yc*WW + xc;
            }
        }
        __syncthreads();
        // A tile: fp16 gather — 2048 items, 4 channels each (8B/corner/lane)
        for (int i = tid; i < 2048; i += 256) {
            int cq = i & 15, px = i >> 4;
            int4   ip = *(const int4*)(s_idx + px*4);
            float4 gp = *(const float4*)(s_gw + px*4);
            uint2 q0 = *(const uint2*)(xb + (size_t)ip.x*64 + 4*cq);
            uint2 q1 = *(const uint2*)(xb + (size_t)ip.y*64 + 4*cq);
            uint2 q2 = *(const uint2*)(xb + (size_t)ip.z*64 + 4*cq);
            uint2 q3 = *(const uint2*)(xb + (size_t)ip.w*64 + 4*cq);
            float2 a0 = __half22float2(*(__half2*)&q0.x);
            float2 a1 = __half22float2(*(__half2*)&q1.x);
            float2 a2 = __half22float2(*(__half2*)&q2.x);
            float2 a3 = __half22float2(*(__half2*)&q3.x);
            float2 c0 = __half22float2(*(__half2*)&q0.y);
            float2 c1 = __half22float2(*(__half2*)&q1.y);
            float2 c2 = __half22float2(*(__half2*)&q2.y);
            float2 c3 = __half22float2(*(__half2*)&q3.y);
            float v0 = gp.x*a0.x + gp.y*a1.x + gp.z*a2.x + gp.w*a3.x;
            float v1 = gp.x*a0.y + gp.y*a1.y + gp.z*a2.y + gp.w*a3.y;
            float v2 = gp.x*c0.x + gp.y*c1.x + gp.z*c2.x + gp.w*c3.x;
            float v3 = gp.x*c0.y + gp.y*c1.y + gp.z*c2.y + gp.w*c3.y;
            uint32_t lw0, lw1;
            uint32_t hw0 = pack_split2(v0, v1, lw0);
            uint32_t hw1 = pack_split2(v2, v3, lw1);
            uint32_t off = (uint32_t)px*128u
                         + ((((uint32_t)(cq>>1)) ^ ((uint32_t)px & 7u)) << 4)
                         + ((uint32_t)(cq & 1))*8u;
            *(uint2*)(smem + off)         = make_uint2(hw0, hw1);
            *(uint2*)(smem + 16384 + off) = make_uint2(lw0, lw1);
        }
        if (tap < 8) {
            asm volatile("cp.async.wait_group 1;" ::: "memory");
        } else {
            asm volatile("cp.async.wait_group 0;" ::: "memory");
        }
        __syncthreads();

        const uint32_t bb0 = sbase + ((tap & 1) ? 49152u : 32768u);
#pragma unroll
        for (int ch = 0; ch < 4; ch++) {
            uint32_t ahi[2][4], alo[2][4], bhi[2][4], blo[2][4];
#pragma unroll
            for (int mt = 0; mt < 2; mt++) {
                int pxr = wm*32 + mt*16 + (lane & 15);
                uint32_t u = (uint32_t)(ch*2 + (lane >> 4));
                uint32_t addr = sbase + (uint32_t)pxr*128u
                              + ((u ^ ((uint32_t)pxr & 7u)) << 4);
                ldm4(ahi[mt], addr);
                ldm4(alo[mt], addr + 16384u);
            }
#pragma unroll
            for (int half = 0; half < 2; half++) {
                int ocr = wn*32 + half*16 + (lane & 7) + ((lane >> 4) << 3);
                uint32_t u = (uint32_t)(ch*2 + ((lane >> 3) & 1));
                uint32_t addr = bb0 + (uint32_t)ocr*128u
                              + ((u ^ ((uint32_t)ocr & 7u)) << 4);
                ldm4(bhi[half], addr);
                ldm4(blo[half], addr + 8192u);
            }
#pragma unroll
            for (int mt = 0; mt < 2; mt++)
#pragma unroll
                for (int nt = 0; nt < 4; nt++) {
                    const uint32_t* bh = &bhi[nt >> 1][(nt & 1)*2];
                    const uint32_t* bl = &blo[nt >> 1][(nt & 1)*2];
                    mma_bf16(acc[mt][nt], ahi[mt], bh);
                    mma_bf16(acc[mt][nt], ahi[mt], bl);
                    mma_bf16(acc[mt][nt], alo[mt], bh);
                }
        }
    }

    __syncthreads();
#pragma unroll
    for (int mt = 0; mt < 2; mt++)
#pragma unroll
        for (int nt = 0; nt < 4; nt++) {
            int pxr = wm*32 + mt*16 + (lane >> 2);
            int occ = wn*32 + nt*8 + ((lane & 3) << 1);
            float s0 = s_s[occ],   d0 = s_d[occ];
            float s1 = s_s[occ+1], d1 = s_d[occ+1];
            size_t base = ((size_t)(b*32 + (occ >> 1)))*HWW + y*WW + x0;
            float v0 = fmaf(acc[mt][nt][0], s0, d0); v0 = v0 > 0.f ? v0 : 0.f;
            float v1 = fmaf(acc[mt][nt][1], s1, d1); v1 = v1 > 0.f ? v1 : 0.f;
            float v2 = fmaf(acc[mt][nt][2], s0, d0); v2 = v2 > 0.f ? v2 : 0.f;
            float v3 = fmaf(acc[mt][nt][3], s1, d1); v3 = v3 > 0.f ? v3 : 0.f;
            uint32_t lw0, lw1;
            uint32_t hw0 = pack_split2(v0, v1, lw0);
            uint32_t hw1 = pack_split2(v2, v3, lw1);
            g_h12[base + pxr]     = make_uint2(hw0, lw0);
            g_h12[base + pxr + 8] = make_uint2(hw1, lw1);
        }
}

// ===========================================================================
// conv64 (dil=2) + bn + relu via mma, halo-shared A. A: 132 rows.
// smem: A_hi@0, A_lo@17408, B_hi@34816 (3 taps 24K), B_lo@59392 (24K) = 83968
// ===========================================================================
#define C64_SMEM 83968
__global__ void __launch_bounds__(256)
conv64_tc_kernel(const uint2* __restrict__ in2,
                 const unsigned short* __restrict__ wHi,
                 const unsigned short* __restrict__ wLo,
                 const float* __restrict__ bias,
                 const float* __restrict__ bg, const float* __restrict__ bb,
                 const float* __restrict__ bm, const float* __restrict__ bv,
                 uint2* __restrict__ out2) {
    extern __shared__ char smem[];
    const int x0 = blockIdx.x * 128;
    const int y  = blockIdx.y;
    const int b  = blockIdx.z;
    const int tid = threadIdx.x;
    const int warp = tid >> 5, lane = tid & 31;
    const int wm = warp & 3, wn = warp >> 2;
    const uint32_t sbase = smem_u32(smem);

    __shared__ float s_s[64], s_d[64];
    if (tid < 64) {
        float s = bg[tid] * rsqrtf(bv[tid] + 1e-5f);
        s_s[tid] = s;
        s_d[tid] = (bias[tid] - bm[tid]) * s + bb[tid];
    }

    float acc[2][4][4];
#pragma unroll
    for (int mt = 0; mt < 2; mt++)
#pragma unroll
        for (int nt = 0; nt < 4; nt++)
#pragma unroll
            for (int j = 0; j < 4; j++) acc[mt][nt][j] = 0.f;

    for (int dyi = 0; dyi < 3; dyi++) {
        __syncthreads();
        const int rowy = y + 2*dyi - 2;
        const bool rowok = (unsigned)rowy < HH;
        for (int i = tid; i < 4224; i += 256) {
            int cp = i / 132, r = i - cp*132;
            int xin = x0 + r - 2;
            uint2 v = make_uint2(0u, 0u);
            if (rowok && (unsigned)xin < WW)
                v = in2[((size_t)(b*32 + cp))*HWW + rowy*WW + xin];
            uint32_t off = (uint32_t)r*128u
                         + ((((uint32_t)(cp>>2)) ^ ((uint32_t)r & 7u)) << 4)
                         + ((uint32_t)cp & 3u)*4u;
            *(uint32_t*)(smem + off)         = v.x;
            *(uint32_t*)(smem + 17408 + off) = v.y;
        }
        {
            const uint4* sh = (const uint4*)(wHi + dyi*3*4096);
            const uint4* sl = (const uint4*)(wLo + dyi*3*4096);
            uint4* dh = (uint4*)(smem + 34816);
            uint4* dl = (uint4*)(smem + 59392);
            for (int i = tid; i < 1536; i += 256) { dh[i] = sh[i]; dl[i] = sl[i]; }
        }
        __syncthreads();

#pragma unroll
        for (int kx = 0; kx < 3; kx++) {
#pragma unroll
            for (int ch = 0; ch < 4; ch++) {
                uint32_t ahi[2][4], alo[2][4], bhi[2][4], blo[2][4];
#pragma unroll
                for (int mt = 0; mt < 2; mt++) {
                    int r = wm*32 + mt*16 + (lane & 15) + 2*kx;
                    uint32_t u = (uint32_t)(ch*2 + (lane >> 4));
                    uint32_t addr = sbase + (uint32_t)r*128u
                                  + ((u ^ ((uint32_t)r & 7u)) << 4);
                    ldm4(ahi[mt], addr);
                    ldm4(alo[mt], addr + 17408u);
                }
#pragma unroll
                for (int half = 0; half < 2; half++) {
                    int ocr = wn*32 + half*16 + (lane & 7) + ((lane >> 4) << 3);
                    uint32_t u = (uint32_t)(ch*2 + ((lane >> 3) & 1));
                    uint32_t addr = sbase + 34816u + (uint32_t)kx*8192u
                                  + (uint32_t)ocr*128u
                                  + ((u ^ ((uint32_t)ocr & 7u)) << 4);
                    ldm4(bhi[half], addr);
                    ldm4(blo[half], addr + 24576u);
                }
#pragma unroll
                for (int mt = 0; mt < 2; mt++)
#pragma unroll
                    for (int nt = 0; nt < 4; nt++) {
                        const uint32_t* bh = &bhi[nt >> 1][(nt & 1)*2];
                        const uint32_t* bl = &blo[nt >> 1][(nt & 1)*2];
                        mma_bf16(acc[mt][nt], ahi[mt], bh);
                        mma_bf16(acc[mt][nt], ahi[mt], bl);
                        mma_bf16(acc[mt][nt], alo[mt], bh);
                    }
            }
        }
    }

    __syncthreads();
#pragma unroll
    for (int mt = 0; mt < 2; mt++)
#pragma unroll
        for (int nt = 0; nt < 4; nt++) {
            int pxr = wm*32 + mt*16 + (lane >> 2);
            int occ = wn*32 + nt*8 + ((lane & 3) << 1);
            float s0 = s_s[occ],   d0 = s_d[occ];
            float s1 = s_s[occ+1], d1 = s_d[occ+1];
            size_t base = ((size_t)(b*32 + (occ >> 1)))*HWW + y*WW + x0;
            float v0 = fmaf(acc[mt][nt][0], s0, d0); v0 = v0 > 0.f ? v0 : 0.f;
            float v1 = fmaf(acc[mt][nt][1], s1, d1); v1 = v1 > 0.f ? v1 : 0.f;
            float v2 = fmaf(acc[mt][nt][2], s0, d0); v2 = v2 > 0.f ? v2 : 0.f;
            float v3 = fmaf(acc[mt][nt][3], s1, d1); v3 = v3 > 0.f ? v3 : 0.f;
            uint32_t lw0, lw1;
            uint32_t hw0 = pack_split2(v0, v1, lw0);
            uint32_t hw1 = pack_split2(v2, v3, lw1);
            out2[base + pxr]     = make_uint2(hw0, lw0);
            out2[base + pxr + 8] = make_uint2(hw1, lw1);
        }
}

// ---------------------------------------------------------------------------
// Final 64->1 3x3 conv pad1 + sigmoid + clip; direct coalesced LDG.64.
// ---------------------------------------------------------------------------
__global__ void __launch_bounds__(256)
final_kernel(const float* __restrict__ w3, const float* __restrict__ b3,
             float* __restrict__ out) {
    const int y = blockIdx.x;
    const int b = blockIdx.y;
    const int tid = threadIdx.x;  // 256 = W (x coordinate)

    __shared__ float s_w3[576];
    for (int i = tid; i < 576; i += 256) s_w3[i] = w3[i];
    __syncthreads();

    float acc = 0.f;
#pragma unroll 2
    for (int cp = 0; cp < 32; cp++) {
        const uint2* hp = g_h32 + ((size_t)(b*32 + cp))*HWW;
        const float* w0 = s_w3 + (2*cp)*9;
        const float* w1 = w0 + 9;
#pragma unroll
        for (int ky = 0; ky < 3; ky++) {
            int yy = y + ky - 1;
            if ((unsigned)yy >= HH) continue;
#pragma unroll
            for (int kx = 0; kx < 3; kx++) {
                int xx = tid + kx - 1;
                if ((unsigned)xx >= WW) continue;
                uint2 hl = hp[yy*WW + xx];
                float v0 = __uint_as_float(hl.x << 16) + __uint_as_float(hl.y << 16);
                float v1 = __uint_as_float(hl.x & 0xFFFF0000u)
                         + __uint_as_float(hl.y & 0xFFFF0000u);
                acc = fmaf(w0[ky*3+kx], v0, acc);
                acc = fmaf(w1[ky*3+kx], v1, acc);
            }
        }
    }
    float v = acc + b3[0];
    float sg = 1.f / (1.f + expf(-v));
    sg = fminf(fmaxf(sg, 1e-4f), 1.f - 1e-4f);
    out[((size_t)b*HH + y)*WW + tid] = sg;
}

// ---------------------------------------------------------------------------
extern "C" void kernel_launch(void* const* d_in, const int* in_sizes, int n_in,
                              void* d_out, int out_size) {
    (void)n_in; (void)out_size;
    const float* x     = (const float*)d_in[0];
    const float* w_om  = (const float*)d_in[1];
    const float* b_om  = (const float*)d_in[2];
    const float* w_dcn = (const float*)d_in[3];
    const float* b_dcn = (const float*)d_in[4];
    const float* bn1g  = (const float*)d_in[5];
    const float* bn1b  = (const float*)d_in[6];
    const float* bn1m  = (const float*)d_in[7];
    const float* bn1v  = (const float*)d_in[8];

    const float *w_h, *b_h, *w_w, *b_w, *w3, *b3;
    const float *bn2g, *bn2b, *bn2m, *bn2v, *bn3g, *bn3b, *bn3m, *bn3v;
    if (in_sizes[9] == CC) {
        bn2g = (const float*)d_in[9];  bn2b = (const float*)d_in[10];
        bn2m = (const float*)d_in[11]; bn2v = (const float*)d_in[12];
        bn3g = (const float*)d_in[13]; bn3b = (const float*)d_in[14];
        bn3m = (const float*)d_in[15]; bn3v = (const float*)d_in[16];
        w_h  = (const float*)d_in[17]; b_h  = (const float*)d_in[18];
        w_w  = (const float*)d_in[19]; b_w  = (const float*)d_in[20];
        w3   = (const float*)d_in[21]; b3   = (const float*)d_in[22];
    } else {
        w_h  = (const float*)d_in[9];  b_h  = (const float*)d_in[10];
        bn2g = (const float*)d_in[11]; bn2b = (const float*)d_in[12];
        bn2m = (const float*)d_in[13]; bn2v = (const float*)d_in[14];
        w_w  = (const float*)d_in[15]; b_w  = (const float*)d_in[16];
        bn3g = (const float*)d_in[17]; bn3b = (const float*)d_in[18];
        bn3m = (const float*)d_in[19]; bn3v = (const float*)d_in[20];
        w3   = (const float*)d_in[21]; b3   = (const float*)d_in[22];
    }
    float* out = (float*)d_out;

    uint2 *p_x2, *p_h12, *p_h22, *p_h32;
    unsigned short *p_wBom_hi, *p_wBom_lo, *p_wBd_hi, *p_wBd_lo;
    unsigned short *p_wBh_hi, *p_wBh_lo, *p_wBw_hi, *p_wBw_lo;
    cudaGetSymbolAddress((void**)&p_x2,  g_x2);
    cudaGetSymbolAddress((void**)&p_h12, g_h12);
    cudaGetSymbolAddress((void**)&p_h22, g_h22);
    cudaGetSymbolAddress((void**)&p_h32, g_h32);
    cudaGetSymbolAddress((void**)&p_wBom_hi, g_wBom_hi);
    cudaGetSymbolAddress((void**)&p_wBom_lo, g_wBom_lo);
    cudaGetSymbolAddress((void**)&p_wBd_hi, g_wBd_hi);
    cudaGetSymbolAddress((void**)&p_wBd_lo, g_wBd_lo);
    cudaGetSymbolAddress((void**)&p_wBh_hi, g_wBh_hi);
    cudaGetSymbolAddress((void**)&p_wBh_lo, g_wBh_lo);
    cudaGetSymbolAddress((void**)&p_wBw_hi, g_wBw_hi);
    cudaGetSymbolAddress((void**)&p_wBw_lo, g_wBw_lo);

    cudaFuncSetAttribute(om_tc_kernel,
                         cudaFuncAttributeMaxDynamicSharedMemorySize, OM_SMEM);
    cudaFuncSetAttribute(dcn_tc_kernel,
                         cudaFuncAttributeMaxDynamicSharedMemorySize, DCN_SMEM);
    cudaFuncSetAttribute(conv64_tc_kernel,
                         cudaFuncAttributeMaxDynamicSharedMemorySize, C64_SMEM);

    prep_weights_kernel<<<72, 256>>>(w_om, w_dcn, w_h, w_w);
    prep_x_kernel<<<dim3(HWW/64, BB), 256>>>(x);

    dim3 gridc(WW/128, HH, BB);
    om_tc_kernel<<<gridc, 256, OM_SMEM>>>(p_x2, p_wBom_hi, p_wBom_lo, b_om);
    dcn_tc_kernel<<<gridc, 256, DCN_SMEM>>>(p_wBd_hi, p_wBd_lo, b_dcn,
                                            bn1g, bn1b, bn1m, bn1v);
    conv64_tc_kernel<<<gridc, 256, C64_SMEM>>>(p_h12, p_wBh_hi, p_wBh_lo,
                                               b_h, bn2g, bn2b, bn2m, bn2v, p_h22);
    conv64_tc_kernel<<<gridc, 256, C64_SMEM>>>(p_h22, p_wBw_hi, p_wBw_lo,
                                               b_w, bn3g, bn3b, bn3m, bn3v, p_h32);
    final_kernel<<<dim3(HH, BB), 256>>>(w3, b3, out);
}

// round 17
// speedup vs baseline: 5.2642x; 1.4895x over previous
#include <cuda_runtime.h>
#include <cuda_fp16.h>
#include <math.h>
#include <stdint.h>

#define BB 2
#define CC 64
#define HH 256
#define WW 256
#define HWW (HH*WW)

// ---- scratch (device globals; no runtime allocation allowed) ----
__device__ float g_om[BB*27*HWW];                        // offset/mask conv out (fp32)
__device__ __align__(16) __half g_xh16[BB*HWW*64];       // x NHWC fp16 (dcn gather)
__device__ __align__(16) uint32_t g_xp16[BB*32*HWW];     // x half2 c-pair planes
__device__ __align__(16) uint32_t g_h1p[BB*32*HWW];      // h1 half2 planes
__device__ __align__(16) uint32_t g_h2p[BB*32*HWW];      // h2 half2 planes
__device__ __align__(16) uint32_t g_h3p[BB*32*HWW];      // h3 half2 planes
// fp16 swizzled [tap][oc][c] B tiles
__device__ __align__(16) unsigned short g_w16om[9*32*64];
__device__ __align__(16) unsigned short g_w16d[9*64*64];
__device__ __align__(16) unsigned short g_w16h[9*64*64];
__device__ __align__(16) unsigned short g_w16w[9*64*64];

__device__ __forceinline__ uint32_t pack_h2(float v0, float v1) {
    __half2 h = __floats2half2_rn(v0, v1);
    return *(uint32_t*)&h;
}

// ---- warp-level tensor ops ----
__device__ __forceinline__ void ldm4(uint32_t* r, uint32_t addr) {
    asm volatile("ldmatrix.sync.aligned.m8n8.x4.shared.b16 {%0,%1,%2,%3}, [%4];"
                 : "=r"(r[0]), "=r"(r[1]), "=r"(r[2]), "=r"(r[3]) : "r"(addr));
}
__device__ __forceinline__ void mma_f16(float* d, const uint32_t* a,
                                        const uint32_t* b) {
    asm volatile(
        "mma.sync.aligned.m16n8k16.row.col.f32.f16.f16.f32 "
        "{%0,%1,%2,%3}, {%4,%5,%6,%7}, {%8,%9}, {%0,%1,%2,%3};"
        : "+f"(d[0]), "+f"(d[1]), "+f"(d[2]), "+f"(d[3])
        : "r"(a[0]), "r"(a[1]), "r"(a[2]), "r"(a[3]), "r"(b[0]), "r"(b[1]));
}
__device__ __forceinline__ uint32_t smem_u32(const void* p) {
    uint32_t a;
    asm("{ .reg .u64 t; cvta.to.shared.u64 t, %1; cvt.u32.u64 %0, t; }"
        : "=r"(a) : "l"(p));
    return a;
}
__device__ __forceinline__ void cpasync16(uint32_t dst, const void* src) {
    asm volatile("cp.async.cg.shared.global [%0], [%1], 16;"
                 :: "r"(dst), "l"(src) : "memory");
}

// ===========================================================================
// Weight prep: fp16 swizzled B tiles.
// ===========================================================================
__global__ void prep_weights_kernel(const float* __restrict__ w_om,
                                    const float* __restrict__ w_dcn,
                                    const float* __restrict__ w_h,
                                    const float* __restrict__ w_w) {
    const int i0 = blockIdx.x * blockDim.x + threadIdx.x;
    const int stride = gridDim.x * blockDim.x;
    for (int i = i0; i < 32*CC*9; i += stride) {
        int oc = i / 576; int r = i - oc*576; int c = r / 9, tap = r - c*9;
        float v = (oc < 27) ? w_om[(oc*CC + c)*9 + tap] : 0.f;
        int dst = tap*2048 + oc*64 + (((c>>3) ^ (oc&7)) << 3) + (c & 7);
        __half hv = __float2half_rn(v);
        g_w16om[dst] = *(unsigned short*)&hv;
    }
    for (int i = i0; i < CC*CC*9; i += stride) {
        int oc = i / 576; int r = i - oc*576; int c = r / 9, tap = r - c*9;
        int dst = tap*4096 + oc*64 + (((c>>3) ^ (oc&7)) << 3) + (c & 7);
        __half hv;
        hv = __float2half_rn(w_dcn[i]); g_w16d[dst] = *(unsigned short*)&hv;
        hv = __float2half_rn(w_h[i]);   g_w16h[dst] = *(unsigned short*)&hv;
        hv = __float2half_rn(w_w[i]);   g_w16w[dst] = *(unsigned short*)&hv;
    }
}

// ===========================================================================
// x prep: tiled transpose -> fp16 NHWC plane + half2 c-pair planes.
// ===========================================================================
__global__ void __launch_bounds__(256)
prep_x_kernel(const float* __restrict__ x) {
    __shared__ float s[64*65];
    const int px0 = blockIdx.x * 64;
    const int b   = blockIdx.y;
    const int tid = threadIdx.x;
    for (int i = tid; i < 4096; i += 256) {
        int c = i >> 6, p = i & 63;
        s[p*65 + c] = x[((size_t)(b*CC + c))*HWW + px0 + p];
    }
    __syncthreads();
    // fp16 NHWC plane (cp inner for coalesced stores)
    for (int i = tid; i < 2048; i += 256) {
        int cp = i & 31, p = i >> 5;
        __half2 hh = __floats2half2_rn(s[p*65 + 2*cp], s[p*65 + 2*cp + 1]);
        *(__half2*)(g_xh16 + ((size_t)b*HWW + px0 + p)*64 + 2*cp) = hh;
    }
    // half2 c-pair planes (px inner for coalesced stores)
    for (int i = tid; i < 2048; i += 256) {
        int cp = i >> 6, p = i & 63;
        g_xp16[((size_t)(b*32 + cp))*HWW + px0 + p]
            = pack_h2(s[p*65 + 2*cp], s[p*65 + 2*cp + 1]);
    }
}

// ===========================================================================
// om conv via fp16 mma (dil=1), halo-shared A. A: 130 rows x 128B = 16640.
// smem: A@0 16640, B@16640 (3 taps x 4096 = 12288) -> 28928
// ===========================================================================
#define OM_SMEM 28928
__global__ void __launch_bounds__(256)
om_tc_kernel(const uint32_t* __restrict__ in1,
             const unsigned short* __restrict__ w16,
             const float* __restrict__ b_om) {
    extern __shared__ char smem[];
    const int x0 = blockIdx.x * 128;
    const int y  = blockIdx.y;
    const int b  = blockIdx.z;
    const int tid = threadIdx.x;
    const int warp = tid >> 5, lane = tid & 31;
    const int wm = warp & 3, wn = warp >> 2;
    const uint32_t sbase = smem_u32(smem);

    float acc[2][2][4];
#pragma unroll
    for (int mt = 0; mt < 2; mt++)
#pragma unroll
        for (int nt = 0; nt < 2; nt++)
#pragma unroll
            for (int j = 0; j < 4; j++) acc[mt][nt][j] = 0.f;

    for (int dyi = 0; dyi < 3; dyi++) {
        __syncthreads();
        const int rowy = y + dyi - 1;
        const bool rowok = (unsigned)rowy < HH;
        for (int i = tid; i < 4160; i += 256) {
            int cp = i / 130, r = i - cp*130;
            int xin = x0 + r - 1;
            uint32_t v = 0u;
            if (rowok && (unsigned)xin < WW)
                v = in1[((size_t)(b*32 + cp))*HWW + rowy*WW + xin];
            uint32_t off = (uint32_t)r*128u
                         + ((((uint32_t)(cp>>2)) ^ ((uint32_t)r & 7u)) << 4)
                         + ((uint32_t)cp & 3u)*4u;
            *(uint32_t*)(smem + off) = v;
        }
        {
            const uint4* sh = (const uint4*)(w16 + dyi*3*2048);
            uint4* dh = (uint4*)(smem + 16640);
            for (int i = tid; i < 768; i += 256) dh[i] = sh[i];
        }
        __syncthreads();

#pragma unroll
        for (int kx = 0; kx < 3; kx++) {
#pragma unroll
            for (int ch = 0; ch < 4; ch++) {
                uint32_t a[2][4], bq[4];
#pragma unroll
                for (int mt = 0; mt < 2; mt++) {
                    int r = wm*32 + mt*16 + (lane & 15) + kx;
                    uint32_t u = (uint32_t)(ch*2 + (lane >> 4));
                    uint32_t addr = sbase + (uint32_t)r*128u
                                  + ((u ^ ((uint32_t)r & 7u)) << 4);
                    ldm4(a[mt], addr);
                }
                {
                    int ocr = wn*16 + (lane & 7) + ((lane >> 4) << 3);
                    uint32_t u = (uint32_t)(ch*2 + ((lane >> 3) & 1));
                    uint32_t addr = sbase + 16640u + (uint32_t)kx*4096u
                                  + (uint32_t)ocr*128u
                                  + ((u ^ ((uint32_t)ocr & 7u)) << 4);
                    ldm4(bq, addr);
                }
#pragma unroll
                for (int mt = 0; mt < 2; mt++)
#pragma unroll
                    for (int nt = 0; nt < 2; nt++)
                        mma_f16(acc[mt][nt], a[mt], &bq[nt*2]);
            }
        }
    }

#pragma unroll
    for (int mt = 0; mt < 2; mt++)
#pragma unroll
        for (int nt = 0; nt < 2; nt++) {
            int pxr = wm*32 + mt*16 + (lane >> 2);
            int occ = wn*16 + nt*8 + ((lane & 3) << 1);
            if (occ < 27) {
                float bo = b_om[occ];
                float* o0 = g_om + ((size_t)(b*27 + occ))*HWW + y*WW + x0;
                o0[pxr]     = acc[mt][nt][0] + bo;
                o0[pxr + 8] = acc[mt][nt][2] + bo;
            }
            if (occ + 1 < 27) {
                float bo = b_om[occ+1];
                float* o1 = g_om + ((size_t)(b*27 + occ+1))*HWW + y*WW + x0;
                o1[pxr]     = acc[mt][nt][1] + bo;
                o1[pxr + 8] = acc[mt][nt][3] + bo;
            }
        }
}

// ===========================================================================
// DCNv2 + bn1 + relu via fp16 mma; fp16 NHWC gather + cp.async dbl-buffered B.
// smem: A@0 16K, Bbuf0@16384 8K, Bbuf1@24576 8K, idx@32768 2K, gw@34816 2K
// -> 36864
// ===========================================================================
#define DCN_GI 32768
#define DCN_GW 34816
#define DCN_SMEM 36864
__global__ void __launch_bounds__(256)
dcn_tc_kernel(const unsigned short* __restrict__ w16,
              const float* __restrict__ bias,
              const float* __restrict__ bg, const float* __restrict__ bb,
              const float* __restrict__ bm, const float* __restrict__ bv) {
    extern __shared__ char smem[];
    const int x0 = blockIdx.x * 128;
    const int y  = blockIdx.y;
    const int b  = blockIdx.z;
    const int tid = threadIdx.x;
    const int warp = tid >> 5, lane = tid & 31;
    const int wm = warp & 3, wn = warp >> 2;
    const uint32_t sbase = smem_u32(smem);
    const __half* __restrict__ xb = g_xh16 + (size_t)b*HWW*64;

    __shared__ float s_s[64], s_d[64];
    if (tid < 64) {
        float s = bg[tid] * rsqrtf(bv[tid] + 1e-5f);
        s_s[tid] = s;
        s_d[tid] = (bias[tid] - bm[tid]) * s + bb[tid];
    }

    float acc[2][4][4];
#pragma unroll
    for (int mt = 0; mt < 2; mt++)
#pragma unroll
        for (int nt = 0; nt < 4; nt++)
#pragma unroll
            for (int j = 0; j < 4; j++) acc[mt][nt][j] = 0.f;

    int* s_idx = (int*)(smem + DCN_GI);
    float* s_gw = (float*)(smem + DCN_GW);

    // prefetch B(tap 0) into buf0
    for (int i = tid; i < 512; i += 256)
        cpasync16(sbase + 16384u + (uint32_t)i*16u, (const void*)(w16 + i*8));
    asm volatile("cp.async.commit_group;" ::: "memory");

    for (int tap = 0; tap < 9; tap++) {
        __syncthreads();
        if (tap + 1 < 9) {
            uint32_t bufo = ((tap + 1) & 1) ? 24576u : 16384u;
            for (int i = tid; i < 512; i += 256)
                cpasync16(sbase + bufo + (uint32_t)i*16u,
                          (const void*)(w16 + (tap+1)*4096 + i*8));
            asm volatile("cp.async.commit_group;" ::: "memory");
        }
        // geometry: 2 threads per px
        {
            int px = tid >> 1, half = tid & 1;
            int xx = x0 + px;
            float o1 = g_om[((b*27 +      tap)*HH + y)*WW + xx];
            float o2 = g_om[((b*27 +  9 + tap)*HH + y)*WW + xx];
            float ml = g_om[((b*27 + 18 + tap)*HH + y)*WW + xx];
            float m  = 1.f / (1.f + expf(-ml));
            float py  = (float)(y  + (tap/3) - 1) + o1;
            float pxf = (float)(xx + (tap%3) - 1) + o2;
            float fy = floorf(py), fx = floorf(pxf);
            float wy1 = py - fy, wx1 = pxf - fx;
            int iy0 = (int)fy, ix0 = (int)fx;
#pragma unroll
            for (int jj = 0; jj < 2; jj++) {
                int j = half*2 + jj;
                int dy = j >> 1, dx = j & 1;
                int yi = iy0 + dy, xi = ix0 + dx;
                bool valid = ((unsigned)yi < HH) && ((unsigned)xi < WW);
                float wgt = (dy ? wy1 : 1.f - wy1) * (dx ? wx1 : 1.f - wx1);
                s_gw[px*4 + j]  = valid ? m * wgt : 0.f;
                int yc = min(max(yi, 0), HH-1);
                int xc = min(max(xi, 0), WW-1);
                s_idx[px*4 + j] = yc*WW + xc;
            }
        }
        __syncthreads();
        // A tile: fp16 gather (4 ch/lane) -> single fp16 plane
        for (int i = tid; i < 2048; i += 256) {
            int cq = i & 15, px = i >> 4;
            int4   ip = *(const int4*)(s_idx + px*4);
            float4 gp = *(const float4*)(s_gw + px*4);
            uint2 q0 = *(const uint2*)(xb + (size_t)ip.x*64 + 4*cq);
            uint2 q1 = *(const uint2*)(xb + (size_t)ip.y*64 + 4*cq);
            uint2 q2 = *(const uint2*)(xb + (size_t)ip.z*64 + 4*cq);
            uint2 q3 = *(const uint2*)(xb + (size_t)ip.w*64 + 4*cq);
            float2 a0 = __half22float2(*(__half2*)&q0.x);
            float2 a1 = __half22float2(*(__half2*)&q1.x);
            float2 a2 = __half22float2(*(__half2*)&q2.x);
            float2 a3 = __half22float2(*(__half2*)&q3.x);
            float2 c0 = __half22float2(*(__half2*)&q0.y);
            float2 c1 = __half22float2(*(__half2*)&q1.y);
            float2 c2 = __half22float2(*(__half2*)&q2.y);
            float2 c3 = __half22float2(*(__half2*)&q3.y);
            float v0 = gp.x*a0.x + gp.y*a1.x + gp.z*a2.x + gp.w*a3.x;
            float v1 = gp.x*a0.y + gp.y*a1.y + gp.z*a2.y + gp.w*a3.y;
            float v2 = gp.x*c0.x + gp.y*c1.x + gp.z*c2.x + gp.w*c3.x;
            float v3 = gp.x*c0.y + gp.y*c1.y + gp.z*c2.y + gp.w*c3.y;
            uint32_t off = (uint32_t)px*128u
                         + ((((uint32_t)(cq>>1)) ^ ((uint32_t)px & 7u)) << 4)
                         + ((uint32_t)(cq & 1))*8u;
            *(uint2*)(smem + off) = make_uint2(pack_h2(v0, v1), pack_h2(v2, v3));
        }
        if (tap < 8) {
            asm volatile("cp.async.wait_group 1;" ::: "memory");
        } else {
            asm volatile("cp.async.wait_group 0;" ::: "memory");
        }
        __syncthreads();

        const uint32_t bb0 = sbase + ((tap & 1) ? 24576u : 16384u);
#pragma unroll
        for (int ch = 0; ch < 4; ch++) {
            uint32_t a[2][4], bq[2][4];
#pragma unroll
            for (int mt = 0; mt < 2; mt++) {
                int pxr = wm*32 + mt*16 + (lane & 15);
                uint32_t u = (uint32_t)(ch*2 + (lane >> 4));
                uint32_t addr = sbase + (uint32_t)pxr*128u
                              + ((u ^ ((uint32_t)pxr & 7u)) << 4);
                ldm4(a[mt], addr);
            }
#pragma unroll
            for (int half = 0; half < 2; half++) {
                int ocr = wn*32 + half*16 + (lane & 7) + ((lane >> 4) << 3);
                uint32_t u = (uint32_t)(ch*2 + ((lane >> 3) & 1));
                uint32_t addr = bb0 + (uint32_t)ocr*128u
                              + ((u ^ ((uint32_t)ocr & 7u)) << 4);
                ldm4(bq[half], addr);
            }
#pragma unroll
            for (int mt = 0; mt < 2; mt++)
#pragma unroll
                for (int nt = 0; nt < 4; nt++)
                    mma_f16(acc[mt][nt], a[mt], &bq[nt >> 1][(nt & 1)*2]);
        }
    }

    __syncthreads();
#pragma unroll
    for (int mt = 0; mt < 2; mt++)
#pragma unroll
        for (int nt = 0; nt < 4; nt++) {
            int pxr = wm*32 + mt*16 + (lane >> 2);
            int occ = wn*32 + nt*8 + ((lane & 3) << 1);
            float s0 = s_s[occ],   d0 = s_d[occ];
            float s1 = s_s[occ+1], d1 = s_d[occ+1];
            size_t base = ((size_t)(b*32 + (occ >> 1)))*HWW + y*WW + x0;
            float v0 = fmaf(acc[mt][nt][0], s0, d0); v0 = v0 > 0.f ? v0 : 0.f;
            float v1 = fmaf(acc[mt][nt][1], s1, d1); v1 = v1 > 0.f ? v1 : 0.f;
            float v2 = fmaf(acc[mt][nt][2], s0, d0); v2 = v2 > 0.f ? v2 : 0.f;
            float v3 = fmaf(acc[mt][nt][3], s1, d1); v3 = v3 > 0.f ? v3 : 0.f;
            g_h1p[base + pxr]     = pack_h2(v0, v1);
            g_h1p[base + pxr + 8] = pack_h2(v2, v3);
        }
}

// ===========================================================================
// conv64 (dil=2) + bn + relu via fp16 mma, halo-shared A. A: 132 rows = 16896.
// smem: A@0 16896, B@16896 (3 taps x 8192 = 24576) -> 41472
// ===========================================================================
#define C64_SMEM 41472
__global__ void __launch_bounds__(256)
conv64_tc_kernel(const uint32_t* __restrict__ in1,
                 const unsigned short* __restrict__ w16,
                 const float* __restrict__ bias,
                 const float* __restrict__ bg, const float* __restrict__ bb,
                 const float* __restrict__ bm, const float* __restrict__ bv,
                 uint32_t* __restrict__ out1) {
    extern __shared__ char smem[];
    const int x0 = blockIdx.x * 128;
    const int y  = blockIdx.y;
    const int b  = blockIdx.z;
    const int tid = threadIdx.x;
    const int warp = tid >> 5, lane = tid & 31;
    const int wm = warp & 3, wn = warp >> 2;
    const uint32_t sbase = smem_u32(smem);

    __shared__ float s_s[64], s_d[64];
    if (tid < 64) {
        float s = bg[tid] * rsqrtf(bv[tid] + 1e-5f);
        s_s[tid] = s;
        s_d[tid] = (bias[tid] - bm[tid]) * s + bb[tid];
    }

    float acc[2][4][4];
#pragma unroll
    for (int mt = 0; mt < 2; mt++)
#pragma unroll
        for (int nt = 0; nt < 4; nt++)
#pragma unroll
            for (int j = 0; j < 4; j++) acc[mt][nt][j] = 0.f;

    for (int dyi = 0; dyi < 3; dyi++) {
        __syncthreads();
        const int rowy = y + 2*dyi - 2;
        const bool rowok = (unsigned)rowy < HH;
        for (int i = tid; i < 4224; i += 256) {
            int cp = i / 132, r = i - cp*132;
            int xin = x0 + r - 2;
            uint32_t v = 0u;
            if (rowok && (unsigned)xin < WW)
                v = in1[((size_t)(b*32 + cp))*HWW + rowy*WW + xin];
            uint32_t off = (uint32_t)r*128u
                         + ((((uint32_t)(cp>>2)) ^ ((uint32_t)r & 7u)) << 4)
                         + ((uint32_t)cp & 3u)*4u;
            *(uint32_t*)(smem + off) = v;
        }
        {
            const uint4* sh = (const uint4*)(w16 + dyi*3*4096);
            uint4* dh = (uint4*)(smem + 16896);
            for (int i = tid; i < 1536; i += 256) dh[i] = sh[i];
        }
        __syncthreads();

#pragma unroll
        for (int kx = 0; kx < 3; kx++) {
#pragma unroll
            for (int ch = 0; ch < 4; ch++) {
                uint32_t a[2][4], bq[2][4];
#pragma unroll
                for (int mt = 0; mt < 2; mt++) {
                    int r = wm*32 + mt*16 + (lane & 15) + 2*kx;
                    uint32_t u = (uint32_t)(ch*2 + (lane >> 4));
                    uint32_t addr = sbase + (uint32_t)r*128u
                                  + ((u ^ ((uint32_t)r & 7u)) << 4);
                    ldm4(a[mt], addr);
                }
#pragma unroll
                for (int half = 0; half < 2; half++) {
                    int ocr = wn*32 + half*16 + (lane & 7) + ((lane >> 4) << 3);
                    uint32_t u = (uint32_t)(ch*2 + ((lane >> 3) & 1));
                    uint32_t addr = sbase + 16896u + (uint32_t)kx*8192u
                                  + (uint32_t)ocr*128u
                                  + ((u ^ ((uint32_t)ocr & 7u)) << 4);
                    ldm4(bq[half], addr);
                }
#pragma unroll
                for (int mt = 0; mt < 2; mt++)
#pragma unroll
                    for (int nt = 0; nt < 4; nt++)
                        mma_f16(acc[mt][nt], a[mt], &bq[nt >> 1][(nt & 1)*2]);
            }
        }
    }

    __syncthreads();
#pragma unroll
    for (int mt = 0; mt < 2; mt++)
#pragma unroll
        for (int nt = 0; nt < 4; nt++) {
            int pxr = wm*32 + mt*16 + (lane >> 2);
            int occ = wn*32 + nt*8 + ((lane & 3) << 1);
            float s0 = s_s[occ],   d0 = s_d[occ];
            float s1 = s_s[occ+1], d1 = s_d[occ+1];
            size_t base = ((size_t)(b*32 + (occ >> 1)))*HWW + y*WW + x0;
            float v0 = fmaf(acc[mt][nt][0], s0, d0); v0 = v0 > 0.f ? v0 : 0.f;
            float v1 = fmaf(acc[mt][nt][1], s1, d1); v1 = v1 > 0.f ? v1 : 0.f;
            float v2 = fmaf(acc[mt][nt][2], s0, d0); v2 = v2 > 0.f ? v2 : 0.f;
            float v3 = fmaf(acc[mt][nt][3], s1, d1); v3 = v3 > 0.f ? v3 : 0.f;
            out1[base + pxr]     = pack_h2(v0, v1);
            out1[base + pxr + 8] = pack_h2(v2, v3);
        }
}

// ---------------------------------------------------------------------------
// Final 64->1 3x3 conv pad1 + sigmoid + clip; reads half2 planes.
// ---------------------------------------------------------------------------
__global__ void __launch_bounds__(256)
final_kernel(const float* __restrict__ w3, const float* __restrict__ b3,
             float* __restrict__ out) {
    const int y = blockIdx.x;
    const int b = blockIdx.y;
    const int tid = threadIdx.x;  // 256 = W (x coordinate)

    __shared__ float s_w3[576];
    for (int i = tid; i < 576; i += 256) s_w3[i] = w3[i];
    __syncthreads();

    float acc = 0.f;
#pragma unroll 2
    for (int cp = 0; cp < 32; cp++) {
        const uint32_t* hp = g_h3p + ((size_t)(b*32 + cp))*HWW;
        const float* w0 = s_w3 + (2*cp)*9;
        const float* w1 = w0 + 9;
#pragma unroll
        for (int ky = 0; ky < 3; ky++) {
            int yy = y + ky - 1;
            if ((unsigned)yy >= HH) continue;
#pragma unroll
            for (int kx = 0; kx < 3; kx++) {
                int xx = tid + kx - 1;
                if ((unsigned)xx >= WW) continue;
                uint32_t hl = hp[yy*WW + xx];
                float2 v = __half22float2(*(__half2*)&hl);
                acc = fmaf(w0[ky*3+kx], v.x, acc);
                acc = fmaf(w1[ky*3+kx], v.y, acc);
            }
        }
    }
    float v = acc + b3[0];
    float sg = 1.f / (1.f + expf(-v));
    sg = fminf(fmaxf(sg, 1e-4f), 1.f - 1e-4f);
    out[((size_t)b*HH + y)*WW + tid] = sg;
}

// ---------------------------------------------------------------------------
extern "C" void kernel_launch(void* const* d_in, const int* in_sizes, int n_in,
                              void* d_out, int out_size) {
    (void)n_in; (void)out_size;
    const float* x     = (const float*)d_in[0];
    const float* w_om  = (const float*)d_in[1];
    const float* b_om  = (const float*)d_in[2];
    const float* w_dcn = (const float*)d_in[3];
    const float* b_dcn = (const float*)d_in[4];
    const float* bn1g  = (const float*)d_in[5];
    const float* bn1b  = (const float*)d_in[6];
    const float* bn1m  = (const float*)d_in[7];
    const float* bn1v  = (const float*)d_in[8];

    const float *w_h, *b_h, *w_w, *b_w, *w3, *b3;
    const float *bn2g, *bn2b, *bn2m, *bn2v, *bn3g, *bn3b, *bn3m, *bn3v;
    if (in_sizes[9] == CC) {
        bn2g = (const float*)d_in[9];  bn2b = (const float*)d_in[10];
        bn2m = (const float*)d_in[11]; bn2v = (const float*)d_in[12];
        bn3g = (const float*)d_in[13]; bn3b = (const float*)d_in[14];
        bn3m = (const float*)d_in[15]; bn3v = (const float*)d_in[16];
        w_h  = (const float*)d_in[17]; b_h  = (const float*)d_in[18];
        w_w  = (const float*)d_in[19]; b_w  = (const float*)d_in[20];
        w3   = (const float*)d_in[21]; b3   = (const float*)d_in[22];
    } else {
        w_h  = (const float*)d_in[9];  b_h  = (const float*)d_in[10];
        bn2g = (const float*)d_in[11]; bn2b = (const float*)d_in[12];
        bn2m = (const float*)d_in[13]; bn2v = (const float*)d_in[14];
        w_w  = (const float*)d_in[15]; b_w  = (const float*)d_in[16];
        bn3g = (const float*)d_in[17]; bn3b = (const float*)d_in[18];
        bn3m = (const float*)d_in[19]; bn3v = (const float*)d_in[20];
        w3   = (const float*)d_in[21]; b3   = (const float*)d_in[22];
    }
    float* out = (float*)d_out;

    uint32_t *p_xp, *p_h1p, *p_h2p, *p_h3p;
    unsigned short *p_w16om, *p_w16d, *p_w16h, *p_w16w;
    cudaGetSymbolAddress((void**)&p_xp,  g_xp16);
    cudaGetSymbolAddress((void**)&p_h1p, g_h1p);
    cudaGetSymbolAddress((void**)&p_h2p, g_h2p);
    cudaGetSymbolAddress((void**)&p_h3p, g_h3p);
    cudaGetSymbolAddress((void**)&p_w16om, g_w16om);
    cudaGetSymbolAddress((void**)&p_w16d,  g_w16d);
    cudaGetSymbolAddress((void**)&p_w16h,  g_w16h);
    cudaGetSymbolAddress((void**)&p_w16w,  g_w16w);

    cudaFuncSetAttribute(om_tc_kernel,
                         cudaFuncAttributeMaxDynamicSharedMemorySize, OM_SMEM);
    cudaFuncSetAttribute(dcn_tc_kernel,
                         cudaFuncAttributeMaxDynamicSharedMemorySize, DCN_SMEM);
    cudaFuncSetAttribute(conv64_tc_kernel,
                         cudaFuncAttributeMaxDynamicSharedMemorySize, C64_SMEM);

    prep_weights_kernel<<<72, 256>>>(w_om, w_dcn, w_h, w_w);
    prep_x_kernel<<<dim3(HWW/64, BB), 256>>>(x);

    dim3 gridc(WW/128, HH, BB);
    om_tc_kernel<<<gridc, 256, OM_SMEM>>>(p_xp, p_w16om, b_om);
    dcn_tc_kernel<<<gridc, 256, DCN_SMEM>>>(p_w16d, b_dcn,
                                            bn1g, bn1b, bn1m, bn1v);
    conv64_tc_kernel<<<gridc, 256, C64_SMEM>>>(p_h1p, p_w16h,
                                               b_h, bn2g, bn2b, bn2m, bn2v, p_h2p);
    conv64_tc_kernel<<<gridc, 256, C64_SMEM>>>(p_h2p, p_w16w,
                                               b_w, bn3g, bn3b, bn3m, bn3v, p_h3p);
    final_kernel<<<dim3(HH, BB), 256>>>(w3, b3, out);
}